// round 7
// baseline (speedup 1.0000x reference)
#include <cuda_runtime.h>
#include <cuda_bf16.h>
#include <math.h>
#include <float.h>
#include <stdint.h>

#define B_   2
#define T_   2048
#define C_   2048
#define H_   16
#define KVH_ 4
#define HD_  128
#define M_   (B_*T_)           // 4096
#define K3_  6144              // 3 * 2048 (split-K)
#define QKV_LD 3072

// ---------------- scratch ----------------
__device__ __nv_bfloat16 g_xs [(size_t)M_ * K3_];
__device__ __nv_bfloat16 g_wb1[(size_t)3072 * K3_];
__device__ __nv_bfloat16 g_wb2[(size_t)2048 * K3_];
__device__ __nv_bfloat16 g_ys [(size_t)M_ * K3_];
__device__ float g_qkv[(size_t)M_ * QKV_LD];
__device__ __nv_bfloat16 g_k2[(size_t)B_ * KVH_ * T_ * 256];        // [bkv][t][hi128|lo128]
__device__ __nv_bfloat16 g_vt[(size_t)B_ * KVH_ * HD_ * 2 * T_];    // [bkv][d][hi T|lo T]

// ---------------- helpers ----------------
__device__ __forceinline__ void split2(float v, __nv_bfloat16& h, __nv_bfloat16& l) {
    h = __float2bfloat16_rn(v);
    l = __float2bfloat16_rn(v - __bfloat162float(h));
}
__device__ __forceinline__ uint32_t smem_u32(const void* p) {
    uint32_t a;
    asm("{ .reg .u64 t; cvta.to.shared.u64 t, %1; cvt.u32.u64 %0, t; }" : "=r"(a) : "l"(p));
    return a;
}
__device__ __forceinline__ uint32_t packbf2(float x, float y) {
    __nv_bfloat162 t = __floats2bfloat162_rn(x, y);
    return *(uint32_t*)&t;
}
#define LDMX4(r0, r1, r2, r3, addr) \
    asm volatile("ldmatrix.sync.aligned.m8n8.x4.shared.b16 {%0,%1,%2,%3}, [%4];" \
        : "=r"(r0), "=r"(r1), "=r"(r2), "=r"(r3) : "r"(addr))
#define MMA16816(c, a0, a1, a2, a3, b0, b1) \
    asm volatile("mma.sync.aligned.m16n8k16.row.col.f32.bf16.bf16.f32 " \
        "{%0,%1,%2,%3}, {%4,%5,%6,%7}, {%8,%9}, {%0,%1,%2,%3};" \
        : "+f"((c)[0]), "+f"((c)[1]), "+f"((c)[2]), "+f"((c)[3]) \
        : "r"(a0), "r"(a1), "r"(a2), "r"(a3), "r"(b0), "r"(b1))
#define CP_ASYNC16(dst, src) \
    asm volatile("cp.async.cg.shared.global [%0], [%1], 16;" :: "r"(dst), "l"(src) : "memory")
#define CP_COMMIT() asm volatile("cp.async.commit_group;" ::: "memory")
#define CP_WAIT(n)  asm volatile("cp.async.wait_group %0;" :: "n"(n) : "memory")

// ---------------- split kernels ----------------
__global__ __launch_bounds__(256)
void split_a_kernel(const float* __restrict__ src, __nv_bfloat16* __restrict__ dst) {
    int idx = blockIdx.x * 256 + threadIdx.x;
    int m = idx >> 9;
    int k = (idx & 511) << 2;
    float4 v = *(const float4*)(src + (size_t)m * 2048 + k);
    __nv_bfloat16 h0, h1, h2, h3, l0, l1, l2, l3;
    split2(v.x, h0, l0); split2(v.y, h1, l1);
    split2(v.z, h2, l2); split2(v.w, h3, l3);
    __nv_bfloat162 H0 = __halves2bfloat162(h0, h1), H1 = __halves2bfloat162(h2, h3);
    __nv_bfloat162 L0 = __halves2bfloat162(l0, l1), L1 = __halves2bfloat162(l2, l3);
    __nv_bfloat162* d0 = (__nv_bfloat162*)(dst + (size_t)m * K3_ + k);
    d0[0] = H0; d0[1] = H1;
    __nv_bfloat162* d1 = (__nv_bfloat162*)(dst + (size_t)m * K3_ + 2048 + k);
    d1[0] = L0; d1[1] = L1;
    __nv_bfloat162* d2 = (__nv_bfloat162*)(dst + (size_t)m * K3_ + 4096 + k);
    d2[0] = H0; d2[1] = H1;
}

__global__ __launch_bounds__(256)
void tsplit_b_kernel(const float* __restrict__ src, __nv_bfloat16* __restrict__ dst, int Ncols) {
    __shared__ float t[32][33];
    const int n0 = blockIdx.x * 32, k0 = blockIdx.y * 32;
    const int tx = threadIdx.x, ty = threadIdx.y;
#pragma unroll
    for (int i = 0; i < 4; i++)
        t[ty + i * 8][tx] = src[(size_t)(k0 + ty + i * 8) * Ncols + n0 + tx];
    __syncthreads();
#pragma unroll
    for (int i = 0; i < 4; i++) {
        float v = t[tx][ty + i * 8];
        __nv_bfloat16 h, l;
        split2(v, h, l);
        __nv_bfloat16* row = dst + (size_t)(n0 + ty + i * 8) * K3_ + k0 + tx;
        row[0]    = h;
        row[2048] = h;
        row[4096] = l;
    }
}

// ---------------- V transpose+split ----------------
__global__ __launch_bounds__(256)
void split_v_kernel(const float* __restrict__ qkv, __nv_bfloat16* __restrict__ vt) {
    __shared__ float tbuf[32][33];
    const int d0 = blockIdx.x * 32;
    const int t0 = blockIdx.y * 32;
    const int bkv = blockIdx.z;
    const int b = bkv >> 2, kv = bkv & 3;
    const int tx = threadIdx.x, ty = threadIdx.y;
#pragma unroll
    for (int i = 0; i < 4; i++)
        tbuf[ty + i * 8][tx] =
            qkv[(size_t)(b * T_ + t0 + ty + i * 8) * QKV_LD + 2560 + kv * 128 + d0 + tx];
    __syncthreads();
#pragma unroll
    for (int i = 0; i < 4; i++) {
        float v = tbuf[tx][ty + i * 8];
        __nv_bfloat16 h, l;
        split2(v, h, l);
        __nv_bfloat16* row = vt + ((size_t)bkv * 128 + d0 + ty + i * 8) * (2 * T_) + t0 + tx;
        row[0]  = h;
        row[T_] = l;
    }
}

// ---------------- bf16 mma.sync GEMM: 128 thr, 4 warps @ 64x64, 4-stage cp.async ----------------
#define SMPAD 80
#define GSTAGE_B (2 * 128 * SMPAD)      // 20480 per stage (A + B)
#define GSMEM (4 * GSTAGE_B)            // 81920

__global__ __launch_bounds__(128, 2)
void gemm_bf16(const __nv_bfloat16* __restrict__ A, const __nv_bfloat16* __restrict__ Bt,
               float* __restrict__ C, int N) {
    extern __shared__ uint8_t sm[];
    const uint32_t smb = smem_u32(sm);

    const int tid = threadIdx.x;
    const int lane = tid & 31, wid = tid >> 5;
    const int wm = wid >> 1, wn = wid & 1;        // 2x2 warps -> 64x64 per warp
    const int m0 = blockIdx.y * 128, n0 = blockIdx.x * 128;

    // copy indices: thread tid owns row tid of A and of B (4x16B each per stage)
    const __nv_bfloat16* agp = A  + (size_t)(m0 + tid) * K3_;
    const __nv_bfloat16* bgp = Bt + (size_t)(n0 + tid) * K3_;
    const uint32_t sa_rel = (uint32_t)(tid * SMPAD);
    const uint32_t sb_rel = sa_rel + 128 * SMPAD;

    float acc[4][8][4];
#pragma unroll
    for (int i = 0; i < 4; i++)
#pragma unroll
        for (int j = 0; j < 8; j++)
#pragma unroll
            for (int r = 0; r < 4; r++) acc[i][j][r] = 0.0f;

    const int nK = K3_ / 32;   // 192

    // prologue: stages 0..2
#pragma unroll
    for (int s = 0; s < 3; s++) {
        const uint32_t base = smb + s * GSTAGE_B;
        const int k0 = s * 32;
#pragma unroll
        for (int c = 0; c < 4; c++) {
            CP_ASYNC16(base + sa_rel + c * 16, agp + k0 + c * 8);
            CP_ASYNC16(base + sb_rel + c * 16, bgp + k0 + c * 8);
        }
        CP_COMMIT();
    }

    const int lj = lane >> 3, lr = lane & 7;
    const uint32_t a_rel = (uint32_t)((wm * 64 + ((lj & 1) << 3) + lr) * SMPAD + ((lj >> 1) << 4));
    const uint32_t b_rel = (uint32_t)(128 * SMPAD + (wn * 64 + ((lj >> 1) << 3) + lr) * SMPAD + ((lj & 1) << 4));

    for (int it = 0; it < nK; it++) {
        CP_WAIT(2);                 // stage `it` resident
        __syncthreads();
        const int is = it + 3;
        if (is < nK) {
            const uint32_t base = smb + (is & 3) * GSTAGE_B;
            const int k0 = is * 32;
#pragma unroll
            for (int c = 0; c < 4; c++) {
                CP_ASYNC16(base + sa_rel + c * 16, agp + k0 + c * 8);
                CP_ASYNC16(base + sb_rel + c * 16, bgp + k0 + c * 8);
            }
        }
        CP_COMMIT();

        const uint32_t stg = smb + (it & 3) * GSTAGE_B;
#pragma unroll
        for (int kk = 0; kk < 2; kk++) {
            uint32_t af[4][4];
#pragma unroll
            for (int i = 0; i < 4; i++)
                LDMX4(af[i][0], af[i][1], af[i][2], af[i][3],
                      stg + a_rel + i * 16 * SMPAD + kk * 32);
            uint32_t bf[8][2];
#pragma unroll
            for (int p = 0; p < 4; p++) {
                uint32_t r0, r1, r2, r3;
                LDMX4(r0, r1, r2, r3, stg + b_rel + p * 16 * SMPAD + kk * 32);
                bf[2 * p][0] = r0; bf[2 * p][1] = r1;
                bf[2 * p + 1][0] = r2; bf[2 * p + 1][1] = r3;
            }
#pragma unroll
            for (int i = 0; i < 4; i++)
#pragma unroll
                for (int j = 0; j < 8; j++)
                    MMA16816(acc[i][j], af[i][0], af[i][1], af[i][2], af[i][3],
                             bf[j][0], bf[j][1]);
        }
    }

    const int cr = lane >> 2, cc = (lane & 3) << 1;
#pragma unroll
    for (int i = 0; i < 4; i++) {
        const int mrow = m0 + wm * 64 + i * 16 + cr;
#pragma unroll
        for (int j = 0; j < 8; j++) {
            const int col = n0 + wn * 64 + j * 8 + cc;
            *(float2*)(C + (size_t)mrow * N + col)       = make_float2(acc[i][j][0], acc[i][j][1]);
            *(float2*)(C + (size_t)(mrow + 8) * N + col) = make_float2(acc[i][j][2], acc[i][j][3]);
        }
    }
}

// ---------------- RoPE + RMSNorm (+ fused K split) ----------------
__global__ __launch_bounds__(32)
void rope_rms_kernel(float* __restrict__ qkv,
                     const float* __restrict__ cosp, const float* __restrict__ sinp,
                     __nv_bfloat16* __restrict__ k2) {
    const int n  = blockIdx.x;
    const int bt = n / (H_ + KVH_);
    const int hh = n - bt * (H_ + KVH_);
    float* p = qkv + (size_t)bt * QKV_LD +
               ((hh < H_) ? (size_t)hh * 128 : (size_t)(2048 + (hh - H_) * 128));
    const int t = bt & (T_ - 1);
    const int l = threadIdx.x;

    float o1[2], o2[2];
    float ss = 0.0f;
#pragma unroll
    for (int u = 0; u < 2; u++) {
        int d = l + u * 32;
        float x1 = p[d];
        float x2 = p[d + 64];
        float c = cosp[t * 64 + d];
        float s = sinp[t * 64 + d];
        o1[u] = x1 * c + x2 * s;
        o2[u] = x2 * c - x1 * s;
        ss += o1[u] * o1[u] + o2[u] * o2[u];
    }
#pragma unroll
    for (int off = 16; off > 0; off >>= 1)
        ss += __shfl_xor_sync(0xffffffffu, ss, off);
    float r = rsqrtf(ss * (1.0f / 128.0f) + 1e-5f);
#pragma unroll
    for (int u = 0; u < 2; u++) {
        int d = l + u * 32;
        p[d]      = o1[u] * r;
        p[d + 64] = o2[u] * r;
    }
    if (hh >= H_) {
        const int kvh = hh - H_;
        const int b = bt >> 11;
        __nv_bfloat16* krow = k2 + ((size_t)(b * KVH_ + kvh) * T_ + t) * 256;
#pragma unroll
        for (int u = 0; u < 2; u++) {
            int d = l + u * 32;
            __nv_bfloat16 h1, l1, h2, l2;
            split2(o1[u] * r, h1, l1);
            split2(o2[u] * r, h2, l2);
            krow[d]            = h1;
            krow[128 + d]      = l1;
            krow[d + 64]       = h2;
            krow[128 + d + 64] = l2;
        }
    }
}

// ---------------- tensor-core flash attention ----------------
#define AQS 528
#define AVS 272
#define SM_Q 0
#define SM_K 33792
#define SM_V 67584
#define SM_RED 102400
#define ATT_SMEM 103424
#define ATT_SCALE 0.08838834764831845f

__global__ __launch_bounds__(256)
void attn_mma_kernel(const float* __restrict__ qkv,
                     const __nv_bfloat16* __restrict__ k2,
                     const __nv_bfloat16* __restrict__ vt,
                     __nv_bfloat16* __restrict__ ys) {
    extern __shared__ uint8_t sm[];
    const uint32_t smb = smem_u32(sm);
    float* redmax = (float*)(sm + SM_RED);
    float* redsum = (float*)(sm + SM_RED + 512);

    const int tid = threadIdx.x;
    const int lane = tid & 31, wid = tid >> 5;
    const int wm = wid >> 1, wn = wid & 1;
    const int qtile = 31 - blockIdx.x;
    const int bh = blockIdx.y;
    const int b  = bh >> 4;
    const int h  = bh & 15;
    const int kv = h >> 2;
    const int q0 = qtile * 64;

    const int crow = tid >> 2;
    const int cc0  = (tid & 3) * 32;

    {
        const float* qp = qkv + (size_t)(b * T_ + q0 + crow) * QKV_LD + h * 128 + cc0;
        uint8_t* qrow = sm + SM_Q + crow * AQS;
#pragma unroll
        for (int i = 0; i < 8; i++) {
            float4 v = *(const float4*)(qp + i * 4);
            __nv_bfloat16 h0, h1, h2, h3, l0, l1, l2, l3;
            split2(v.x, h0, l0); split2(v.y, h1, l1);
            split2(v.z, h2, l2); split2(v.w, h3, l3);
            int c = cc0 + i * 4;
            *(__nv_bfloat162*)(qrow + 2 * c)           = __halves2bfloat162(h0, h1);
            *(__nv_bfloat162*)(qrow + 2 * c + 4)       = __halves2bfloat162(h2, h3);
            *(__nv_bfloat162*)(qrow + 256 + 2 * c)     = __halves2bfloat162(l0, l1);
            *(__nv_bfloat162*)(qrow + 256 + 2 * c + 4) = __halves2bfloat162(l2, l3);
        }
    }

    const __nv_bfloat16* k2b = k2 + (size_t)(b * KVH_ + kv) * T_ * 256;
    const __nv_bfloat16* vtb = vt + (size_t)(b * KVH_ + kv) * 128 * (2 * T_);

    const int lj = lane >> 3, lr = lane & 7;
    const uint32_t a_off = smb + SM_Q + (uint32_t)((wm * 16 + ((lj & 1) << 3) + lr) * AQS + ((lj >> 1) << 4));
    uint32_t b_off[2];
#pragma unroll
    for (int p = 0; p < 2; p++)
        b_off[p] = smb + SM_K + (uint32_t)((wn * 32 + p * 16 + ((lj >> 1) << 3) + lr) * AQS + ((lj & 1) << 4));
    uint32_t v_off[8];
#pragma unroll
    for (int p = 0; p < 8; p++)
        v_off[p] = smb + SM_V + (uint32_t)((p * 16 + ((lj >> 1) << 3) + lr) * AVS + ((lj & 1) << 4));

    const int ra = lane >> 2;
    const int row_a = wm * 16 + ra, row_b = row_a + 8;
    const int colb = wn * 32 + 2 * (lane & 3);
    float m_a = -FLT_MAX, m_b = -FLT_MAX, l_a = 0.0f, l_b = 0.0f;

    float o[16][4];
#pragma unroll
    for (int j = 0; j < 16; j++)
#pragma unroll
        for (int r = 0; r < 4; r++) o[j][r] = 0.0f;

    const int krow = tid >> 2, kc = tid & 3;
    const int vrow = tid >> 1, vc = tid & 1;

    for (int jt = 0; jt <= qtile; jt++) {
        const int j0 = jt * 64;
        __syncthreads();
        {
            const uint4* src = (const uint4*)(k2b + (size_t)(j0 + krow) * 256);
            uint8_t* dst = sm + SM_K + krow * AQS;
#pragma unroll
            for (int i = 0; i < 8; i++) {
                int c = kc + i * 4;
                *(uint4*)(dst + c * 16) = src[c];
            }
        }
        {
            const __nv_bfloat16* srow = vtb + (size_t)vrow * (2 * T_) + j0;
            uint8_t* dst = sm + SM_V + vrow * AVS;
#pragma unroll
            for (int i = 0; i < 4; i++) {
                int c = vc + i * 2;
                *(uint4*)(dst + c * 16)       = *(const uint4*)(srow + c * 8);
                *(uint4*)(dst + 128 + c * 16) = *(const uint4*)(srow + T_ + c * 8);
            }
        }
        __syncthreads();

        float s_[4][4];
#pragma unroll
        for (int j = 0; j < 4; j++)
#pragma unroll
            for (int r = 0; r < 4; r++) s_[j][r] = 0.0f;

#pragma unroll
        for (int seg = 0; seg < 3; seg++) {
            const uint32_t abase = (seg == 1) ? 256u : 0u;
            const uint32_t bbase = (seg == 2) ? 256u : 0u;
#pragma unroll
            for (int kk = 0; kk < 8; kk++) {
                uint32_t af[4];
                LDMX4(af[0], af[1], af[2], af[3], a_off + abase + 32 * kk);
                uint32_t bf[4][2];
#pragma unroll
                for (int p = 0; p < 2; p++) {
                    uint32_t r0, r1, r2, r3;
                    LDMX4(r0, r1, r2, r3, b_off[p] + bbase + 32 * kk);
                    bf[2 * p][0] = r0; bf[2 * p][1] = r1;
                    bf[2 * p + 1][0] = r2; bf[2 * p + 1][1] = r3;
                }
#pragma unroll
                for (int j = 0; j < 4; j++)
                    MMA16816(s_[j], af[0], af[1], af[2], af[3], bf[j][0], bf[j][1]);
            }
        }

        const bool diag = (jt == qtile);
        float mxa = -FLT_MAX, mxb = -FLT_MAX;
#pragma unroll
        for (int j = 0; j < 4; j++)
#pragma unroll
            for (int e = 0; e < 2; e++) {
                int cg = colb + 8 * j + e;
                float va = s_[j][e] * ATT_SCALE;
                if (diag && cg > row_a) va = -FLT_MAX;
                s_[j][e] = va; mxa = fmaxf(mxa, va);
                float vb = s_[j][e + 2] * ATT_SCALE;
                if (diag && cg > row_b) vb = -FLT_MAX;
                s_[j][e + 2] = vb; mxb = fmaxf(mxb, vb);
            }
        mxa = fmaxf(mxa, __shfl_xor_sync(0xffffffffu, mxa, 1));
        mxa = fmaxf(mxa, __shfl_xor_sync(0xffffffffu, mxa, 2));
        mxb = fmaxf(mxb, __shfl_xor_sync(0xffffffffu, mxb, 1));
        mxb = fmaxf(mxb, __shfl_xor_sync(0xffffffffu, mxb, 2));
        if ((lane & 3) == 0) {
            redmax[wn * 64 + row_a] = mxa;
            redmax[wn * 64 + row_b] = mxb;
        }
        __syncthreads();
        float mna = fmaxf(m_a, fmaxf(redmax[row_a], redmax[64 + row_a]));
        float mnb = fmaxf(m_b, fmaxf(redmax[row_b], redmax[64 + row_b]));
        float fa = __expf(m_a - mna), fb = __expf(m_b - mnb);
        float sa = 0.0f, sb = 0.0f;
#pragma unroll
        for (int j = 0; j < 4; j++)
#pragma unroll
            for (int e = 0; e < 2; e++) {
                float pa = __expf(s_[j][e] - mna);
                s_[j][e] = pa; sa += pa;
                float pb = __expf(s_[j][e + 2] - mnb);
                s_[j][e + 2] = pb; sb += pb;
            }
        sa += __shfl_xor_sync(0xffffffffu, sa, 1);
        sa += __shfl_xor_sync(0xffffffffu, sa, 2);
        sb += __shfl_xor_sync(0xffffffffu, sb, 1);
        sb += __shfl_xor_sync(0xffffffffu, sb, 2);
        if ((lane & 3) == 0) {
            redsum[wn * 64 + row_a] = sa;
            redsum[wn * 64 + row_b] = sb;
        }
        __syncthreads();
        l_a = l_a * fa + redsum[row_a] + redsum[64 + row_a];
        l_b = l_b * fb + redsum[row_b] + redsum[64 + row_b];
        m_a = mna; m_b = mnb;

#pragma unroll
        for (int j = 0; j < 16; j++) {
            o[j][0] *= fa; o[j][1] *= fa;
            o[j][2] *= fb; o[j][3] *= fb;
        }

        uint32_t php0[4], php1[4], plp0[4], plp1[4];
#pragma unroll
        for (int j = 0; j < 4; j++) {
            __nv_bfloat162 h01 = __floats2bfloat162_rn(s_[j][0], s_[j][1]);
            __nv_bfloat162 h23 = __floats2bfloat162_rn(s_[j][2], s_[j][3]);
            php0[j] = *(uint32_t*)&h01;
            php1[j] = *(uint32_t*)&h23;
            plp0[j] = packbf2(s_[j][0] - __bfloat162float(__low2bfloat16(h01)),
                              s_[j][1] - __bfloat162float(__high2bfloat16(h01)));
            plp1[j] = packbf2(s_[j][2] - __bfloat162float(__low2bfloat16(h23)),
                              s_[j][3] - __bfloat162float(__high2bfloat16(h23)));
        }

#pragma unroll
        for (int seg = 0; seg < 3; seg++) {
            const bool useLo = (seg == 1);
            const uint32_t bbase = (seg == 2) ? (128u + wn * 64u) : (wn * 64u);
#pragma unroll
            for (int kk2 = 0; kk2 < 2; kk2++) {
                uint32_t a0 = useLo ? plp0[2 * kk2]     : php0[2 * kk2];
                uint32_t a1 = useLo ? plp1[2 * kk2]     : php1[2 * kk2];
                uint32_t a2 = useLo ? plp0[2 * kk2 + 1] : php0[2 * kk2 + 1];
                uint32_t a3 = useLo ? plp1[2 * kk2 + 1] : php1[2 * kk2 + 1];
                uint32_t vb[16][2];
#pragma unroll
                for (int p = 0; p < 8; p++) {
                    uint32_t r0, r1, r2, r3;
                    LDMX4(r0, r1, r2, r3, v_off[p] + bbase + 32 * kk2);
                    vb[2 * p][0] = r0; vb[2 * p][1] = r1;
                    vb[2 * p + 1][0] = r2; vb[2 * p + 1][1] = r3;
                }
#pragma unroll
                for (int j = 0; j < 16; j++)
                    MMA16816(o[j], a0, a1, a2, a3, vb[j][0], vb[j][1]);
            }
        }
    }

    __syncthreads();
    float* Ob = (float*)sm;
    if (wn == 1) {
#pragma unroll
        for (int j = 0; j < 16; j++) {
            int col = 8 * j + 2 * (lane & 3);
            *(float2*)&Ob[row_a * 132 + col] = make_float2(o[j][0], o[j][1]);
            *(float2*)&Ob[row_b * 132 + col] = make_float2(o[j][2], o[j][3]);
        }
    }
    __syncthreads();
    if (wn == 0) {
        float inva = 1.0f / l_a, invb = 1.0f / l_b;
        __nv_bfloat16* base = ys + (size_t)(b * T_ + q0) * K3_ + h * 128;
#pragma unroll
        for (int j = 0; j < 16; j++) {
            int col = 8 * j + 2 * (lane & 3);
            float2 pa = *(float2*)&Ob[row_a * 132 + col];
            float2 pb = *(float2*)&Ob[row_b * 132 + col];
            float va0 = (o[j][0] + pa.x) * inva, va1 = (o[j][1] + pa.y) * inva;
            float vb0 = (o[j][2] + pb.x) * invb, vb1 = (o[j][3] + pb.y) * invb;
            __nv_bfloat16 h0, l0, h1, l1;
            split2(va0, h0, l0); split2(va1, h1, l1);
            __nv_bfloat16* rp = base + (size_t)row_a * K3_ + col;
            *(__nv_bfloat162*)(rp)        = __halves2bfloat162(h0, h1);
            *(__nv_bfloat162*)(rp + 2048) = __halves2bfloat162(l0, l1);
            *(__nv_bfloat162*)(rp + 4096) = __halves2bfloat162(h0, h1);
            split2(vb0, h0, l0); split2(vb1, h1, l1);
            rp = base + (size_t)row_b * K3_ + col;
            *(__nv_bfloat162*)(rp)        = __halves2bfloat162(h0, h1);
            *(__nv_bfloat162*)(rp + 2048) = __halves2bfloat162(l0, l1);
            *(__nv_bfloat162*)(rp + 4096) = __halves2bfloat162(h0, h1);
        }
    }
}

// ---------------- launch ----------------
extern "C" void kernel_launch(void* const* d_in, const int* in_sizes, int n_in,
                              void* d_out, int out_size) {
    const float* x    = (const float*)d_in[0];
    const float* cosp = (const float*)d_in[1];
    const float* sinp = (const float*)d_in[2];
    const float* wq   = (const float*)d_in[3];
    const float* wk   = (const float*)d_in[4];
    const float* wv   = (const float*)d_in[5];
    const float* wo   = (const float*)d_in[6];
    float* out = (float*)d_out;

    __nv_bfloat16 *xs, *wb1, *wb2, *ys, *k2, *vt;
    float *qkv;
    cudaGetSymbolAddress((void**)&xs,  g_xs);
    cudaGetSymbolAddress((void**)&wb1, g_wb1);
    cudaGetSymbolAddress((void**)&wb2, g_wb2);
    cudaGetSymbolAddress((void**)&ys,  g_ys);
    cudaGetSymbolAddress((void**)&qkv, g_qkv);
    cudaGetSymbolAddress((void**)&k2,  g_k2);
    cudaGetSymbolAddress((void**)&vt,  g_vt);

    cudaFuncSetAttribute(attn_mma_kernel, cudaFuncAttributeMaxDynamicSharedMemorySize, ATT_SMEM);
    cudaFuncSetAttribute(gemm_bf16, cudaFuncAttributeMaxDynamicSharedMemorySize, GSMEM);

    dim3 tb(32, 8);
    split_a_kernel<<<(M_ * 2048 / 4) / 256, 256>>>(x, xs);
    tsplit_b_kernel<<<dim3(2048 / 32, 2048 / 32), tb>>>(wq, wb1, 2048);
    tsplit_b_kernel<<<dim3(512  / 32, 2048 / 32), tb>>>(wk, wb1 + (size_t)2048 * K3_, 512);
    tsplit_b_kernel<<<dim3(512  / 32, 2048 / 32), tb>>>(wv, wb1 + (size_t)2560 * K3_, 512);
    tsplit_b_kernel<<<dim3(2048 / 32, 2048 / 32), tb>>>(wo, wb2, 2048);

    gemm_bf16<<<dim3(3072 / 128, M_ / 128), 128, GSMEM>>>(xs, wb1, qkv, 3072);
    rope_rms_kernel<<<M_ * (H_ + KVH_), 32>>>(qkv, cosp, sinp, k2);
    split_v_kernel<<<dim3(4, 64, 8), tb>>>(qkv, vt);

    attn_mma_kernel<<<dim3(32, 32), 256, ATT_SMEM>>>(qkv, k2, vt, ys);
    gemm_bf16<<<dim3(2048 / 128, M_ / 128), 128, GSMEM>>>(ys, wb2, out, 2048);
}

// round 8
// speedup vs baseline: 1.2469x; 1.2469x over previous
#include <cuda_runtime.h>
#include <cuda_bf16.h>
#include <math.h>
#include <float.h>
#include <stdint.h>

#define B_   2
#define T_   2048
#define C_   2048
#define H_   16
#define KVH_ 4
#define HD_  128
#define M_   (B_*T_)           // 4096
#define K3_  6144              // 3 * 2048 (split-K)
#define QKV_LD 3072

// ---------------- scratch ----------------
__device__ __nv_bfloat16 g_xs [(size_t)M_ * K3_];
__device__ __nv_bfloat16 g_wb1[(size_t)3072 * K3_];
__device__ __nv_bfloat16 g_wb2[(size_t)2048 * K3_];
__device__ __nv_bfloat16 g_ys [(size_t)M_ * K3_];
__device__ float g_qkv[(size_t)M_ * QKV_LD];
__device__ __nv_bfloat16 g_k2[(size_t)B_ * KVH_ * T_ * 256];        // [bkv][t][hi128|lo128]
__device__ __nv_bfloat16 g_vt[(size_t)B_ * KVH_ * HD_ * 2 * T_];    // [bkv][d][hi T|lo T]

// ---------------- helpers ----------------
__device__ __forceinline__ void split2(float v, __nv_bfloat16& h, __nv_bfloat16& l) {
    h = __float2bfloat16_rn(v);
    l = __float2bfloat16_rn(v - __bfloat162float(h));
}
__device__ __forceinline__ uint32_t smem_u32(const void* p) {
    uint32_t a;
    asm("{ .reg .u64 t; cvta.to.shared.u64 t, %1; cvt.u32.u64 %0, t; }" : "=r"(a) : "l"(p));
    return a;
}
__device__ __forceinline__ uint32_t packbf2(float x, float y) {
    __nv_bfloat162 t = __floats2bfloat162_rn(x, y);
    return *(uint32_t*)&t;
}
#define LDMX4(r0, r1, r2, r3, addr) \
    asm volatile("ldmatrix.sync.aligned.m8n8.x4.shared.b16 {%0,%1,%2,%3}, [%4];" \
        : "=r"(r0), "=r"(r1), "=r"(r2), "=r"(r3) : "r"(addr))
#define MMA16816(c, a0, a1, a2, a3, b0, b1) \
    asm volatile("mma.sync.aligned.m16n8k16.row.col.f32.bf16.bf16.f32 " \
        "{%0,%1,%2,%3}, {%4,%5,%6,%7}, {%8,%9}, {%0,%1,%2,%3};" \
        : "+f"((c)[0]), "+f"((c)[1]), "+f"((c)[2]), "+f"((c)[3]) \
        : "r"(a0), "r"(a1), "r"(a2), "r"(a3), "r"(b0), "r"(b1))
#define CP_ASYNC16(dst, src) \
    asm volatile("cp.async.cg.shared.global [%0], [%1], 16;" :: "r"(dst), "l"(src) : "memory")
#define CP_COMMIT() asm volatile("cp.async.commit_group;" ::: "memory")
#define CP_WAIT(n)  asm volatile("cp.async.wait_group %0;" :: "n"(n) : "memory")

// ---------------- split kernels ----------------
__global__ __launch_bounds__(256)
void split_a_kernel(const float* __restrict__ src, __nv_bfloat16* __restrict__ dst) {
    int idx = blockIdx.x * 256 + threadIdx.x;
    int m = idx >> 9;
    int k = (idx & 511) << 2;
    float4 v = *(const float4*)(src + (size_t)m * 2048 + k);
    __nv_bfloat16 h0, h1, h2, h3, l0, l1, l2, l3;
    split2(v.x, h0, l0); split2(v.y, h1, l1);
    split2(v.z, h2, l2); split2(v.w, h3, l3);
    __nv_bfloat162 H0 = __halves2bfloat162(h0, h1), H1 = __halves2bfloat162(h2, h3);
    __nv_bfloat162 L0 = __halves2bfloat162(l0, l1), L1 = __halves2bfloat162(l2, l3);
    __nv_bfloat162* d0 = (__nv_bfloat162*)(dst + (size_t)m * K3_ + k);
    d0[0] = H0; d0[1] = H1;
    __nv_bfloat162* d1 = (__nv_bfloat162*)(dst + (size_t)m * K3_ + 2048 + k);
    d1[0] = L0; d1[1] = L1;
    __nv_bfloat162* d2 = (__nv_bfloat162*)(dst + (size_t)m * K3_ + 4096 + k);
    d2[0] = H0; d2[1] = H1;
}

__global__ __launch_bounds__(256)
void tsplit_b_kernel(const float* __restrict__ src, __nv_bfloat16* __restrict__ dst, int Ncols) {
    __shared__ float t[32][33];
    const int n0 = blockIdx.x * 32, k0 = blockIdx.y * 32;
    const int tx = threadIdx.x, ty = threadIdx.y;
#pragma unroll
    for (int i = 0; i < 4; i++)
        t[ty + i * 8][tx] = src[(size_t)(k0 + ty + i * 8) * Ncols + n0 + tx];
    __syncthreads();
#pragma unroll
    for (int i = 0; i < 4; i++) {
        float v = t[tx][ty + i * 8];
        __nv_bfloat16 h, l;
        split2(v, h, l);
        __nv_bfloat16* row = dst + (size_t)(n0 + ty + i * 8) * K3_ + k0 + tx;
        row[0]    = h;
        row[2048] = h;
        row[4096] = l;
    }
}

// ---------------- V transpose+split ----------------
__global__ __launch_bounds__(256)
void split_v_kernel(const float* __restrict__ qkv, __nv_bfloat16* __restrict__ vt) {
    __shared__ float tbuf[32][33];
    const int d0 = blockIdx.x * 32;
    const int t0 = blockIdx.y * 32;
    const int bkv = blockIdx.z;
    const int b = bkv >> 2, kv = bkv & 3;
    const int tx = threadIdx.x, ty = threadIdx.y;
#pragma unroll
    for (int i = 0; i < 4; i++)
        tbuf[ty + i * 8][tx] =
            qkv[(size_t)(b * T_ + t0 + ty + i * 8) * QKV_LD + 2560 + kv * 128 + d0 + tx];
    __syncthreads();
#pragma unroll
    for (int i = 0; i < 4; i++) {
        float v = tbuf[tx][ty + i * 8];
        __nv_bfloat16 h, l;
        split2(v, h, l);
        __nv_bfloat16* row = vt + ((size_t)bkv * 128 + d0 + ty + i * 8) * (2 * T_) + t0 + tx;
        row[0]  = h;
        row[T_] = l;
    }
}

// ---------------- bf16 mma.sync GEMM, round-6 proven config ----------------
#define SMPAD 80
#define GSTAGE_B (2 * 128 * SMPAD)      // 20480 per stage (A + B)
#define GSMEM (4 * GSTAGE_B)            // 81920

__global__ __launch_bounds__(256, 2)
void gemm_bf16(const __nv_bfloat16* __restrict__ A, const __nv_bfloat16* __restrict__ Bt,
               float* __restrict__ C, int N) {
    extern __shared__ uint8_t sm[];
    const uint32_t smb = smem_u32(sm);

    const int tid = threadIdx.x;
    const int lane = tid & 31, wid = tid >> 5;
    const int wm = wid >> 1, wn = wid & 1;
    const int m0 = blockIdx.y * 128, n0 = blockIdx.x * 128;

    const int crow = tid >> 1;
    const int cc2  = (tid & 1) * 2;
    const __nv_bfloat16* agp = A  + (size_t)(m0 + crow) * K3_ + cc2 * 8;
    const __nv_bfloat16* bgp = Bt + (size_t)(n0 + crow) * K3_ + cc2 * 8;
    const uint32_t sa_rel = (uint32_t)(crow * SMPAD + cc2 * 16);
    const uint32_t sb_rel = sa_rel + 128 * SMPAD;

    float acc[2][8][4];
#pragma unroll
    for (int i = 0; i < 2; i++)
#pragma unroll
        for (int j = 0; j < 8; j++)
#pragma unroll
            for (int r = 0; r < 4; r++) acc[i][j][r] = 0.0f;

    const int nK = K3_ / 32;   // 192

#pragma unroll
    for (int s = 0; s < 3; s++) {
        const uint32_t base = smb + s * GSTAGE_B;
        const int k0 = s * 32;
        CP_ASYNC16(base + sa_rel,      agp + k0);
        CP_ASYNC16(base + sa_rel + 16, agp + k0 + 8);
        CP_ASYNC16(base + sb_rel,      bgp + k0);
        CP_ASYNC16(base + sb_rel + 16, bgp + k0 + 8);
        CP_COMMIT();
    }

    const int lj = lane >> 3, lr = lane & 7;
    const uint32_t a_rel = (uint32_t)((wm * 32 + ((lj & 1) << 3) + lr) * SMPAD + ((lj >> 1) << 4));
    const uint32_t b_rel = (uint32_t)(128 * SMPAD + (wn * 64 + ((lj >> 1) << 3) + lr) * SMPAD + ((lj & 1) << 4));

    for (int it = 0; it < nK; it++) {
        CP_WAIT(2);
        __syncthreads();
        const int is = it + 3;
        if (is < nK) {
            const uint32_t base = smb + (is & 3) * GSTAGE_B;
            const int k0 = is * 32;
            CP_ASYNC16(base + sa_rel,      agp + k0);
            CP_ASYNC16(base + sa_rel + 16, agp + k0 + 8);
            CP_ASYNC16(base + sb_rel,      bgp + k0);
            CP_ASYNC16(base + sb_rel + 16, bgp + k0 + 8);
        }
        CP_COMMIT();

        const uint32_t stg = smb + (it & 3) * GSTAGE_B;
#pragma unroll
        for (int kk = 0; kk < 2; kk++) {
            uint32_t af[2][4];
#pragma unroll
            for (int i = 0; i < 2; i++)
                LDMX4(af[i][0], af[i][1], af[i][2], af[i][3],
                      stg + a_rel + i * 16 * SMPAD + kk * 32);
            uint32_t bf[8][2];
#pragma unroll
            for (int p = 0; p < 4; p++) {
                uint32_t r0, r1, r2, r3;
                LDMX4(r0, r1, r2, r3, stg + b_rel + p * 16 * SMPAD + kk * 32);
                bf[2 * p][0] = r0; bf[2 * p][1] = r1;
                bf[2 * p + 1][0] = r2; bf[2 * p + 1][1] = r3;
            }
#pragma unroll
            for (int i = 0; i < 2; i++)
#pragma unroll
                for (int j = 0; j < 8; j++)
                    MMA16816(acc[i][j], af[i][0], af[i][1], af[i][2], af[i][3],
                             bf[j][0], bf[j][1]);
        }
    }

    const int cr = lane >> 2, cc = (lane & 3) << 1;
#pragma unroll
    for (int i = 0; i < 2; i++) {
        const int mrow = m0 + wm * 32 + i * 16 + cr;
#pragma unroll
        for (int j = 0; j < 8; j++) {
            const int col = n0 + wn * 64 + j * 8 + cc;
            *(float2*)(C + (size_t)mrow * N + col)       = make_float2(acc[i][j][0], acc[i][j][1]);
            *(float2*)(C + (size_t)(mrow + 8) * N + col) = make_float2(acc[i][j][2], acc[i][j][3]);
        }
    }
}

// ---------------- RoPE + RMSNorm (+ fused K split) ----------------
__global__ __launch_bounds__(32)
void rope_rms_kernel(float* __restrict__ qkv,
                     const float* __restrict__ cosp, const float* __restrict__ sinp,
                     __nv_bfloat16* __restrict__ k2) {
    const int n  = blockIdx.x;
    const int bt = n / (H_ + KVH_);
    const int hh = n - bt * (H_ + KVH_);
    float* p = qkv + (size_t)bt * QKV_LD +
               ((hh < H_) ? (size_t)hh * 128 : (size_t)(2048 + (hh - H_) * 128));
    const int t = bt & (T_ - 1);
    const int l = threadIdx.x;

    float o1[2], o2[2];
    float ss = 0.0f;
#pragma unroll
    for (int u = 0; u < 2; u++) {
        int d = l + u * 32;
        float x1 = p[d];
        float x2 = p[d + 64];
        float c = cosp[t * 64 + d];
        float s = sinp[t * 64 + d];
        o1[u] = x1 * c + x2 * s;
        o2[u] = x2 * c - x1 * s;
        ss += o1[u] * o1[u] + o2[u] * o2[u];
    }
#pragma unroll
    for (int off = 16; off > 0; off >>= 1)
        ss += __shfl_xor_sync(0xffffffffu, ss, off);
    float r = rsqrtf(ss * (1.0f / 128.0f) + 1e-5f);
#pragma unroll
    for (int u = 0; u < 2; u++) {
        int d = l + u * 32;
        p[d]      = o1[u] * r;
        p[d + 64] = o2[u] * r;
    }
    if (hh >= H_) {
        const int kvh = hh - H_;
        const int b = bt >> 11;
        __nv_bfloat16* krow = k2 + ((size_t)(b * KVH_ + kvh) * T_ + t) * 256;
#pragma unroll
        for (int u = 0; u < 2; u++) {
            int d = l + u * 32;
            __nv_bfloat16 h1, l1, h2, l2;
            split2(o1[u] * r, h1, l1);
            split2(o2[u] * r, h2, l2);
            krow[d]            = h1;
            krow[128 + d]      = l1;
            krow[d + 64]       = h2;
            krow[128 + d + 64] = l2;
        }
    }
}

// ---------------- tensor-core flash attention (double-buffered K/V via cp.async) ----------------
#define AQS 528
#define AVS 272
#define SM_Q   0
#define SM_K0  33792
#define SM_K1  (SM_K0 + 64 * AQS)     // 67584
#define SM_V0  (SM_K1 + 64 * AQS)     // 101376
#define SM_V1  (SM_V0 + 128 * AVS)    // 136192
#define SM_RED (SM_V1 + 128 * AVS)    // 171008
#define ATT_SMEM (SM_RED + 1024)      // 172032
#define ATT_SCALE 0.08838834764831845f

__global__ __launch_bounds__(256)
void attn_mma_kernel(const float* __restrict__ qkv,
                     const __nv_bfloat16* __restrict__ k2,
                     const __nv_bfloat16* __restrict__ vt,
                     __nv_bfloat16* __restrict__ ys) {
    extern __shared__ uint8_t sm[];
    const uint32_t smb = smem_u32(sm);
    float* redmax = (float*)(sm + SM_RED);
    float* redsum = (float*)(sm + SM_RED + 512);

    const int tid = threadIdx.x;
    const int lane = tid & 31, wid = tid >> 5;
    const int wm = wid >> 1, wn = wid & 1;
    const int qtile = 31 - blockIdx.x;
    const int bh = blockIdx.y;
    const int b  = bh >> 4;
    const int h  = bh & 15;
    const int kv = h >> 2;
    const int q0 = qtile * 64;

    const int crow = tid >> 2;
    const int cc0  = (tid & 3) * 32;

    const __nv_bfloat16* k2b = k2 + (size_t)(b * KVH_ + kv) * T_ * 256;
    const __nv_bfloat16* vtb = vt + (size_t)(b * KVH_ + kv) * 128 * (2 * T_);

    // copy indices (cp.async): K 64 rows x 32 chunks, V 128 rows x 16 chunks
    const int krow = tid >> 2, kc = tid & 3;
    const int vrow = tid >> 1, vc = tid & 1;
    const uint32_t kdst_rel = (uint32_t)(krow * AQS);
    const uint32_t vdst_rel = (uint32_t)(vrow * AVS);

    // ---- prologue: issue tile 0 loads, then convert Q while they fly ----
    {
        const __nv_bfloat16* src = k2b + (size_t)krow * 256;
#pragma unroll
        for (int i = 0; i < 8; i++) {
            int c = kc + i * 4;
            CP_ASYNC16(smb + SM_K0 + kdst_rel + c * 16, src + c * 8);
        }
        const __nv_bfloat16* srow = vtb + (size_t)vrow * (2 * T_);
#pragma unroll
        for (int i = 0; i < 4; i++) {
            int c = vc + i * 2;
            CP_ASYNC16(smb + SM_V0 + vdst_rel + c * 16,        srow + c * 8);
            CP_ASYNC16(smb + SM_V0 + vdst_rel + 128 + c * 16,  srow + T_ + c * 8);
        }
        CP_COMMIT();
    }

    // convert Q tile (overlaps tile-0 cp.async)
    {
        const float* qp = qkv + (size_t)(b * T_ + q0 + crow) * QKV_LD + h * 128 + cc0;
        uint8_t* qrow = sm + SM_Q + crow * AQS;
#pragma unroll
        for (int i = 0; i < 8; i++) {
            float4 v = *(const float4*)(qp + i * 4);
            __nv_bfloat16 h0, h1, h2, h3, l0, l1, l2, l3;
            split2(v.x, h0, l0); split2(v.y, h1, l1);
            split2(v.z, h2, l2); split2(v.w, h3, l3);
            int c = cc0 + i * 4;
            *(__nv_bfloat162*)(qrow + 2 * c)           = __halves2bfloat162(h0, h1);
            *(__nv_bfloat162*)(qrow + 2 * c + 4)       = __halves2bfloat162(h2, h3);
            *(__nv_bfloat162*)(qrow + 256 + 2 * c)     = __halves2bfloat162(l0, l1);
            *(__nv_bfloat162*)(qrow + 256 + 2 * c + 4) = __halves2bfloat162(l2, l3);
        }
    }

    const int lj = lane >> 3, lr = lane & 7;
    const uint32_t a_off = smb + SM_Q + (uint32_t)((wm * 16 + ((lj & 1) << 3) + lr) * AQS + ((lj >> 1) << 4));
    const uint32_t b_rel = (uint32_t)((wn * 32 + ((lj >> 1) << 3) + lr) * AQS + ((lj & 1) << 4));
    const uint32_t v_rel = (uint32_t)((((lj >> 1) << 3) + lr) * AVS + ((lj & 1) << 4));

    const int ra = lane >> 2;
    const int row_a = wm * 16 + ra, row_b = row_a + 8;
    const int colb = wn * 32 + 2 * (lane & 3);
    float m_a = -FLT_MAX, m_b = -FLT_MAX, l_a = 0.0f, l_b = 0.0f;

    float o[16][4];
#pragma unroll
    for (int j = 0; j < 16; j++)
#pragma unroll
        for (int r = 0; r < 4; r++) o[j][r] = 0.0f;

    for (int jt = 0; jt <= qtile; jt++) {
        const int buf = jt & 1;
        const uint32_t sK = smb + (buf ? SM_K1 : SM_K0);
        const uint32_t sV = smb + (buf ? SM_V1 : SM_V0);

        CP_WAIT(0);            // tile jt resident
        __syncthreads();       // all warps past tile jt-1 compute (other buffer now free)

        // issue tile jt+1 into the other buffer (overlaps this tile's compute)
        if (jt < qtile) {
            const int j1 = (jt + 1) * 64;
            const uint32_t dK = smb + (buf ? SM_K0 : SM_K1);
            const uint32_t dV = smb + (buf ? SM_V0 : SM_V1);
            const __nv_bfloat16* src = k2b + (size_t)(j1 + krow) * 256;
#pragma unroll
            for (int i = 0; i < 8; i++) {
                int c = kc + i * 4;
                CP_ASYNC16(dK + kdst_rel + c * 16, src + c * 8);
            }
            const __nv_bfloat16* srow = vtb + (size_t)vrow * (2 * T_) + j1;
#pragma unroll
            for (int i = 0; i < 4; i++) {
                int c = vc + i * 2;
                CP_ASYNC16(dV + vdst_rel + c * 16,       srow + c * 8);
                CP_ASYNC16(dV + vdst_rel + 128 + c * 16, srow + T_ + c * 8);
            }
        }
        CP_COMMIT();

        // ---- S = Q' K'^T (3 split segments) ----
        float s_[4][4];
#pragma unroll
        for (int j = 0; j < 4; j++)
#pragma unroll
            for (int r = 0; r < 4; r++) s_[j][r] = 0.0f;

#pragma unroll
        for (int seg = 0; seg < 3; seg++) {
            const uint32_t abase = (seg == 1) ? 256u : 0u;
            const uint32_t bbase = (seg == 2) ? 256u : 0u;
#pragma unroll
            for (int kk = 0; kk < 8; kk++) {
                uint32_t af[4];
                LDMX4(af[0], af[1], af[2], af[3], a_off + abase + 32 * kk);
                uint32_t bf[4][2];
#pragma unroll
                for (int p = 0; p < 2; p++) {
                    uint32_t r0, r1, r2, r3;
                    LDMX4(r0, r1, r2, r3, sK + b_rel + p * 16 * AQS + bbase + 32 * kk);
                    bf[2 * p][0] = r0; bf[2 * p][1] = r1;
                    bf[2 * p + 1][0] = r2; bf[2 * p + 1][1] = r3;
                }
#pragma unroll
                for (int j = 0; j < 4; j++)
                    MMA16816(s_[j], af[0], af[1], af[2], af[3], bf[j][0], bf[j][1]);
            }
        }

        // ---- online softmax ----
        const bool diag = (jt == qtile);
        const int j0 = jt * 64;
        float mxa = -FLT_MAX, mxb = -FLT_MAX;
#pragma unroll
        for (int j = 0; j < 4; j++)
#pragma unroll
            for (int e = 0; e < 2; e++) {
                int cg = colb + 8 * j + e;
                float va = s_[j][e] * ATT_SCALE;
                if (diag && cg > row_a) va = -FLT_MAX;
                s_[j][e] = va; mxa = fmaxf(mxa, va);
                float vb = s_[j][e + 2] * ATT_SCALE;
                if (diag && cg > row_b) vb = -FLT_MAX;
                s_[j][e + 2] = vb; mxb = fmaxf(mxb, vb);
            }
        (void)j0;
        mxa = fmaxf(mxa, __shfl_xor_sync(0xffffffffu, mxa, 1));
        mxa = fmaxf(mxa, __shfl_xor_sync(0xffffffffu, mxa, 2));
        mxb = fmaxf(mxb, __shfl_xor_sync(0xffffffffu, mxb, 1));
        mxb = fmaxf(mxb, __shfl_xor_sync(0xffffffffu, mxb, 2));
        if ((lane & 3) == 0) {
            redmax[wn * 64 + row_a] = mxa;
            redmax[wn * 64 + row_b] = mxb;
        }
        __syncthreads();
        float mna = fmaxf(m_a, fmaxf(redmax[row_a], redmax[64 + row_a]));
        float mnb = fmaxf(m_b, fmaxf(redmax[row_b], redmax[64 + row_b]));
        float fa = __expf(m_a - mna), fb = __expf(m_b - mnb);
        float sa = 0.0f, sb = 0.0f;
#pragma unroll
        for (int j = 0; j < 4; j++)
#pragma unroll
            for (int e = 0; e < 2; e++) {
                float pa = __expf(s_[j][e] - mna);
                s_[j][e] = pa; sa += pa;
                float pb = __expf(s_[j][e + 2] - mnb);
                s_[j][e + 2] = pb; sb += pb;
            }
        sa += __shfl_xor_sync(0xffffffffu, sa, 1);
        sa += __shfl_xor_sync(0xffffffffu, sa, 2);
        sb += __shfl_xor_sync(0xffffffffu, sb, 1);
        sb += __shfl_xor_sync(0xffffffffu, sb, 2);
        if ((lane & 3) == 0) {
            redsum[wn * 64 + row_a] = sa;
            redsum[wn * 64 + row_b] = sb;
        }
        __syncthreads();
        l_a = l_a * fa + redsum[row_a] + redsum[64 + row_a];
        l_b = l_b * fb + redsum[row_b] + redsum[64 + row_b];
        m_a = mna; m_b = mnb;

#pragma unroll
        for (int j = 0; j < 16; j++) {
            o[j][0] *= fa; o[j][1] *= fa;
            o[j][2] *= fb; o[j][3] *= fb;
        }

        uint32_t php0[4], php1[4], plp0[4], plp1[4];
#pragma unroll
        for (int j = 0; j < 4; j++) {
            __nv_bfloat162 h01 = __floats2bfloat162_rn(s_[j][0], s_[j][1]);
            __nv_bfloat162 h23 = __floats2bfloat162_rn(s_[j][2], s_[j][3]);
            php0[j] = *(uint32_t*)&h01;
            php1[j] = *(uint32_t*)&h23;
            plp0[j] = packbf2(s_[j][0] - __bfloat162float(__low2bfloat16(h01)),
                              s_[j][1] - __bfloat162float(__high2bfloat16(h01)));
            plp1[j] = packbf2(s_[j][2] - __bfloat162float(__low2bfloat16(h23)),
                              s_[j][3] - __bfloat162float(__high2bfloat16(h23)));
        }

#pragma unroll
        for (int seg = 0; seg < 3; seg++) {
            const bool useLo = (seg == 1);
            const uint32_t bbase = (seg == 2) ? (128u + wn * 64u) : (wn * 64u);
#pragma unroll
            for (int kk2 = 0; kk2 < 2; kk2++) {
                uint32_t a0 = useLo ? plp0[2 * kk2]     : php0[2 * kk2];
                uint32_t a1 = useLo ? plp1[2 * kk2]     : php1[2 * kk2];
                uint32_t a2 = useLo ? plp0[2 * kk2 + 1] : php0[2 * kk2 + 1];
                uint32_t a3 = useLo ? plp1[2 * kk2 + 1] : php1[2 * kk2 + 1];
                uint32_t vb[16][2];
#pragma unroll
                for (int p = 0; p < 8; p++) {
                    uint32_t r0, r1, r2, r3;
                    LDMX4(r0, r1, r2, r3, sV + v_rel + p * 16 * AVS + bbase + 32 * kk2);
                    vb[2 * p][0] = r0; vb[2 * p][1] = r1;
                    vb[2 * p + 1][0] = r2; vb[2 * p + 1][1] = r3;
                }
#pragma unroll
                for (int j = 0; j < 16; j++)
                    MMA16816(o[j], a0, a1, a2, a3, vb[j][0], vb[j][1]);
            }
        }
    }

    // ---- epilogue: combine partials, write split ys directly ----
    __syncthreads();
    float* Ob = (float*)sm;
    if (wn == 1) {
#pragma unroll
        for (int j = 0; j < 16; j++) {
            int col = 8 * j + 2 * (lane & 3);
            *(float2*)&Ob[row_a * 132 + col] = make_float2(o[j][0], o[j][1]);
            *(float2*)&Ob[row_b * 132 + col] = make_float2(o[j][2], o[j][3]);
        }
    }
    __syncthreads();
    if (wn == 0) {
        float inva = 1.0f / l_a, invb = 1.0f / l_b;
        __nv_bfloat16* base = ys + (size_t)(b * T_ + q0) * K3_ + h * 128;
#pragma unroll
        for (int j = 0; j < 16; j++) {
            int col = 8 * j + 2 * (lane & 3);
            float2 pa = *(float2*)&Ob[row_a * 132 + col];
            float2 pb = *(float2*)&Ob[row_b * 132 + col];
            float va0 = (o[j][0] + pa.x) * inva, va1 = (o[j][1] + pa.y) * inva;
            float vb0 = (o[j][2] + pb.x) * invb, vb1 = (o[j][3] + pb.y) * invb;
            __nv_bfloat16 h0, l0, h1, l1;
            split2(va0, h0, l0); split2(va1, h1, l1);
            __nv_bfloat16* rp = base + (size_t)row_a * K3_ + col;
            *(__nv_bfloat162*)(rp)        = __halves2bfloat162(h0, h1);
            *(__nv_bfloat162*)(rp + 2048) = __halves2bfloat162(l0, l1);
            *(__nv_bfloat162*)(rp + 4096) = __halves2bfloat162(h0, h1);
            split2(vb0, h0, l0); split2(vb1, h1, l1);
            rp = base + (size_t)row_b * K3_ + col;
            *(__nv_bfloat162*)(rp)        = __halves2bfloat162(h0, h1);
            *(__nv_bfloat162*)(rp + 2048) = __halves2bfloat162(l0, l1);
            *(__nv_bfloat162*)(rp + 4096) = __halves2bfloat162(h0, h1);
        }
    }
}

// ---------------- launch ----------------
extern "C" void kernel_launch(void* const* d_in, const int* in_sizes, int n_in,
                              void* d_out, int out_size) {
    const float* x    = (const float*)d_in[0];
    const float* cosp = (const float*)d_in[1];
    const float* sinp = (const float*)d_in[2];
    const float* wq   = (const float*)d_in[3];
    const float* wk   = (const float*)d_in[4];
    const float* wv   = (const float*)d_in[5];
    const float* wo   = (const float*)d_in[6];
    float* out = (float*)d_out;

    __nv_bfloat16 *xs, *wb1, *wb2, *ys, *k2, *vt;
    float *qkv;
    cudaGetSymbolAddress((void**)&xs,  g_xs);
    cudaGetSymbolAddress((void**)&wb1, g_wb1);
    cudaGetSymbolAddress((void**)&wb2, g_wb2);
    cudaGetSymbolAddress((void**)&ys,  g_ys);
    cudaGetSymbolAddress((void**)&qkv, g_qkv);
    cudaGetSymbolAddress((void**)&k2,  g_k2);
    cudaGetSymbolAddress((void**)&vt,  g_vt);

    cudaFuncSetAttribute(attn_mma_kernel, cudaFuncAttributeMaxDynamicSharedMemorySize, ATT_SMEM);
    cudaFuncSetAttribute(gemm_bf16, cudaFuncAttributeMaxDynamicSharedMemorySize, GSMEM);

    dim3 tb(32, 8);
    split_a_kernel<<<(M_ * 2048 / 4) / 256, 256>>>(x, xs);
    tsplit_b_kernel<<<dim3(2048 / 32, 2048 / 32), tb>>>(wq, wb1, 2048);
    tsplit_b_kernel<<<dim3(512  / 32, 2048 / 32), tb>>>(wk, wb1 + (size_t)2048 * K3_, 512);
    tsplit_b_kernel<<<dim3(512  / 32, 2048 / 32), tb>>>(wv, wb1 + (size_t)2560 * K3_, 512);
    tsplit_b_kernel<<<dim3(2048 / 32, 2048 / 32), tb>>>(wo, wb2, 2048);

    gemm_bf16<<<dim3(3072 / 128, M_ / 128), 256, GSMEM>>>(xs, wb1, qkv, 3072);
    rope_rms_kernel<<<M_ * (H_ + KVH_), 32>>>(qkv, cosp, sinp, k2);
    split_v_kernel<<<dim3(4, 64, 8), tb>>>(qkv, vt);

    attn_mma_kernel<<<dim3(32, 32), 256, ATT_SMEM>>>(qkv, k2, vt, ys);
    gemm_bf16<<<dim3(2048 / 128, M_ / 128), 256, GSMEM>>>(ys, wb2, out, 2048);
}

// round 9
// speedup vs baseline: 1.5805x; 1.2676x over previous
#include <cuda_runtime.h>
#include <cuda_bf16.h>
#include <cuda_fp16.h>
#include <math.h>
#include <float.h>
#include <stdint.h>

#define B_   2
#define T_   2048
#define C_   2048
#define H_   16
#define KVH_ 4
#define HD_  128
#define M_   (B_*T_)           // 4096
#define K2_  4096              // 2 * 2048 (fp16 [Ah|Al] x [Bh|Bh])
#define QKV_LD 3072

// ---------------- scratch ----------------
__device__ __half g_xs [(size_t)M_ * K2_];
__device__ __half g_wb1[(size_t)3072 * K2_];
__device__ __half g_wb2[(size_t)2048 * K2_];
__device__ __half g_ys [(size_t)M_ * K2_];
__device__ float g_qkv[(size_t)M_ * QKV_LD];
__device__ __nv_bfloat16 g_k2[(size_t)B_ * KVH_ * T_ * 256];        // [bkv][t][hi128|lo128]
__device__ __nv_bfloat16 g_vt[(size_t)B_ * KVH_ * HD_ * 2 * T_];    // [bkv][d][hi T|lo T]

// ---------------- helpers ----------------
__device__ __forceinline__ void split2(float v, __nv_bfloat16& h, __nv_bfloat16& l) {
    h = __float2bfloat16_rn(v);
    l = __float2bfloat16_rn(v - __bfloat162float(h));
}
__device__ __forceinline__ void split2h(float v, __half& h, __half& l) {
    h = __float2half_rn(v);
    l = __float2half_rn(v - __half2float(h));
}
__device__ __forceinline__ uint32_t smem_u32(const void* p) {
    uint32_t a;
    asm("{ .reg .u64 t; cvta.to.shared.u64 t, %1; cvt.u32.u64 %0, t; }" : "=r"(a) : "l"(p));
    return a;
}
__device__ __forceinline__ uint32_t packbf2(float x, float y) {
    __nv_bfloat162 t = __floats2bfloat162_rn(x, y);
    return *(uint32_t*)&t;
}
#define LDMX4(r0, r1, r2, r3, addr) \
    asm volatile("ldmatrix.sync.aligned.m8n8.x4.shared.b16 {%0,%1,%2,%3}, [%4];" \
        : "=r"(r0), "=r"(r1), "=r"(r2), "=r"(r3) : "r"(addr))
#define MMA16816BF(c, a0, a1, a2, a3, b0, b1) \
    asm volatile("mma.sync.aligned.m16n8k16.row.col.f32.bf16.bf16.f32 " \
        "{%0,%1,%2,%3}, {%4,%5,%6,%7}, {%8,%9}, {%0,%1,%2,%3};" \
        : "+f"((c)[0]), "+f"((c)[1]), "+f"((c)[2]), "+f"((c)[3]) \
        : "r"(a0), "r"(a1), "r"(a2), "r"(a3), "r"(b0), "r"(b1))
#define MMA16816F16(c, a0, a1, a2, a3, b0, b1) \
    asm volatile("mma.sync.aligned.m16n8k16.row.col.f32.f16.f16.f32 " \
        "{%0,%1,%2,%3}, {%4,%5,%6,%7}, {%8,%9}, {%0,%1,%2,%3};" \
        : "+f"((c)[0]), "+f"((c)[1]), "+f"((c)[2]), "+f"((c)[3]) \
        : "r"(a0), "r"(a1), "r"(a2), "r"(a3), "r"(b0), "r"(b1))
#define CP_ASYNC16(dst, src) \
    asm volatile("cp.async.cg.shared.global [%0], [%1], 16;" :: "r"(dst), "l"(src) : "memory")
#define CP_COMMIT() asm volatile("cp.async.commit_group;" ::: "memory")
#define CP_WAIT(n)  asm volatile("cp.async.wait_group %0;" :: "n"(n) : "memory")

// ---------------- split kernels (fp16 GEMM operands) ----------------
// x fp32 [M][2048] -> xs fp16 [M][hi 2048 | lo 2048]
__global__ __launch_bounds__(256)
void split_a_kernel(const float* __restrict__ src, __half* __restrict__ dst) {
    int idx = blockIdx.x * 256 + threadIdx.x;
    int m = idx >> 9;
    int k = (idx & 511) << 2;
    float4 v = *(const float4*)(src + (size_t)m * 2048 + k);
    __half h0, h1, h2, h3, l0, l1, l2, l3;
    split2h(v.x, h0, l0); split2h(v.y, h1, l1);
    split2h(v.z, h2, l2); split2h(v.w, h3, l3);
    __half2* d0 = (__half2*)(dst + (size_t)m * K2_ + k);
    d0[0] = __halves2half2(h0, h1); d0[1] = __halves2half2(h2, h3);
    __half2* d1 = (__half2*)(dst + (size_t)m * K2_ + 2048 + k);
    d1[0] = __halves2half2(l0, l1); d1[1] = __halves2half2(l2, l3);
}

// W fp32 [2048][Ncols] -> Bt fp16 [n][hi 2048 | hi 2048] (duplicated hi)
__global__ __launch_bounds__(256)
void tsplit_b_kernel(const float* __restrict__ src, __half* __restrict__ dst, int Ncols) {
    __shared__ float t[32][33];
    const int n0 = blockIdx.x * 32, k0 = blockIdx.y * 32;
    const int tx = threadIdx.x, ty = threadIdx.y;
#pragma unroll
    for (int i = 0; i < 4; i++)
        t[ty + i * 8][tx] = src[(size_t)(k0 + ty + i * 8) * Ncols + n0 + tx];
    __syncthreads();
#pragma unroll
    for (int i = 0; i < 4; i++) {
        __half h = __float2half_rn(t[tx][ty + i * 8]);
        __half* row = dst + (size_t)(n0 + ty + i * 8) * K2_ + k0 + tx;
        row[0]    = h;
        row[2048] = h;
    }
}

// ---------------- V transpose+split (bf16, attention) ----------------
__global__ __launch_bounds__(256)
void split_v_kernel(const float* __restrict__ qkv, __nv_bfloat16* __restrict__ vt) {
    __shared__ float tbuf[32][33];
    const int d0 = blockIdx.x * 32;
    const int t0 = blockIdx.y * 32;
    const int bkv = blockIdx.z;
    const int b = bkv >> 2, kv = bkv & 3;
    const int tx = threadIdx.x, ty = threadIdx.y;
#pragma unroll
    for (int i = 0; i < 4; i++)
        tbuf[ty + i * 8][tx] =
            qkv[(size_t)(b * T_ + t0 + ty + i * 8) * QKV_LD + 2560 + kv * 128 + d0 + tx];
    __syncthreads();
#pragma unroll
    for (int i = 0; i < 4; i++) {
        float v = tbuf[tx][ty + i * 8];
        __nv_bfloat16 h, l;
        split2(v, h, l);
        __nv_bfloat16* row = vt + ((size_t)bkv * 128 + d0 + ty + i * 8) * (2 * T_) + t0 + tx;
        row[0]  = h;
        row[T_] = l;
    }
}

// ---------------- fp16 mma.sync GEMM, 4-stage cp.async (round-6 proven shape) ----------------
#define SMPAD 80
#define GSTAGE_B (2 * 128 * SMPAD)      // 20480 per stage (A + B)
#define GSMEM (4 * GSTAGE_B)            // 81920

__global__ __launch_bounds__(256, 2)
void gemm_f16(const __half* __restrict__ A, const __half* __restrict__ Bt,
              float* __restrict__ C, int N) {
    extern __shared__ uint8_t sm[];
    const uint32_t smb = smem_u32(sm);

    const int tid = threadIdx.x;
    const int lane = tid & 31, wid = tid >> 5;
    const int wm = wid >> 1, wn = wid & 1;
    const int m0 = blockIdx.y * 128, n0 = blockIdx.x * 128;

    const int crow = tid >> 1;
    const int cc2  = (tid & 1) * 2;
    const __half* agp = A  + (size_t)(m0 + crow) * K2_ + cc2 * 8;
    const __half* bgp = Bt + (size_t)(n0 + crow) * K2_ + cc2 * 8;
    const uint32_t sa_rel = (uint32_t)(crow * SMPAD + cc2 * 16);
    const uint32_t sb_rel = sa_rel + 128 * SMPAD;

    float acc[2][8][4];
#pragma unroll
    for (int i = 0; i < 2; i++)
#pragma unroll
        for (int j = 0; j < 8; j++)
#pragma unroll
            for (int r = 0; r < 4; r++) acc[i][j][r] = 0.0f;

    const int nK = K2_ / 32;   // 128

#pragma unroll
    for (int s = 0; s < 3; s++) {
        const uint32_t base = smb + s * GSTAGE_B;
        const int k0 = s * 32;
        CP_ASYNC16(base + sa_rel,      agp + k0);
        CP_ASYNC16(base + sa_rel + 16, agp + k0 + 8);
        CP_ASYNC16(base + sb_rel,      bgp + k0);
        CP_ASYNC16(base + sb_rel + 16, bgp + k0 + 8);
        CP_COMMIT();
    }

    const int lj = lane >> 3, lr = lane & 7;
    const uint32_t a_rel = (uint32_t)((wm * 32 + ((lj & 1) << 3) + lr) * SMPAD + ((lj >> 1) << 4));
    const uint32_t b_rel = (uint32_t)(128 * SMPAD + (wn * 64 + ((lj >> 1) << 3) + lr) * SMPAD + ((lj & 1) << 4));

    for (int it = 0; it < nK; it++) {
        CP_WAIT(2);
        __syncthreads();
        const int is = it + 3;
        if (is < nK) {
            const uint32_t base = smb + (is & 3) * GSTAGE_B;
            const int k0 = is * 32;
            CP_ASYNC16(base + sa_rel,      agp + k0);
            CP_ASYNC16(base + sa_rel + 16, agp + k0 + 8);
            CP_ASYNC16(base + sb_rel,      bgp + k0);
            CP_ASYNC16(base + sb_rel + 16, bgp + k0 + 8);
        }
        CP_COMMIT();

        const uint32_t stg = smb + (it & 3) * GSTAGE_B;
#pragma unroll
        for (int kk = 0; kk < 2; kk++) {
            uint32_t af[2][4];
#pragma unroll
            for (int i = 0; i < 2; i++)
                LDMX4(af[i][0], af[i][1], af[i][2], af[i][3],
                      stg + a_rel + i * 16 * SMPAD + kk * 32);
            uint32_t bf[8][2];
#pragma unroll
            for (int p = 0; p < 4; p++) {
                uint32_t r0, r1, r2, r3;
                LDMX4(r0, r1, r2, r3, stg + b_rel + p * 16 * SMPAD + kk * 32);
                bf[2 * p][0] = r0; bf[2 * p][1] = r1;
                bf[2 * p + 1][0] = r2; bf[2 * p + 1][1] = r3;
            }
#pragma unroll
            for (int i = 0; i < 2; i++)
#pragma unroll
                for (int j = 0; j < 8; j++)
                    MMA16816F16(acc[i][j], af[i][0], af[i][1], af[i][2], af[i][3],
                                bf[j][0], bf[j][1]);
        }
    }

    const int cr = lane >> 2, cc = (lane & 3) << 1;
#pragma unroll
    for (int i = 0; i < 2; i++) {
        const int mrow = m0 + wm * 32 + i * 16 + cr;
#pragma unroll
        for (int j = 0; j < 8; j++) {
            const int col = n0 + wn * 64 + j * 8 + cc;
            *(float2*)(C + (size_t)mrow * N + col)       = make_float2(acc[i][j][0], acc[i][j][1]);
            *(float2*)(C + (size_t)(mrow + 8) * N + col) = make_float2(acc[i][j][2], acc[i][j][3]);
        }
    }
}

// ---------------- RoPE + RMSNorm (+ fused K split) ----------------
__global__ __launch_bounds__(32)
void rope_rms_kernel(float* __restrict__ qkv,
                     const float* __restrict__ cosp, const float* __restrict__ sinp,
                     __nv_bfloat16* __restrict__ k2) {
    const int n  = blockIdx.x;
    const int bt = n / (H_ + KVH_);
    const int hh = n - bt * (H_ + KVH_);
    float* p = qkv + (size_t)bt * QKV_LD +
               ((hh < H_) ? (size_t)hh * 128 : (size_t)(2048 + (hh - H_) * 128));
    const int t = bt & (T_ - 1);
    const int l = threadIdx.x;

    float o1[2], o2[2];
    float ss = 0.0f;
#pragma unroll
    for (int u = 0; u < 2; u++) {
        int d = l + u * 32;
        float x1 = p[d];
        float x2 = p[d + 64];
        float c = cosp[t * 64 + d];
        float s = sinp[t * 64 + d];
        o1[u] = x1 * c + x2 * s;
        o2[u] = x2 * c - x1 * s;
        ss += o1[u] * o1[u] + o2[u] * o2[u];
    }
#pragma unroll
    for (int off = 16; off > 0; off >>= 1)
        ss += __shfl_xor_sync(0xffffffffu, ss, off);
    float r = rsqrtf(ss * (1.0f / 128.0f) + 1e-5f);
#pragma unroll
    for (int u = 0; u < 2; u++) {
        int d = l + u * 32;
        p[d]      = o1[u] * r;
        p[d + 64] = o2[u] * r;
    }
    if (hh >= H_) {
        const int kvh = hh - H_;
        const int b = bt >> 11;
        __nv_bfloat16* krow = k2 + ((size_t)(b * KVH_ + kvh) * T_ + t) * 256;
#pragma unroll
        for (int u = 0; u < 2; u++) {
            int d = l + u * 32;
            __nv_bfloat16 h1, l1, h2, l2;
            split2(o1[u] * r, h1, l1);
            split2(o2[u] * r, h2, l2);
            krow[d]            = h1;
            krow[128 + d]      = l1;
            krow[d + 64]       = h2;
            krow[128 + d + 64] = l2;
        }
    }
}

// ---------------- tensor-core flash attention (double-buffered K/V via cp.async) ----------------
#define AQS 528
#define AVS 272
#define SM_Q   0
#define SM_K0  33792
#define SM_K1  (SM_K0 + 64 * AQS)     // 67584
#define SM_V0  (SM_K1 + 64 * AQS)     // 101376
#define SM_V1  (SM_V0 + 128 * AVS)    // 136192
#define SM_RED (SM_V1 + 128 * AVS)    // 171008
#define ATT_SMEM (SM_RED + 1024)      // 172032
#define ATT_SCALE 0.08838834764831845f

__global__ __launch_bounds__(256)
void attn_mma_kernel(const float* __restrict__ qkv,
                     const __nv_bfloat16* __restrict__ k2,
                     const __nv_bfloat16* __restrict__ vt,
                     __half* __restrict__ ys) {
    extern __shared__ uint8_t sm[];
    const uint32_t smb = smem_u32(sm);
    float* redmax = (float*)(sm + SM_RED);
    float* redsum = (float*)(sm + SM_RED + 512);

    const int tid = threadIdx.x;
    const int lane = tid & 31, wid = tid >> 5;
    const int wm = wid >> 1, wn = wid & 1;
    const int qtile = 31 - blockIdx.x;
    const int bh = blockIdx.y;
    const int b  = bh >> 4;
    const int h  = bh & 15;
    const int kv = h >> 2;
    const int q0 = qtile * 64;

    const int crow = tid >> 2;
    const int cc0  = (tid & 3) * 32;

    const __nv_bfloat16* k2b = k2 + (size_t)(b * KVH_ + kv) * T_ * 256;
    const __nv_bfloat16* vtb = vt + (size_t)(b * KVH_ + kv) * 128 * (2 * T_);

    const int krow = tid >> 2, kc = tid & 3;
    const int vrow = tid >> 1, vc = tid & 1;
    const uint32_t kdst_rel = (uint32_t)(krow * AQS);
    const uint32_t vdst_rel = (uint32_t)(vrow * AVS);

    // prologue: issue tile 0 loads, convert Q while in flight
    {
        const __nv_bfloat16* src = k2b + (size_t)krow * 256;
#pragma unroll
        for (int i = 0; i < 8; i++) {
            int c = kc + i * 4;
            CP_ASYNC16(smb + SM_K0 + kdst_rel + c * 16, src + c * 8);
        }
        const __nv_bfloat16* srow = vtb + (size_t)vrow * (2 * T_);
#pragma unroll
        for (int i = 0; i < 4; i++) {
            int c = vc + i * 2;
            CP_ASYNC16(smb + SM_V0 + vdst_rel + c * 16,        srow + c * 8);
            CP_ASYNC16(smb + SM_V0 + vdst_rel + 128 + c * 16,  srow + T_ + c * 8);
        }
        CP_COMMIT();
    }

    {
        const float* qp = qkv + (size_t)(b * T_ + q0 + crow) * QKV_LD + h * 128 + cc0;
        uint8_t* qrow = sm + SM_Q + crow * AQS;
#pragma unroll
        for (int i = 0; i < 8; i++) {
            float4 v = *(const float4*)(qp + i * 4);
            __nv_bfloat16 h0, h1, h2, h3, l0, l1, l2, l3;
            split2(v.x, h0, l0); split2(v.y, h1, l1);
            split2(v.z, h2, l2); split2(v.w, h3, l3);
            int c = cc0 + i * 4;
            *(__nv_bfloat162*)(qrow + 2 * c)           = __halves2bfloat162(h0, h1);
            *(__nv_bfloat162*)(qrow + 2 * c + 4)       = __halves2bfloat162(h2, h3);
            *(__nv_bfloat162*)(qrow + 256 + 2 * c)     = __halves2bfloat162(l0, l1);
            *(__nv_bfloat162*)(qrow + 256 + 2 * c + 4) = __halves2bfloat162(l2, l3);
        }
    }

    const int lj = lane >> 3, lr = lane & 7;
    const uint32_t a_off = smb + SM_Q + (uint32_t)((wm * 16 + ((lj & 1) << 3) + lr) * AQS + ((lj >> 1) << 4));
    const uint32_t b_rel = (uint32_t)((wn * 32 + ((lj >> 1) << 3) + lr) * AQS + ((lj & 1) << 4));
    const uint32_t v_rel = (uint32_t)((((lj >> 1) << 3) + lr) * AVS + ((lj & 1) << 4));

    const int ra = lane >> 2;
    const int row_a = wm * 16 + ra, row_b = row_a + 8;
    const int colb = wn * 32 + 2 * (lane & 3);
    float m_a = -FLT_MAX, m_b = -FLT_MAX, l_a = 0.0f, l_b = 0.0f;

    float o[16][4];
#pragma unroll
    for (int j = 0; j < 16; j++)
#pragma unroll
        for (int r = 0; r < 4; r++) o[j][r] = 0.0f;

    for (int jt = 0; jt <= qtile; jt++) {
        const int buf = jt & 1;
        const uint32_t sK = smb + (buf ? SM_K1 : SM_K0);
        const uint32_t sV = smb + (buf ? SM_V1 : SM_V0);

        CP_WAIT(0);
        __syncthreads();

        if (jt < qtile) {
            const int j1 = (jt + 1) * 64;
            const uint32_t dK = smb + (buf ? SM_K0 : SM_K1);
            const uint32_t dV = smb + (buf ? SM_V0 : SM_V1);
            const __nv_bfloat16* src = k2b + (size_t)(j1 + krow) * 256;
#pragma unroll
            for (int i = 0; i < 8; i++) {
                int c = kc + i * 4;
                CP_ASYNC16(dK + kdst_rel + c * 16, src + c * 8);
            }
            const __nv_bfloat16* srow = vtb + (size_t)vrow * (2 * T_) + j1;
#pragma unroll
            for (int i = 0; i < 4; i++) {
                int c = vc + i * 2;
                CP_ASYNC16(dV + vdst_rel + c * 16,       srow + c * 8);
                CP_ASYNC16(dV + vdst_rel + 128 + c * 16, srow + T_ + c * 8);
            }
        }
        CP_COMMIT();

        float s_[4][4];
#pragma unroll
        for (int j = 0; j < 4; j++)
#pragma unroll
            for (int r = 0; r < 4; r++) s_[j][r] = 0.0f;

#pragma unroll
        for (int seg = 0; seg < 3; seg++) {
            const uint32_t abase = (seg == 1) ? 256u : 0u;
            const uint32_t bbase = (seg == 2) ? 256u : 0u;
#pragma unroll
            for (int kk = 0; kk < 8; kk++) {
                uint32_t af[4];
                LDMX4(af[0], af[1], af[2], af[3], a_off + abase + 32 * kk);
                uint32_t bf[4][2];
#pragma unroll
                for (int p = 0; p < 2; p++) {
                    uint32_t r0, r1, r2, r3;
                    LDMX4(r0, r1, r2, r3, sK + b_rel + p * 16 * AQS + bbase + 32 * kk);
                    bf[2 * p][0] = r0; bf[2 * p][1] = r1;
                    bf[2 * p + 1][0] = r2; bf[2 * p + 1][1] = r3;
                }
#pragma unroll
                for (int j = 0; j < 4; j++)
                    MMA16816BF(s_[j], af[0], af[1], af[2], af[3], bf[j][0], bf[j][1]);
            }
        }

        const bool diag = (jt == qtile);
        float mxa = -FLT_MAX, mxb = -FLT_MAX;
#pragma unroll
        for (int j = 0; j < 4; j++)
#pragma unroll
            for (int e = 0; e < 2; e++) {
                int cg = colb + 8 * j + e;
                float va = s_[j][e] * ATT_SCALE;
                if (diag && cg > row_a) va = -FLT_MAX;
                s_[j][e] = va; mxa = fmaxf(mxa, va);
                float vb = s_[j][e + 2] * ATT_SCALE;
                if (diag && cg > row_b) vb = -FLT_MAX;
                s_[j][e + 2] = vb; mxb = fmaxf(mxb, vb);
            }
        mxa = fmaxf(mxa, __shfl_xor_sync(0xffffffffu, mxa, 1));
        mxa = fmaxf(mxa, __shfl_xor_sync(0xffffffffu, mxa, 2));
        mxb = fmaxf(mxb, __shfl_xor_sync(0xffffffffu, mxb, 1));
        mxb = fmaxf(mxb, __shfl_xor_sync(0xffffffffu, mxb, 2));
        if ((lane & 3) == 0) {
            redmax[wn * 64 + row_a] = mxa;
            redmax[wn * 64 + row_b] = mxb;
        }
        __syncthreads();
        float mna = fmaxf(m_a, fmaxf(redmax[row_a], redmax[64 + row_a]));
        float mnb = fmaxf(m_b, fmaxf(redmax[row_b], redmax[64 + row_b]));
        float fa = __expf(m_a - mna), fb = __expf(m_b - mnb);
        float sa = 0.0f, sb = 0.0f;
#pragma unroll
        for (int j = 0; j < 4; j++)
#pragma unroll
            for (int e = 0; e < 2; e++) {
                float pa = __expf(s_[j][e] - mna);
                s_[j][e] = pa; sa += pa;
                float pb = __expf(s_[j][e + 2] - mnb);
                s_[j][e + 2] = pb; sb += pb;
            }
        sa += __shfl_xor_sync(0xffffffffu, sa, 1);
        sa += __shfl_xor_sync(0xffffffffu, sa, 2);
        sb += __shfl_xor_sync(0xffffffffu, sb, 1);
        sb += __shfl_xor_sync(0xffffffffu, sb, 2);
        if ((lane & 3) == 0) {
            redsum[wn * 64 + row_a] = sa;
            redsum[wn * 64 + row_b] = sb;
        }
        __syncthreads();
        l_a = l_a * fa + redsum[row_a] + redsum[64 + row_a];
        l_b = l_b * fb + redsum[row_b] + redsum[64 + row_b];
        m_a = mna; m_b = mnb;

#pragma unroll
        for (int j = 0; j < 16; j++) {
            o[j][0] *= fa; o[j][1] *= fa;
            o[j][2] *= fb; o[j][3] *= fb;
        }

        uint32_t php0[4], php1[4], plp0[4], plp1[4];
#pragma unroll
        for (int j = 0; j < 4; j++) {
            __nv_bfloat162 h01 = __floats2bfloat162_rn(s_[j][0], s_[j][1]);
            __nv_bfloat162 h23 = __floats2bfloat162_rn(s_[j][2], s_[j][3]);
            php0[j] = *(uint32_t*)&h01;
            php1[j] = *(uint32_t*)&h23;
            plp0[j] = packbf2(s_[j][0] - __bfloat162float(__low2bfloat16(h01)),
                              s_[j][1] - __bfloat162float(__high2bfloat16(h01)));
            plp1[j] = packbf2(s_[j][2] - __bfloat162float(__low2bfloat16(h23)),
                              s_[j][3] - __bfloat162float(__high2bfloat16(h23)));
        }

#pragma unroll
        for (int seg = 0; seg < 3; seg++) {
            const bool useLo = (seg == 1);
            const uint32_t bbase = (seg == 2) ? (128u + wn * 64u) : (wn * 64u);
#pragma unroll
            for (int kk2 = 0; kk2 < 2; kk2++) {
                uint32_t a0 = useLo ? plp0[2 * kk2]     : php0[2 * kk2];
                uint32_t a1 = useLo ? plp1[2 * kk2]     : php1[2 * kk2];
                uint32_t a2 = useLo ? plp0[2 * kk2 + 1] : php0[2 * kk2 + 1];
                uint32_t a3 = useLo ? plp1[2 * kk2 + 1] : php1[2 * kk2 + 1];
                uint32_t vb[16][2];
#pragma unroll
                for (int p = 0; p < 8; p++) {
                    uint32_t r0, r1, r2, r3;
                    LDMX4(r0, r1, r2, r3, sV + v_rel + p * 16 * AVS + bbase + 32 * kk2);
                    vb[2 * p][0] = r0; vb[2 * p][1] = r1;
                    vb[2 * p + 1][0] = r2; vb[2 * p + 1][1] = r3;
                }
#pragma unroll
                for (int j = 0; j < 16; j++)
                    MMA16816BF(o[j], a0, a1, a2, a3, vb[j][0], vb[j][1]);
            }
        }
    }

    // epilogue: combine partials, write fp16 [hi|lo] ys directly
    __syncthreads();
    float* Ob = (float*)sm;
    if (wn == 1) {
#pragma unroll
        for (int j = 0; j < 16; j++) {
            int col = 8 * j + 2 * (lane & 3);
            *(float2*)&Ob[row_a * 132 + col] = make_float2(o[j][0], o[j][1]);
            *(float2*)&Ob[row_b * 132 + col] = make_float2(o[j][2], o[j][3]);
        }
    }
    __syncthreads();
    if (wn == 0) {
        float inva = 1.0f / l_a, invb = 1.0f / l_b;
        __half* base = ys + (size_t)(b * T_ + q0) * K2_ + h * 128;
#pragma unroll
        for (int j = 0; j < 16; j++) {
            int col = 8 * j + 2 * (lane & 3);
            float2 pa = *(float2*)&Ob[row_a * 132 + col];
            float2 pb = *(float2*)&Ob[row_b * 132 + col];
            float va0 = (o[j][0] + pa.x) * inva, va1 = (o[j][1] + pa.y) * inva;
            float vb0 = (o[j][2] + pb.x) * invb, vb1 = (o[j][3] + pb.y) * invb;
            __half h0, l0, h1, l1;
            split2h(va0, h0, l0); split2h(va1, h1, l1);
            __half* rp = base + (size_t)row_a * K2_ + col;
            *(__half2*)(rp)        = __halves2half2(h0, h1);
            *(__half2*)(rp + 2048) = __halves2half2(l0, l1);
            split2h(vb0, h0, l0); split2h(vb1, h1, l1);
            rp = base + (size_t)row_b * K2_ + col;
            *(__half2*)(rp)        = __halves2half2(h0, h1);
            *(__half2*)(rp + 2048) = __halves2half2(l0, l1);
        }
    }
}

// ---------------- launch ----------------
extern "C" void kernel_launch(void* const* d_in, const int* in_sizes, int n_in,
                              void* d_out, int out_size) {
    const float* x    = (const float*)d_in[0];
    const float* cosp = (const float*)d_in[1];
    const float* sinp = (const float*)d_in[2];
    const float* wq   = (const float*)d_in[3];
    const float* wk   = (const float*)d_in[4];
    const float* wv   = (const float*)d_in[5];
    const float* wo   = (const float*)d_in[6];
    float* out = (float*)d_out;

    __half *xs, *wb1, *wb2, *ys;
    __nv_bfloat16 *k2, *vt;
    float *qkv;
    cudaGetSymbolAddress((void**)&xs,  g_xs);
    cudaGetSymbolAddress((void**)&wb1, g_wb1);
    cudaGetSymbolAddress((void**)&wb2, g_wb2);
    cudaGetSymbolAddress((void**)&ys,  g_ys);
    cudaGetSymbolAddress((void**)&qkv, g_qkv);
    cudaGetSymbolAddress((void**)&k2,  g_k2);
    cudaGetSymbolAddress((void**)&vt,  g_vt);

    cudaFuncSetAttribute(attn_mma_kernel, cudaFuncAttributeMaxDynamicSharedMemorySize, ATT_SMEM);
    cudaFuncSetAttribute(gemm_f16, cudaFuncAttributeMaxDynamicSharedMemorySize, GSMEM);

    dim3 tb(32, 8);
    split_a_kernel<<<(M_ * 2048 / 4) / 256, 256>>>(x, xs);
    tsplit_b_kernel<<<dim3(2048 / 32, 2048 / 32), tb>>>(wq, wb1, 2048);
    tsplit_b_kernel<<<dim3(512  / 32, 2048 / 32), tb>>>(wk, wb1 + (size_t)2048 * K2_, 512);
    tsplit_b_kernel<<<dim3(512  / 32, 2048 / 32), tb>>>(wv, wb1 + (size_t)2560 * K2_, 512);
    tsplit_b_kernel<<<dim3(2048 / 32, 2048 / 32), tb>>>(wo, wb2, 2048);

    gemm_f16<<<dim3(3072 / 128, M_ / 128), 256, GSMEM>>>(xs, wb1, qkv, 3072);
    rope_rms_kernel<<<M_ * (H_ + KVH_), 32>>>(qkv, cosp, sinp, k2);
    split_v_kernel<<<dim3(4, 64, 8), tb>>>(qkv, vt);

    attn_mma_kernel<<<dim3(32, 32), 256, ATT_SMEM>>>(qkv, k2, vt, ys);
    gemm_f16<<<dim3(2048 / 128, M_ / 128), 256, GSMEM>>>(ys, wb2, out, 2048);
}

// round 10
// speedup vs baseline: 1.8332x; 1.1599x over previous
#include <cuda_runtime.h>
#include <cuda_bf16.h>
#include <cuda_fp16.h>
#include <math.h>
#include <float.h>
#include <stdint.h>

#define B_   2
#define T_   2048
#define C_   2048
#define H_   16
#define KVH_ 4
#define HD_  128
#define M_   (B_*T_)           // 4096
#define K2_  4096              // 2 * 2048 (fp16 [Ah|Al] x [Bh|Bh])
#define QKV_LD 3072

// ---------------- scratch ----------------
__device__ __half g_xs [(size_t)M_ * K2_];
__device__ __half g_wb1[(size_t)3072 * K2_];
__device__ __half g_wb2[(size_t)2048 * K2_];
__device__ __half g_ys [(size_t)M_ * K2_];
__device__ float g_qkv[(size_t)M_ * QKV_LD];
__device__ __half g_k2[(size_t)B_ * KVH_ * T_ * 128];    // [bkv][t][Kh 128]
__device__ __half g_vt[(size_t)B_ * KVH_ * HD_ * T_];    // [bkv][d][Vh t0..T]

// ---------------- helpers ----------------
__device__ __forceinline__ void split2h(float v, __half& h, __half& l) {
    h = __float2half_rn(v);
    l = __float2half_rn(v - __half2float(h));
}
__device__ __forceinline__ uint32_t smem_u32(const void* p) {
    uint32_t a;
    asm("{ .reg .u64 t; cvta.to.shared.u64 t, %1; cvt.u32.u64 %0, t; }" : "=r"(a) : "l"(p));
    return a;
}
__device__ __forceinline__ uint32_t packh2(float x, float y) {
    __half2 t = __floats2half2_rn(x, y);
    return *(uint32_t*)&t;
}
#define LDMX4(r0, r1, r2, r3, addr) \
    asm volatile("ldmatrix.sync.aligned.m8n8.x4.shared.b16 {%0,%1,%2,%3}, [%4];" \
        : "=r"(r0), "=r"(r1), "=r"(r2), "=r"(r3) : "r"(addr))
#define MMA16816F16(c, a0, a1, a2, a3, b0, b1) \
    asm volatile("mma.sync.aligned.m16n8k16.row.col.f32.f16.f16.f32 " \
        "{%0,%1,%2,%3}, {%4,%5,%6,%7}, {%8,%9}, {%0,%1,%2,%3};" \
        : "+f"((c)[0]), "+f"((c)[1]), "+f"((c)[2]), "+f"((c)[3]) \
        : "r"(a0), "r"(a1), "r"(a2), "r"(a3), "r"(b0), "r"(b1))
#define CP_ASYNC16(dst, src) \
    asm volatile("cp.async.cg.shared.global [%0], [%1], 16;" :: "r"(dst), "l"(src) : "memory")
#define CP_COMMIT() asm volatile("cp.async.commit_group;" ::: "memory")
#define CP_WAIT(n)  asm volatile("cp.async.wait_group %0;" :: "n"(n) : "memory")

// ---------------- split kernels (fp16 GEMM operands) ----------------
__global__ __launch_bounds__(256)
void split_a_kernel(const float* __restrict__ src, __half* __restrict__ dst) {
    int idx = blockIdx.x * 256 + threadIdx.x;
    int m = idx >> 9;
    int k = (idx & 511) << 2;
    float4 v = *(const float4*)(src + (size_t)m * 2048 + k);
    __half h0, h1, h2, h3, l0, l1, l2, l3;
    split2h(v.x, h0, l0); split2h(v.y, h1, l1);
    split2h(v.z, h2, l2); split2h(v.w, h3, l3);
    __half2* d0 = (__half2*)(dst + (size_t)m * K2_ + k);
    d0[0] = __halves2half2(h0, h1); d0[1] = __halves2half2(h2, h3);
    __half2* d1 = (__half2*)(dst + (size_t)m * K2_ + 2048 + k);
    d1[0] = __halves2half2(l0, l1); d1[1] = __halves2half2(l2, l3);
}

__global__ __launch_bounds__(256)
void tsplit_b_kernel(const float* __restrict__ src, __half* __restrict__ dst, int Ncols) {
    __shared__ float t[32][33];
    const int n0 = blockIdx.x * 32, k0 = blockIdx.y * 32;
    const int tx = threadIdx.x, ty = threadIdx.y;
#pragma unroll
    for (int i = 0; i < 4; i++)
        t[ty + i * 8][tx] = src[(size_t)(k0 + ty + i * 8) * Ncols + n0 + tx];
    __syncthreads();
#pragma unroll
    for (int i = 0; i < 4; i++) {
        __half h = __float2half_rn(t[tx][ty + i * 8]);
        __half* row = dst + (size_t)(n0 + ty + i * 8) * K2_ + k0 + tx;
        row[0]    = h;
        row[2048] = h;
    }
}

// ---------------- V transpose (fp16 hi only) ----------------
__global__ __launch_bounds__(256)
void split_v_kernel(const float* __restrict__ qkv, __half* __restrict__ vt) {
    __shared__ float tbuf[32][33];
    const int d0 = blockIdx.x * 32;
    const int t0 = blockIdx.y * 32;
    const int bkv = blockIdx.z;
    const int b = bkv >> 2, kv = bkv & 3;
    const int tx = threadIdx.x, ty = threadIdx.y;
#pragma unroll
    for (int i = 0; i < 4; i++)
        tbuf[ty + i * 8][tx] =
            qkv[(size_t)(b * T_ + t0 + ty + i * 8) * QKV_LD + 2560 + kv * 128 + d0 + tx];
    __syncthreads();
#pragma unroll
    for (int i = 0; i < 4; i++)
        vt[((size_t)bkv * 128 + d0 + ty + i * 8) * T_ + t0 + tx] =
            __float2half_rn(tbuf[tx][ty + i * 8]);
}

// ---------------- fp16 mma.sync GEMM, 4-stage cp.async ----------------
#define SMPAD 80
#define GSTAGE_B (2 * 128 * SMPAD)      // 20480 per stage (A + B)
#define GSMEM (4 * GSTAGE_B)            // 81920

__global__ __launch_bounds__(256, 2)
void gemm_f16(const __half* __restrict__ A, const __half* __restrict__ Bt,
              float* __restrict__ C, int N) {
    extern __shared__ uint8_t sm[];
    const uint32_t smb = smem_u32(sm);

    const int tid = threadIdx.x;
    const int lane = tid & 31, wid = tid >> 5;
    const int wm = wid >> 1, wn = wid & 1;
    const int m0 = blockIdx.y * 128, n0 = blockIdx.x * 128;

    const int crow = tid >> 1;
    const int cc2  = (tid & 1) * 2;
    const __half* agp = A  + (size_t)(m0 + crow) * K2_ + cc2 * 8;
    const __half* bgp = Bt + (size_t)(n0 + crow) * K2_ + cc2 * 8;
    const uint32_t sa_rel = (uint32_t)(crow * SMPAD + cc2 * 16);
    const uint32_t sb_rel = sa_rel + 128 * SMPAD;

    float acc[2][8][4];
#pragma unroll
    for (int i = 0; i < 2; i++)
#pragma unroll
        for (int j = 0; j < 8; j++)
#pragma unroll
            for (int r = 0; r < 4; r++) acc[i][j][r] = 0.0f;

    const int nK = K2_ / 32;   // 128

#pragma unroll
    for (int s = 0; s < 3; s++) {
        const uint32_t base = smb + s * GSTAGE_B;
        const int k0 = s * 32;
        CP_ASYNC16(base + sa_rel,      agp + k0);
        CP_ASYNC16(base + sa_rel + 16, agp + k0 + 8);
        CP_ASYNC16(base + sb_rel,      bgp + k0);
        CP_ASYNC16(base + sb_rel + 16, bgp + k0 + 8);
        CP_COMMIT();
    }

    const int lj = lane >> 3, lr = lane & 7;
    const uint32_t a_rel = (uint32_t)((wm * 32 + ((lj & 1) << 3) + lr) * SMPAD + ((lj >> 1) << 4));
    const uint32_t b_rel = (uint32_t)(128 * SMPAD + (wn * 64 + ((lj >> 1) << 3) + lr) * SMPAD + ((lj & 1) << 4));

    for (int it = 0; it < nK; it++) {
        CP_WAIT(2);
        __syncthreads();
        const int is = it + 3;
        if (is < nK) {
            const uint32_t base = smb + (is & 3) * GSTAGE_B;
            const int k0 = is * 32;
            CP_ASYNC16(base + sa_rel,      agp + k0);
            CP_ASYNC16(base + sa_rel + 16, agp + k0 + 8);
            CP_ASYNC16(base + sb_rel,      bgp + k0);
            CP_ASYNC16(base + sb_rel + 16, bgp + k0 + 8);
        }
        CP_COMMIT();

        const uint32_t stg = smb + (it & 3) * GSTAGE_B;
#pragma unroll
        for (int kk = 0; kk < 2; kk++) {
            uint32_t af[2][4];
#pragma unroll
            for (int i = 0; i < 2; i++)
                LDMX4(af[i][0], af[i][1], af[i][2], af[i][3],
                      stg + a_rel + i * 16 * SMPAD + kk * 32);
            uint32_t bf[8][2];
#pragma unroll
            for (int p = 0; p < 4; p++) {
                uint32_t r0, r1, r2, r3;
                LDMX4(r0, r1, r2, r3, stg + b_rel + p * 16 * SMPAD + kk * 32);
                bf[2 * p][0] = r0; bf[2 * p][1] = r1;
                bf[2 * p + 1][0] = r2; bf[2 * p + 1][1] = r3;
            }
#pragma unroll
            for (int i = 0; i < 2; i++)
#pragma unroll
                for (int j = 0; j < 8; j++)
                    MMA16816F16(acc[i][j], af[i][0], af[i][1], af[i][2], af[i][3],
                                bf[j][0], bf[j][1]);
        }
    }

    const int cr = lane >> 2, cc = (lane & 3) << 1;
#pragma unroll
    for (int i = 0; i < 2; i++) {
        const int mrow = m0 + wm * 32 + i * 16 + cr;
#pragma unroll
        for (int j = 0; j < 8; j++) {
            const int col = n0 + wn * 64 + j * 8 + cc;
            *(float2*)(C + (size_t)mrow * N + col)       = make_float2(acc[i][j][0], acc[i][j][1]);
            *(float2*)(C + (size_t)(mrow + 8) * N + col) = make_float2(acc[i][j][2], acc[i][j][3]);
        }
    }
}

// ---------------- RoPE + RMSNorm (+ fused K fp16 write) ----------------
__global__ __launch_bounds__(32)
void rope_rms_kernel(float* __restrict__ qkv,
                     const float* __restrict__ cosp, const float* __restrict__ sinp,
                     __half* __restrict__ k2) {
    const int n  = blockIdx.x;
    const int bt = n / (H_ + KVH_);
    const int hh = n - bt * (H_ + KVH_);
    float* p = qkv + (size_t)bt * QKV_LD +
               ((hh < H_) ? (size_t)hh * 128 : (size_t)(2048 + (hh - H_) * 128));
    const int t = bt & (T_ - 1);
    const int l = threadIdx.x;

    float o1[2], o2[2];
    float ss = 0.0f;
#pragma unroll
    for (int u = 0; u < 2; u++) {
        int d = l + u * 32;
        float x1 = p[d];
        float x2 = p[d + 64];
        float c = cosp[t * 64 + d];
        float s = sinp[t * 64 + d];
        o1[u] = x1 * c + x2 * s;
        o2[u] = x2 * c - x1 * s;
        ss += o1[u] * o1[u] + o2[u] * o2[u];
    }
#pragma unroll
    for (int off = 16; off > 0; off >>= 1)
        ss += __shfl_xor_sync(0xffffffffu, ss, off);
    float r = rsqrtf(ss * (1.0f / 128.0f) + 1e-5f);
#pragma unroll
    for (int u = 0; u < 2; u++) {
        int d = l + u * 32;
        p[d]      = o1[u] * r;
        p[d + 64] = o2[u] * r;
    }
    if (hh >= H_) {
        const int kvh = hh - H_;
        const int b = bt >> 11;
        __half* krow = k2 + ((size_t)(b * KVH_ + kvh) * T_ + t) * 128;
#pragma unroll
        for (int u = 0; u < 2; u++) {
            int d = l + u * 32;
            krow[d]      = __float2half_rn(o1[u] * r);
            krow[d + 64] = __float2half_rn(o2[u] * r);
        }
    }
}

// ---------------- tensor-core flash attention (fp16 2-term, hi-only K/V) ----------------
#define AQS 528          // Q row: [Qh 256B | Ql 256B] + pad
#define AKS 272          // K row: [Kh 256B] + pad
#define AVS2 144         // V row: [Vh 128B] + pad
#define SM_Q   0
#define SM_K0  33792                   // 64*528
#define SM_K1  (SM_K0 + 64 * AKS)      // 51200
#define SM_V0  (SM_K1 + 64 * AKS)      // 68608
#define SM_V1  (SM_V0 + 128 * AVS2)    // 87040
#define SM_RED (SM_V1 + 128 * AVS2)    // 105472
#define ATT_SMEM (SM_RED + 1024)       // 106496
#define ATT_SCALE 0.08838834764831845f

__global__ __launch_bounds__(256)
void attn_mma_kernel(const float* __restrict__ qkv,
                     const __half* __restrict__ k2,
                     const __half* __restrict__ vt,
                     __half* __restrict__ ys) {
    extern __shared__ uint8_t sm[];
    const uint32_t smb = smem_u32(sm);
    float* redmax = (float*)(sm + SM_RED);
    float* redsum = (float*)(sm + SM_RED + 512);

    const int tid = threadIdx.x;
    const int lane = tid & 31, wid = tid >> 5;
    const int wm = wid >> 1, wn = wid & 1;
    const int qtile = 31 - blockIdx.x;
    const int bh = blockIdx.y;
    const int b  = bh >> 4;
    const int h  = bh & 15;
    const int kv = h >> 2;
    const int q0 = qtile * 64;

    const int crow = tid >> 2;
    const int cc0  = (tid & 3) * 32;

    const __half* k2b = k2 + (size_t)(b * KVH_ + kv) * T_ * 128;
    const __half* vtb = vt + (size_t)(b * KVH_ + kv) * 128 * T_;

    // copy indices: K 64 rows x 16 chunks (4/thread), V 128 rows x 8 chunks (4/thread)
    const int krow = tid >> 2, kc = tid & 3;
    const int vrow = tid >> 1, vc = tid & 1;
    const uint32_t kdst_rel = (uint32_t)(krow * AKS);
    const uint32_t vdst_rel = (uint32_t)(vrow * AVS2);

    // prologue: issue tile 0 loads, convert Q while in flight
    {
        const __half* src = k2b + (size_t)krow * 128;
#pragma unroll
        for (int i = 0; i < 4; i++) {
            int c = kc + i * 4;
            CP_ASYNC16(smb + SM_K0 + kdst_rel + c * 16, src + c * 8);
        }
        const __half* srow = vtb + (size_t)vrow * T_;
#pragma unroll
        for (int i = 0; i < 4; i++) {
            int c = vc + i * 2;
            CP_ASYNC16(smb + SM_V0 + vdst_rel + c * 16, srow + c * 8);
        }
        CP_COMMIT();
    }

    // convert Q tile to fp16 hi|lo
    {
        const float* qp = qkv + (size_t)(b * T_ + q0 + crow) * QKV_LD + h * 128 + cc0;
        uint8_t* qrow = sm + SM_Q + crow * AQS;
#pragma unroll
        for (int i = 0; i < 8; i++) {
            float4 v = *(const float4*)(qp + i * 4);
            __half h0, h1, h2, h3, l0, l1, l2, l3;
            split2h(v.x, h0, l0); split2h(v.y, h1, l1);
            split2h(v.z, h2, l2); split2h(v.w, h3, l3);
            int c = cc0 + i * 4;
            *(__half2*)(qrow + 2 * c)           = __halves2half2(h0, h1);
            *(__half2*)(qrow + 2 * c + 4)       = __halves2half2(h2, h3);
            *(__half2*)(qrow + 256 + 2 * c)     = __halves2half2(l0, l1);
            *(__half2*)(qrow + 256 + 2 * c + 4) = __halves2half2(l2, l3);
        }
    }

    const int lj = lane >> 3, lr = lane & 7;
    const uint32_t a_off = smb + SM_Q + (uint32_t)((wm * 16 + ((lj & 1) << 3) + lr) * AQS + ((lj >> 1) << 4));
    const uint32_t b_rel = (uint32_t)((wn * 32 + ((lj >> 1) << 3) + lr) * AKS + ((lj & 1) << 4));
    const uint32_t v_rel = (uint32_t)((((lj >> 1) << 3) + lr) * AVS2 + ((lj & 1) << 4));

    const int ra = lane >> 2;
    const int row_a = wm * 16 + ra, row_b = row_a + 8;
    const int colb = wn * 32 + 2 * (lane & 3);
    float m_a = -FLT_MAX, m_b = -FLT_MAX, l_a = 0.0f, l_b = 0.0f;

    float o[16][4];
#pragma unroll
    for (int j = 0; j < 16; j++)
#pragma unroll
        for (int r = 0; r < 4; r++) o[j][r] = 0.0f;

    for (int jt = 0; jt <= qtile; jt++) {
        const int buf = jt & 1;
        const uint32_t sK = smb + (buf ? SM_K1 : SM_K0);
        const uint32_t sV = smb + (buf ? SM_V1 : SM_V0);

        CP_WAIT(0);
        __syncthreads();

        if (jt < qtile) {
            const int j1 = (jt + 1) * 64;
            const uint32_t dK = smb + (buf ? SM_K0 : SM_K1);
            const uint32_t dV = smb + (buf ? SM_V0 : SM_V1);
            const __half* src = k2b + (size_t)(j1 + krow) * 128;
#pragma unroll
            for (int i = 0; i < 4; i++) {
                int c = kc + i * 4;
                CP_ASYNC16(dK + kdst_rel + c * 16, src + c * 8);
            }
            const __half* srow = vtb + (size_t)vrow * T_ + j1;
#pragma unroll
            for (int i = 0; i < 4; i++) {
                int c = vc + i * 2;
                CP_ASYNC16(dV + vdst_rel + c * 16, srow + c * 8);
            }
        }
        CP_COMMIT();

        // ---- S = (Qh + Ql) Kh^T : 2 fp16 segments ----
        float s_[4][4];
#pragma unroll
        for (int j = 0; j < 4; j++)
#pragma unroll
            for (int r = 0; r < 4; r++) s_[j][r] = 0.0f;

#pragma unroll
        for (int seg = 0; seg < 2; seg++) {
            const uint32_t abase = seg ? 256u : 0u;
#pragma unroll
            for (int kk = 0; kk < 8; kk++) {
                uint32_t af[4];
                LDMX4(af[0], af[1], af[2], af[3], a_off + abase + 32 * kk);
                uint32_t bf[4][2];
#pragma unroll
                for (int p = 0; p < 2; p++) {
                    uint32_t r0, r1, r2, r3;
                    LDMX4(r0, r1, r2, r3, sK + b_rel + p * 16 * AKS + 32 * kk);
                    bf[2 * p][0] = r0; bf[2 * p][1] = r1;
                    bf[2 * p + 1][0] = r2; bf[2 * p + 1][1] = r3;
                }
#pragma unroll
                for (int j = 0; j < 4; j++)
                    MMA16816F16(s_[j], af[0], af[1], af[2], af[3], bf[j][0], bf[j][1]);
            }
        }

        // ---- online softmax ----
        const bool diag = (jt == qtile);
        float mxa = -FLT_MAX, mxb = -FLT_MAX;
#pragma unroll
        for (int j = 0; j < 4; j++)
#pragma unroll
            for (int e = 0; e < 2; e++) {
                int cg = colb + 8 * j + e;
                float va = s_[j][e] * ATT_SCALE;
                if (diag && cg > row_a) va = -FLT_MAX;
                s_[j][e] = va; mxa = fmaxf(mxa, va);
                float vb = s_[j][e + 2] * ATT_SCALE;
                if (diag && cg > row_b) vb = -FLT_MAX;
                s_[j][e + 2] = vb; mxb = fmaxf(mxb, vb);
            }
        mxa = fmaxf(mxa, __shfl_xor_sync(0xffffffffu, mxa, 1));
        mxa = fmaxf(mxa, __shfl_xor_sync(0xffffffffu, mxa, 2));
        mxb = fmaxf(mxb, __shfl_xor_sync(0xffffffffu, mxb, 1));
        mxb = fmaxf(mxb, __shfl_xor_sync(0xffffffffu, mxb, 2));
        if ((lane & 3) == 0) {
            redmax[wn * 64 + row_a] = mxa;
            redmax[wn * 64 + row_b] = mxb;
        }
        __syncthreads();
        float mna = fmaxf(m_a, fmaxf(redmax[row_a], redmax[64 + row_a]));
        float mnb = fmaxf(m_b, fmaxf(redmax[row_b], redmax[64 + row_b]));
        float fa = __expf(m_a - mna), fb = __expf(m_b - mnb);
        float sa = 0.0f, sb = 0.0f;
#pragma unroll
        for (int j = 0; j < 4; j++)
#pragma unroll
            for (int e = 0; e < 2; e++) {
                float pa = __expf(s_[j][e] - mna);
                s_[j][e] = pa; sa += pa;
                float pb = __expf(s_[j][e + 2] - mnb);
                s_[j][e + 2] = pb; sb += pb;
            }
        sa += __shfl_xor_sync(0xffffffffu, sa, 1);
        sa += __shfl_xor_sync(0xffffffffu, sa, 2);
        sb += __shfl_xor_sync(0xffffffffu, sb, 1);
        sb += __shfl_xor_sync(0xffffffffu, sb, 2);
        if ((lane & 3) == 0) {
            redsum[wn * 64 + row_a] = sa;
            redsum[wn * 64 + row_b] = sb;
        }
        __syncthreads();
        l_a = l_a * fa + redsum[row_a] + redsum[64 + row_a];
        l_b = l_b * fb + redsum[row_b] + redsum[64 + row_b];
        m_a = mna; m_b = mnb;

#pragma unroll
        for (int j = 0; j < 16; j++) {
            o[j][0] *= fa; o[j][1] *= fa;
            o[j][2] *= fb; o[j][3] *= fb;
        }

        // ---- P fragments (fp16 hi/lo) ----
        uint32_t php0[4], php1[4], plp0[4], plp1[4];
#pragma unroll
        for (int j = 0; j < 4; j++) {
            __half2 h01 = __floats2half2_rn(s_[j][0], s_[j][1]);
            __half2 h23 = __floats2half2_rn(s_[j][2], s_[j][3]);
            php0[j] = *(uint32_t*)&h01;
            php1[j] = *(uint32_t*)&h23;
            plp0[j] = packh2(s_[j][0] - __half2float(__low2half(h01)),
                             s_[j][1] - __half2float(__high2half(h01)));
            plp1[j] = packh2(s_[j][2] - __half2float(__low2half(h23)),
                             s_[j][3] - __half2float(__high2half(h23)));
        }

        // ---- O += (Ph + Pl) Vh : 2 fp16 segments ----
#pragma unroll
        for (int seg = 0; seg < 2; seg++) {
            const bool useLo = (seg == 1);
            const uint32_t bbase = wn * 64u;
#pragma unroll
            for (int kk2 = 0; kk2 < 2; kk2++) {
                uint32_t a0 = useLo ? plp0[2 * kk2]     : php0[2 * kk2];
                uint32_t a1 = useLo ? plp1[2 * kk2]     : php1[2 * kk2];
                uint32_t a2 = useLo ? plp0[2 * kk2 + 1] : php0[2 * kk2 + 1];
                uint32_t a3 = useLo ? plp1[2 * kk2 + 1] : php1[2 * kk2 + 1];
                uint32_t vb[16][2];
#pragma unroll
                for (int p = 0; p < 8; p++) {
                    uint32_t r0, r1, r2, r3;
                    LDMX4(r0, r1, r2, r3, sV + v_rel + p * 16 * AVS2 + bbase + 32 * kk2);
                    vb[2 * p][0] = r0; vb[2 * p][1] = r1;
                    vb[2 * p + 1][0] = r2; vb[2 * p + 1][1] = r3;
                }
#pragma unroll
                for (int j = 0; j < 16; j++)
                    MMA16816F16(o[j], a0, a1, a2, a3, vb[j][0], vb[j][1]);
            }
        }
    }

    // epilogue: combine partials, write fp16 [hi|lo] ys directly
    __syncthreads();
    float* Ob = (float*)sm;
    if (wn == 1) {
#pragma unroll
        for (int j = 0; j < 16; j++) {
            int col = 8 * j + 2 * (lane & 3);
            *(float2*)&Ob[row_a * 132 + col] = make_float2(o[j][0], o[j][1]);
            *(float2*)&Ob[row_b * 132 + col] = make_float2(o[j][2], o[j][3]);
        }
    }
    __syncthreads();
    if (wn == 0) {
        float inva = 1.0f / l_a, invb = 1.0f / l_b;
        __half* base = ys + (size_t)(b * T_ + q0) * K2_ + h * 128;
#pragma unroll
        for (int j = 0; j < 16; j++) {
            int col = 8 * j + 2 * (lane & 3);
            float2 pa = *(float2*)&Ob[row_a * 132 + col];
            float2 pb = *(float2*)&Ob[row_b * 132 + col];
            float va0 = (o[j][0] + pa.x) * inva, va1 = (o[j][1] + pa.y) * inva;
            float vb0 = (o[j][2] + pb.x) * invb, vb1 = (o[j][3] + pb.y) * invb;
            __half h0, l0, h1, l1;
            split2h(va0, h0, l0); split2h(va1, h1, l1);
            __half* rp = base + (size_t)row_a * K2_ + col;
            *(__half2*)(rp)        = __halves2half2(h0, h1);
            *(__half2*)(rp + 2048) = __halves2half2(l0, l1);
            split2h(vb0, h0, l0); split2h(vb1, h1, l1);
            rp = base + (size_t)row_b * K2_ + col;
            *(__half2*)(rp)        = __halves2half2(h0, h1);
            *(__half2*)(rp + 2048) = __halves2half2(l0, l1);
        }
    }
}

// ---------------- launch ----------------
extern "C" void kernel_launch(void* const* d_in, const int* in_sizes, int n_in,
                              void* d_out, int out_size) {
    const float* x    = (const float*)d_in[0];
    const float* cosp = (const float*)d_in[1];
    const float* sinp = (const float*)d_in[2];
    const float* wq   = (const float*)d_in[3];
    const float* wk   = (const float*)d_in[4];
    const float* wv   = (const float*)d_in[5];
    const float* wo   = (const float*)d_in[6];
    float* out = (float*)d_out;

    __half *xs, *wb1, *wb2, *ys, *k2, *vt;
    float *qkv;
    cudaGetSymbolAddress((void**)&xs,  g_xs);
    cudaGetSymbolAddress((void**)&wb1, g_wb1);
    cudaGetSymbolAddress((void**)&wb2, g_wb2);
    cudaGetSymbolAddress((void**)&ys,  g_ys);
    cudaGetSymbolAddress((void**)&qkv, g_qkv);
    cudaGetSymbolAddress((void**)&k2,  g_k2);
    cudaGetSymbolAddress((void**)&vt,  g_vt);

    cudaFuncSetAttribute(attn_mma_kernel, cudaFuncAttributeMaxDynamicSharedMemorySize, ATT_SMEM);
    cudaFuncSetAttribute(gemm_f16, cudaFuncAttributeMaxDynamicSharedMemorySize, GSMEM);

    dim3 tb(32, 8);
    split_a_kernel<<<(M_ * 2048 / 4) / 256, 256>>>(x, xs);
    tsplit_b_kernel<<<dim3(2048 / 32, 2048 / 32), tb>>>(wq, wb1, 2048);
    tsplit_b_kernel<<<dim3(512  / 32, 2048 / 32), tb>>>(wk, wb1 + (size_t)2048 * K2_, 512);
    tsplit_b_kernel<<<dim3(512  / 32, 2048 / 32), tb>>>(wv, wb1 + (size_t)2560 * K2_, 512);
    tsplit_b_kernel<<<dim3(2048 / 32, 2048 / 32), tb>>>(wo, wb2, 2048);

    gemm_f16<<<dim3(3072 / 128, M_ / 128), 256, GSMEM>>>(xs, wb1, qkv, 3072);
    rope_rms_kernel<<<M_ * (H_ + KVH_), 32>>>(qkv, cosp, sinp, k2);
    split_v_kernel<<<dim3(4, 64, 8), tb>>>(qkv, vt);

    attn_mma_kernel<<<dim3(32, 32), 256, ATT_SMEM>>>(qkv, k2, vt, ys);
    gemm_f16<<<dim3(2048 / 128, M_ / 128), 256, GSMEM>>>(ys, wb2, out, 2048);
}

// round 11
// speedup vs baseline: 1.9969x; 1.0893x over previous
#include <cuda_runtime.h>
#include <cuda_bf16.h>
#include <cuda_fp16.h>
#include <math.h>
#include <float.h>
#include <stdint.h>

#define B_   2
#define T_   2048
#define C_   2048
#define H_   16
#define KVH_ 4
#define HD_  128
#define M_   (B_*T_)           // 4096
#define K2_  4096              // A planes: [Ah 2048 | Al 2048]
#define KB_  2048              // B stored once (wrapped)
#define QKV_LD 3072

// ---------------- scratch ----------------
__device__ __half g_xs [(size_t)M_ * K2_];
__device__ __half g_wb1[(size_t)3072 * KB_];
__device__ __half g_wb2[(size_t)2048 * KB_];
__device__ __half g_ys [(size_t)M_ * K2_];
__device__ float g_qkv[(size_t)M_ * QKV_LD];
__device__ __half g_k2[(size_t)B_ * KVH_ * T_ * 128];    // [bkv][t][Kh 128]
__device__ __half g_vt[(size_t)B_ * KVH_ * HD_ * T_];    // [bkv][d][Vh t0..T]

// ---------------- helpers ----------------
__device__ __forceinline__ void split2h(float v, __half& h, __half& l) {
    h = __float2half_rn(v);
    l = __float2half_rn(v - __half2float(h));
}
__device__ __forceinline__ uint32_t smem_u32(const void* p) {
    uint32_t a;
    asm("{ .reg .u64 t; cvta.to.shared.u64 t, %1; cvt.u32.u64 %0, t; }" : "=r"(a) : "l"(p));
    return a;
}
__device__ __forceinline__ uint32_t packh2(float x, float y) {
    __half2 t = __floats2half2_rn(x, y);
    return *(uint32_t*)&t;
}
#define LDMX4(r0, r1, r2, r3, addr) \
    asm volatile("ldmatrix.sync.aligned.m8n8.x4.shared.b16 {%0,%1,%2,%3}, [%4];" \
        : "=r"(r0), "=r"(r1), "=r"(r2), "=r"(r3) : "r"(addr))
#define MMA16816F16(c, a0, a1, a2, a3, b0, b1) \
    asm volatile("mma.sync.aligned.m16n8k16.row.col.f32.f16.f16.f32 " \
        "{%0,%1,%2,%3}, {%4,%5,%6,%7}, {%8,%9}, {%0,%1,%2,%3};" \
        : "+f"((c)[0]), "+f"((c)[1]), "+f"((c)[2]), "+f"((c)[3]) \
        : "r"(a0), "r"(a1), "r"(a2), "r"(a3), "r"(b0), "r"(b1))
#define CP_ASYNC16(dst, src) \
    asm volatile("cp.async.cg.shared.global [%0], [%1], 16;" :: "r"(dst), "l"(src) : "memory")
#define CP_COMMIT() asm volatile("cp.async.commit_group;" ::: "memory")
#define CP_WAIT(n)  asm volatile("cp.async.wait_group %0;" :: "n"(n) : "memory")

// ---------------- split kernels ----------------
__global__ __launch_bounds__(256)
void split_a_kernel(const float* __restrict__ src, __half* __restrict__ dst) {
    int idx = blockIdx.x * 256 + threadIdx.x;
    int m = idx >> 9;
    int k = (idx & 511) << 2;
    float4 v = *(const float4*)(src + (size_t)m * 2048 + k);
    __half h0, h1, h2, h3, l0, l1, l2, l3;
    split2h(v.x, h0, l0); split2h(v.y, h1, l1);
    split2h(v.z, h2, l2); split2h(v.w, h3, l3);
    __half2* d0 = (__half2*)(dst + (size_t)m * K2_ + k);
    d0[0] = __halves2half2(h0, h1); d0[1] = __halves2half2(h2, h3);
    __half2* d1 = (__half2*)(dst + (size_t)m * K2_ + 2048 + k);
    d1[0] = __halves2half2(l0, l1); d1[1] = __halves2half2(l2, l3);
}

// W fp32 [2048][Ncols] -> Bt fp16 [n][2048] (single hi plane; GEMM wraps K)
__global__ __launch_bounds__(256)
void tsplit_b_kernel(const float* __restrict__ src, __half* __restrict__ dst, int Ncols) {
    __shared__ float t[32][33];
    const int n0 = blockIdx.x * 32, k0 = blockIdx.y * 32;
    const int tx = threadIdx.x, ty = threadIdx.y;
#pragma unroll
    for (int i = 0; i < 4; i++)
        t[ty + i * 8][tx] = src[(size_t)(k0 + ty + i * 8) * Ncols + n0 + tx];
    __syncthreads();
#pragma unroll
    for (int i = 0; i < 4; i++)
        dst[(size_t)(n0 + ty + i * 8) * KB_ + k0 + tx] =
            __float2half_rn(t[tx][ty + i * 8]);
}

// ---------------- V transpose (fp16 hi only) ----------------
__global__ __launch_bounds__(256)
void split_v_kernel(const float* __restrict__ qkv, __half* __restrict__ vt) {
    __shared__ float tbuf[32][33];
    const int d0 = blockIdx.x * 32;
    const int t0 = blockIdx.y * 32;
    const int bkv = blockIdx.z;
    const int b = bkv >> 2, kv = bkv & 3;
    const int tx = threadIdx.x, ty = threadIdx.y;
#pragma unroll
    for (int i = 0; i < 4; i++)
        tbuf[ty + i * 8][tx] =
            qkv[(size_t)(b * T_ + t0 + ty + i * 8) * QKV_LD + 2560 + kv * 128 + d0 + tx];
    __syncthreads();
#pragma unroll
    for (int i = 0; i < 4; i++)
        vt[((size_t)bkv * 128 + d0 + ty + i * 8) * T_ + t0 + tx] =
            __float2half_rn(tbuf[tx][ty + i * 8]);
}

// ---------------- fp16 mma.sync GEMM: 256x128 CTA tile, 512 thr, 4-stage cp.async ----------------
#define SMPAD 80
#define GASTG (256 * SMPAD)             // 20480 A bytes/stage
#define GBSTG (128 * SMPAD)             // 10240 B bytes/stage
#define GSTAGE_B (GASTG + GBSTG)        // 30720
#define GSMEM (4 * GSTAGE_B)            // 122880

__global__ __launch_bounds__(512, 1)
void gemm_f16(const __half* __restrict__ A, const __half* __restrict__ Bt,
              float* __restrict__ C, int N) {
    extern __shared__ uint8_t sm[];
    const uint32_t smb = smem_u32(sm);

    const int tid = threadIdx.x;
    const int lane = tid & 31, wid = tid >> 5;
    const int wm = wid >> 1, wn = wid & 1;          // 8m x 2n warps, 32x64 warp tile
    const int m0 = blockIdx.y * 256, n0 = blockIdx.x * 128;

    // copy: each thread 2 A chunks (rows r, r+128) + 1 B chunk (row r)
    const int crow = tid >> 2, c16 = tid & 3;
    const __half* agp0 = A + (size_t)(m0 + crow) * K2_ + c16 * 8;
    const __half* agp1 = agp0 + (size_t)128 * K2_;
    const __half* bgp  = Bt + (size_t)(n0 + crow) * KB_ + c16 * 8;   // crow < 128 used for B
    const uint32_t sa0_rel = (uint32_t)(crow * SMPAD + c16 * 16);
    const uint32_t sa1_rel = sa0_rel + 128 * SMPAD;
    const uint32_t sb_rel  = (uint32_t)(GASTG + crow * SMPAD + c16 * 16);
    const bool do_b = (crow < 128);

    float acc[2][8][4];
#pragma unroll
    for (int i = 0; i < 2; i++)
#pragma unroll
        for (int j = 0; j < 8; j++)
#pragma unroll
            for (int r = 0; r < 4; r++) acc[i][j][r] = 0.0f;

    const int nK = K2_ / 32;   // 128 stages

#pragma unroll
    for (int s = 0; s < 3; s++) {
        const uint32_t base = smb + s * GSTAGE_B;
        const int k0 = s * 32;
        CP_ASYNC16(base + sa0_rel, agp0 + k0);
        CP_ASYNC16(base + sa1_rel, agp1 + k0);
        if (do_b) CP_ASYNC16(base + sb_rel, bgp + (k0 & (KB_ - 1)));
        CP_COMMIT();
    }

    const int lj = lane >> 3, lr = lane & 7;
    const uint32_t a_rel = (uint32_t)((wm * 32 + ((lj & 1) << 3) + lr) * SMPAD + ((lj >> 1) << 4));
    const uint32_t b_rel = (uint32_t)(GASTG + (wn * 64 + ((lj >> 1) << 3) + lr) * SMPAD + ((lj & 1) << 4));

    for (int it = 0; it < nK; it++) {
        CP_WAIT(2);
        __syncthreads();
        const int is = it + 3;
        if (is < nK) {
            const uint32_t base = smb + (is & 3) * GSTAGE_B;
            const int k0 = is * 32;
            CP_ASYNC16(base + sa0_rel, agp0 + k0);
            CP_ASYNC16(base + sa1_rel, agp1 + k0);
            if (do_b) CP_ASYNC16(base + sb_rel, bgp + (k0 & (KB_ - 1)));
        }
        CP_COMMIT();

        const uint32_t stg = smb + (it & 3) * GSTAGE_B;
#pragma unroll
        for (int kk = 0; kk < 2; kk++) {
            uint32_t af[2][4];
#pragma unroll
            for (int i = 0; i < 2; i++)
                LDMX4(af[i][0], af[i][1], af[i][2], af[i][3],
                      stg + a_rel + i * 16 * SMPAD + kk * 32);
            uint32_t bf[8][2];
#pragma unroll
            for (int p = 0; p < 4; p++) {
                uint32_t r0, r1, r2, r3;
                LDMX4(r0, r1, r2, r3, stg + b_rel + p * 16 * SMPAD + kk * 32);
                bf[2 * p][0] = r0; bf[2 * p][1] = r1;
                bf[2 * p + 1][0] = r2; bf[2 * p + 1][1] = r3;
            }
#pragma unroll
            for (int i = 0; i < 2; i++)
#pragma unroll
                for (int j = 0; j < 8; j++)
                    MMA16816F16(acc[i][j], af[i][0], af[i][1], af[i][2], af[i][3],
                                bf[j][0], bf[j][1]);
        }
    }

    const int cr = lane >> 2, cc = (lane & 3) << 1;
#pragma unroll
    for (int i = 0; i < 2; i++) {
        const int mrow = m0 + wm * 32 + i * 16 + cr;
#pragma unroll
        for (int j = 0; j < 8; j++) {
            const int col = n0 + wn * 64 + j * 8 + cc;
            *(float2*)(C + (size_t)mrow * N + col)       = make_float2(acc[i][j][0], acc[i][j][1]);
            *(float2*)(C + (size_t)(mrow + 8) * N + col) = make_float2(acc[i][j][2], acc[i][j][3]);
        }
    }
}

// ---------------- RoPE + RMSNorm (+ fused K fp16 write) ----------------
__global__ __launch_bounds__(32)
void rope_rms_kernel(float* __restrict__ qkv,
                     const float* __restrict__ cosp, const float* __restrict__ sinp,
                     __half* __restrict__ k2) {
    const int n  = blockIdx.x;
    const int bt = n / (H_ + KVH_);
    const int hh = n - bt * (H_ + KVH_);
    float* p = qkv + (size_t)bt * QKV_LD +
               ((hh < H_) ? (size_t)hh * 128 : (size_t)(2048 + (hh - H_) * 128));
    const int t = bt & (T_ - 1);
    const int l = threadIdx.x;

    float o1[2], o2[2];
    float ss = 0.0f;
#pragma unroll
    for (int u = 0; u < 2; u++) {
        int d = l + u * 32;
        float x1 = p[d];
        float x2 = p[d + 64];
        float c = cosp[t * 64 + d];
        float s = sinp[t * 64 + d];
        o1[u] = x1 * c + x2 * s;
        o2[u] = x2 * c - x1 * s;
        ss += o1[u] * o1[u] + o2[u] * o2[u];
    }
#pragma unroll
    for (int off = 16; off > 0; off >>= 1)
        ss += __shfl_xor_sync(0xffffffffu, ss, off);
    float r = rsqrtf(ss * (1.0f / 128.0f) + 1e-5f);
#pragma unroll
    for (int u = 0; u < 2; u++) {
        int d = l + u * 32;
        p[d]      = o1[u] * r;
        p[d + 64] = o2[u] * r;
    }
    if (hh >= H_) {
        const int kvh = hh - H_;
        const int b = bt >> 11;
        __half* krow = k2 + ((size_t)(b * KVH_ + kvh) * T_ + t) * 128;
#pragma unroll
        for (int u = 0; u < 2; u++) {
            int d = l + u * 32;
            krow[d]      = __float2half_rn(o1[u] * r);
            krow[d + 64] = __float2half_rn(o2[u] * r);
        }
    }
}

// ---------------- tensor-core flash attention (fp16 2-term, hi-only K/V) ----------------
#define AQS 528
#define AKS 272
#define AVS2 144
#define SM_Q   0
#define SM_K0  33792
#define SM_K1  (SM_K0 + 64 * AKS)
#define SM_V0  (SM_K1 + 64 * AKS)
#define SM_V1  (SM_V0 + 128 * AVS2)
#define SM_RED (SM_V1 + 128 * AVS2)
#define ATT_SMEM (SM_RED + 1024)
#define ATT_SCALE 0.08838834764831845f

__global__ __launch_bounds__(256)
void attn_mma_kernel(const float* __restrict__ qkv,
                     const __half* __restrict__ k2,
                     const __half* __restrict__ vt,
                     __half* __restrict__ ys) {
    extern __shared__ uint8_t sm[];
    const uint32_t smb = smem_u32(sm);
    float* redmax = (float*)(sm + SM_RED);
    float* redsum = (float*)(sm + SM_RED + 512);

    const int tid = threadIdx.x;
    const int lane = tid & 31, wid = tid >> 5;
    const int wm = wid >> 1, wn = wid & 1;
    const int qtile = 31 - blockIdx.x;
    const int bh = blockIdx.y;
    const int b  = bh >> 4;
    const int h  = bh & 15;
    const int kv = h >> 2;
    const int q0 = qtile * 64;

    const int crow = tid >> 2;
    const int cc0  = (tid & 3) * 32;

    const __half* k2b = k2 + (size_t)(b * KVH_ + kv) * T_ * 128;
    const __half* vtb = vt + (size_t)(b * KVH_ + kv) * 128 * T_;

    const int krow = tid >> 2, kc = tid & 3;
    const int vrow = tid >> 1, vc = tid & 1;
    const uint32_t kdst_rel = (uint32_t)(krow * AKS);
    const uint32_t vdst_rel = (uint32_t)(vrow * AVS2);

    {
        const __half* src = k2b + (size_t)krow * 128;
#pragma unroll
        for (int i = 0; i < 4; i++) {
            int c = kc + i * 4;
            CP_ASYNC16(smb + SM_K0 + kdst_rel + c * 16, src + c * 8);
        }
        const __half* srow = vtb + (size_t)vrow * T_;
#pragma unroll
        for (int i = 0; i < 4; i++) {
            int c = vc + i * 2;
            CP_ASYNC16(smb + SM_V0 + vdst_rel + c * 16, srow + c * 8);
        }
        CP_COMMIT();
    }

    {
        const float* qp = qkv + (size_t)(b * T_ + q0 + crow) * QKV_LD + h * 128 + cc0;
        uint8_t* qrow = sm + SM_Q + crow * AQS;
#pragma unroll
        for (int i = 0; i < 8; i++) {
            float4 v = *(const float4*)(qp + i * 4);
            __half h0, h1, h2, h3, l0, l1, l2, l3;
            split2h(v.x, h0, l0); split2h(v.y, h1, l1);
            split2h(v.z, h2, l2); split2h(v.w, h3, l3);
            int c = cc0 + i * 4;
            *(__half2*)(qrow + 2 * c)           = __halves2half2(h0, h1);
            *(__half2*)(qrow + 2 * c + 4)       = __halves2half2(h2, h3);
            *(__half2*)(qrow + 256 + 2 * c)     = __halves2half2(l0, l1);
            *(__half2*)(qrow + 256 + 2 * c + 4) = __halves2half2(l2, l3);
        }
    }

    const int lj = lane >> 3, lr = lane & 7;
    const uint32_t a_off = smb + SM_Q + (uint32_t)((wm * 16 + ((lj & 1) << 3) + lr) * AQS + ((lj >> 1) << 4));
    const uint32_t b_rel = (uint32_t)((wn * 32 + ((lj >> 1) << 3) + lr) * AKS + ((lj & 1) << 4));
    const uint32_t v_rel = (uint32_t)((((lj >> 1) << 3) + lr) * AVS2 + ((lj & 1) << 4));

    const int ra = lane >> 2;
    const int row_a = wm * 16 + ra, row_b = row_a + 8;
    const int colb = wn * 32 + 2 * (lane & 3);
    float m_a = -FLT_MAX, m_b = -FLT_MAX, l_a = 0.0f, l_b = 0.0f;

    float o[16][4];
#pragma unroll
    for (int j = 0; j < 16; j++)
#pragma unroll
        for (int r = 0; r < 4; r++) o[j][r] = 0.0f;

    for (int jt = 0; jt <= qtile; jt++) {
        const int buf = jt & 1;
        const uint32_t sK = smb + (buf ? SM_K1 : SM_K0);
        const uint32_t sV = smb + (buf ? SM_V1 : SM_V0);

        CP_WAIT(0);
        __syncthreads();

        if (jt < qtile) {
            const int j1 = (jt + 1) * 64;
            const uint32_t dK = smb + (buf ? SM_K0 : SM_K1);
            const uint32_t dV = smb + (buf ? SM_V0 : SM_V1);
            const __half* src = k2b + (size_t)(j1 + krow) * 128;
#pragma unroll
            for (int i = 0; i < 4; i++) {
                int c = kc + i * 4;
                CP_ASYNC16(dK + kdst_rel + c * 16, src + c * 8);
            }
            const __half* srow = vtb + (size_t)vrow * T_ + j1;
#pragma unroll
            for (int i = 0; i < 4; i++) {
                int c = vc + i * 2;
                CP_ASYNC16(dV + vdst_rel + c * 16, srow + c * 8);
            }
        }
        CP_COMMIT();

        float s_[4][4];
#pragma unroll
        for (int j = 0; j < 4; j++)
#pragma unroll
            for (int r = 0; r < 4; r++) s_[j][r] = 0.0f;

#pragma unroll
        for (int seg = 0; seg < 2; seg++) {
            const uint32_t abase = seg ? 256u : 0u;
#pragma unroll
            for (int kk = 0; kk < 8; kk++) {
                uint32_t af[4];
                LDMX4(af[0], af[1], af[2], af[3], a_off + abase + 32 * kk);
                uint32_t bf[4][2];
#pragma unroll
                for (int p = 0; p < 2; p++) {
                    uint32_t r0, r1, r2, r3;
                    LDMX4(r0, r1, r2, r3, sK + b_rel + p * 16 * AKS + 32 * kk);
                    bf[2 * p][0] = r0; bf[2 * p][1] = r1;
                    bf[2 * p + 1][0] = r2; bf[2 * p + 1][1] = r3;
                }
#pragma unroll
                for (int j = 0; j < 4; j++)
                    MMA16816F16(s_[j], af[0], af[1], af[2], af[3], bf[j][0], bf[j][1]);
            }
        }

        const bool diag = (jt == qtile);
        float mxa = -FLT_MAX, mxb = -FLT_MAX;
#pragma unroll
        for (int j = 0; j < 4; j++)
#pragma unroll
            for (int e = 0; e < 2; e++) {
                int cg = colb + 8 * j + e;
                float va = s_[j][e] * ATT_SCALE;
                if (diag && cg > row_a) va = -FLT_MAX;
                s_[j][e] = va; mxa = fmaxf(mxa, va);
                float vb = s_[j][e + 2] * ATT_SCALE;
                if (diag && cg > row_b) vb = -FLT_MAX;
                s_[j][e + 2] = vb; mxb = fmaxf(mxb, vb);
            }
        mxa = fmaxf(mxa, __shfl_xor_sync(0xffffffffu, mxa, 1));
        mxa = fmaxf(mxa, __shfl_xor_sync(0xffffffffu, mxa, 2));
        mxb = fmaxf(mxb, __shfl_xor_sync(0xffffffffu, mxb, 1));
        mxb = fmaxf(mxb, __shfl_xor_sync(0xffffffffu, mxb, 2));
        if ((lane & 3) == 0) {
            redmax[wn * 64 + row_a] = mxa;
            redmax[wn * 64 + row_b] = mxb;
        }
        __syncthreads();
        float mna = fmaxf(m_a, fmaxf(redmax[row_a], redmax[64 + row_a]));
        float mnb = fmaxf(m_b, fmaxf(redmax[row_b], redmax[64 + row_b]));
        float fa = __expf(m_a - mna), fb = __expf(m_b - mnb);
        float sa = 0.0f, sb = 0.0f;
#pragma unroll
        for (int j = 0; j < 4; j++)
#pragma unroll
            for (int e = 0; e < 2; e++) {
                float pa = __expf(s_[j][e] - mna);
                s_[j][e] = pa; sa += pa;
                float pb = __expf(s_[j][e + 2] - mnb);
                s_[j][e + 2] = pb; sb += pb;
            }
        sa += __shfl_xor_sync(0xffffffffu, sa, 1);
        sa += __shfl_xor_sync(0xffffffffu, sa, 2);
        sb += __shfl_xor_sync(0xffffffffu, sb, 1);
        sb += __shfl_xor_sync(0xffffffffu, sb, 2);
        if ((lane & 3) == 0) {
            redsum[wn * 64 + row_a] = sa;
            redsum[wn * 64 + row_b] = sb;
        }
        __syncthreads();
        l_a = l_a * fa + redsum[row_a] + redsum[64 + row_a];
        l_b = l_b * fb + redsum[row_b] + redsum[64 + row_b];
        m_a = mna; m_b = mnb;

#pragma unroll
        for (int j = 0; j < 16; j++) {
            o[j][0] *= fa; o[j][1] *= fa;
            o[j][2] *= fb; o[j][3] *= fb;
        }

        uint32_t php0[4], php1[4], plp0[4], plp1[4];
#pragma unroll
        for (int j = 0; j < 4; j++) {
            __half2 h01 = __floats2half2_rn(s_[j][0], s_[j][1]);
            __half2 h23 = __floats2half2_rn(s_[j][2], s_[j][3]);
            php0[j] = *(uint32_t*)&h01;
            php1[j] = *(uint32_t*)&h23;
            plp0[j] = packh2(s_[j][0] - __half2float(__low2half(h01)),
                             s_[j][1] - __half2float(__high2half(h01)));
            plp1[j] = packh2(s_[j][2] - __half2float(__low2half(h23)),
                             s_[j][3] - __half2float(__high2half(h23)));
        }

#pragma unroll
        for (int seg = 0; seg < 2; seg++) {
            const bool useLo = (seg == 1);
            const uint32_t bbase = wn * 64u;
#pragma unroll
            for (int kk2 = 0; kk2 < 2; kk2++) {
                uint32_t a0 = useLo ? plp0[2 * kk2]     : php0[2 * kk2];
                uint32_t a1 = useLo ? plp1[2 * kk2]     : php1[2 * kk2];
                uint32_t a2 = useLo ? plp0[2 * kk2 + 1] : php0[2 * kk2 + 1];
                uint32_t a3 = useLo ? plp1[2 * kk2 + 1] : php1[2 * kk2 + 1];
                uint32_t vb[16][2];
#pragma unroll
                for (int p = 0; p < 8; p++) {
                    uint32_t r0, r1, r2, r3;
                    LDMX4(r0, r1, r2, r3, sV + v_rel + p * 16 * AVS2 + bbase + 32 * kk2);
                    vb[2 * p][0] = r0; vb[2 * p][1] = r1;
                    vb[2 * p + 1][0] = r2; vb[2 * p + 1][1] = r3;
                }
#pragma unroll
                for (int j = 0; j < 16; j++)
                    MMA16816F16(o[j], a0, a1, a2, a3, vb[j][0], vb[j][1]);
            }
        }
    }

    __syncthreads();
    float* Ob = (float*)sm;
    if (wn == 1) {
#pragma unroll
        for (int j = 0; j < 16; j++) {
            int col = 8 * j + 2 * (lane & 3);
            *(float2*)&Ob[row_a * 132 + col] = make_float2(o[j][0], o[j][1]);
            *(float2*)&Ob[row_b * 132 + col] = make_float2(o[j][2], o[j][3]);
        }
    }
    __syncthreads();
    if (wn == 0) {
        float inva = 1.0f / l_a, invb = 1.0f / l_b;
        __half* base = ys + (size_t)(b * T_ + q0) * K2_ + h * 128;
#pragma unroll
        for (int j = 0; j < 16; j++) {
            int col = 8 * j + 2 * (lane & 3);
            float2 pa = *(float2*)&Ob[row_a * 132 + col];
            float2 pb = *(float2*)&Ob[row_b * 132 + col];
            float va0 = (o[j][0] + pa.x) * inva, va1 = (o[j][1] + pa.y) * inva;
            float vb0 = (o[j][2] + pb.x) * invb, vb1 = (o[j][3] + pb.y) * invb;
            __half h0, l0, h1, l1;
            split2h(va0, h0, l0); split2h(va1, h1, l1);
            __half* rp = base + (size_t)row_a * K2_ + col;
            *(__half2*)(rp)        = __halves2half2(h0, h1);
            *(__half2*)(rp + 2048) = __halves2half2(l0, l1);
            split2h(vb0, h0, l0); split2h(vb1, h1, l1);
            rp = base + (size_t)row_b * K2_ + col;
            *(__half2*)(rp)        = __halves2half2(h0, h1);
            *(__half2*)(rp + 2048) = __halves2half2(l0, l1);
        }
    }
}

// ---------------- launch ----------------
extern "C" void kernel_launch(void* const* d_in, const int* in_sizes, int n_in,
                              void* d_out, int out_size) {
    const float* x    = (const float*)d_in[0];
    const float* cosp = (const float*)d_in[1];
    const float* sinp = (const float*)d_in[2];
    const float* wq   = (const float*)d_in[3];
    const float* wk   = (const float*)d_in[4];
    const float* wv   = (const float*)d_in[5];
    const float* wo   = (const float*)d_in[6];
    float* out = (float*)d_out;

    __half *xs, *wb1, *wb2, *ys, *k2, *vt;
    float *qkv;
    cudaGetSymbolAddress((void**)&xs,  g_xs);
    cudaGetSymbolAddress((void**)&wb1, g_wb1);
    cudaGetSymbolAddress((void**)&wb2, g_wb2);
    cudaGetSymbolAddress((void**)&ys,  g_ys);
    cudaGetSymbolAddress((void**)&qkv, g_qkv);
    cudaGetSymbolAddress((void**)&k2,  g_k2);
    cudaGetSymbolAddress((void**)&vt,  g_vt);

    cudaFuncSetAttribute(attn_mma_kernel, cudaFuncAttributeMaxDynamicSharedMemorySize, ATT_SMEM);
    cudaFuncSetAttribute(gemm_f16, cudaFuncAttributeMaxDynamicSharedMemorySize, GSMEM);

    dim3 tb(32, 8);
    split_a_kernel<<<(M_ * 2048 / 4) / 256, 256>>>(x, xs);
    tsplit_b_kernel<<<dim3(2048 / 32, 2048 / 32), tb>>>(wq, wb1, 2048);
    tsplit_b_kernel<<<dim3(512  / 32, 2048 / 32), tb>>>(wk, wb1 + (size_t)2048 * KB_, 512);
    tsplit_b_kernel<<<dim3(512  / 32, 2048 / 32), tb>>>(wv, wb1 + (size_t)2560 * KB_, 512);
    tsplit_b_kernel<<<dim3(2048 / 32, 2048 / 32), tb>>>(wo, wb2, 2048);

    gemm_f16<<<dim3(3072 / 128, M_ / 256), 512, GSMEM>>>(xs, wb1, qkv, 3072);
    rope_rms_kernel<<<M_ * (H_ + KVH_), 32>>>(qkv, cosp, sinp, k2);
    split_v_kernel<<<dim3(4, 64, 8), tb>>>(qkv, vt);

    attn_mma_kernel<<<dim3(32, 32), 256, ATT_SMEM>>>(qkv, k2, vt, ys);
    gemm_f16<<<dim3(2048 / 128, M_ / 256), 512, GSMEM>>>(ys, wb2, out, 2048);
}

// round 12
// speedup vs baseline: 2.2281x; 1.1158x over previous
#include <cuda_runtime.h>
#include <cuda_bf16.h>
#include <cuda_fp16.h>
#include <math.h>
#include <float.h>
#include <stdint.h>

#define B_   2
#define T_   2048
#define C_   2048
#define H_   16
#define KVH_ 4
#define HD_  128
#define M_   (B_*T_)           // 4096
#define K2_  4096              // A planes: [Ah 2048 | Al 2048]
#define KB_  2048              // B stored once (wrapped)
#define QKV_LD 3072

// ---------------- scratch ----------------
__device__ __half g_xs [(size_t)M_ * K2_];
__device__ __half g_wb1[(size_t)3072 * KB_];
__device__ __half g_wb2[(size_t)2048 * KB_];
__device__ __half g_ys [(size_t)M_ * K2_];
__device__ float g_qkv[(size_t)M_ * QKV_LD];
__device__ __half g_k2[(size_t)B_ * KVH_ * T_ * 128];    // [bkv][t][Kh 128]
__device__ __half g_vt[(size_t)B_ * KVH_ * HD_ * T_];    // [bkv][d][Vh t0..T]

// ---------------- helpers ----------------
__device__ __forceinline__ void split2h(float v, __half& h, __half& l) {
    h = __float2half_rn(v);
    l = __float2half_rn(v - __half2float(h));
}
__device__ __forceinline__ uint32_t smem_u32(const void* p) {
    uint32_t a;
    asm("{ .reg .u64 t; cvta.to.shared.u64 t, %1; cvt.u32.u64 %0, t; }" : "=r"(a) : "l"(p));
    return a;
}
#define LDMX4(r0, r1, r2, r3, addr) \
    asm volatile("ldmatrix.sync.aligned.m8n8.x4.shared.b16 {%0,%1,%2,%3}, [%4];" \
        : "=r"(r0), "=r"(r1), "=r"(r2), "=r"(r3) : "r"(addr))
#define MMA16816F16(c, a0, a1, a2, a3, b0, b1) \
    asm volatile("mma.sync.aligned.m16n8k16.row.col.f32.f16.f16.f32 " \
        "{%0,%1,%2,%3}, {%4,%5,%6,%7}, {%8,%9}, {%0,%1,%2,%3};" \
        : "+f"((c)[0]), "+f"((c)[1]), "+f"((c)[2]), "+f"((c)[3]) \
        : "r"(a0), "r"(a1), "r"(a2), "r"(a3), "r"(b0), "r"(b1))
#define CP_ASYNC16(dst, src) \
    asm volatile("cp.async.cg.shared.global [%0], [%1], 16;" :: "r"(dst), "l"(src) : "memory")
#define CP_COMMIT() asm volatile("cp.async.commit_group;" ::: "memory")
#define CP_WAIT(n)  asm volatile("cp.async.wait_group %0;" :: "n"(n) : "memory")

// ---------------- split kernels ----------------
__global__ __launch_bounds__(256)
void split_a_kernel(const float* __restrict__ src, __half* __restrict__ dst) {
    int idx = blockIdx.x * 256 + threadIdx.x;
    int m = idx >> 9;
    int k = (idx & 511) << 2;
    float4 v = *(const float4*)(src + (size_t)m * 2048 + k);
    __half h0, h1, h2, h3, l0, l1, l2, l3;
    split2h(v.x, h0, l0); split2h(v.y, h1, l1);
    split2h(v.z, h2, l2); split2h(v.w, h3, l3);
    __half2* d0 = (__half2*)(dst + (size_t)m * K2_ + k);
    d0[0] = __halves2half2(h0, h1); d0[1] = __halves2half2(h2, h3);
    __half2* d1 = (__half2*)(dst + (size_t)m * K2_ + 2048 + k);
    d1[0] = __halves2half2(l0, l1); d1[1] = __halves2half2(l2, l3);
}

__global__ __launch_bounds__(256)
void tsplit_b_kernel(const float* __restrict__ src, __half* __restrict__ dst, int Ncols) {
    __shared__ float t[32][33];
    const int n0 = blockIdx.x * 32, k0 = blockIdx.y * 32;
    const int tx = threadIdx.x, ty = threadIdx.y;
#pragma unroll
    for (int i = 0; i < 4; i++)
        t[ty + i * 8][tx] = src[(size_t)(k0 + ty + i * 8) * Ncols + n0 + tx];
    __syncthreads();
#pragma unroll
    for (int i = 0; i < 4; i++)
        dst[(size_t)(n0 + ty + i * 8) * KB_ + k0 + tx] =
            __float2half_rn(t[tx][ty + i * 8]);
}

// ---------------- V transpose (fp16 hi only) ----------------
__global__ __launch_bounds__(256)
void split_v_kernel(const float* __restrict__ qkv, __half* __restrict__ vt) {
    __shared__ float tbuf[32][33];
    const int d0 = blockIdx.x * 32;
    const int t0 = blockIdx.y * 32;
    const int bkv = blockIdx.z;
    const int b = bkv >> 2, kv = bkv & 3;
    const int tx = threadIdx.x, ty = threadIdx.y;
#pragma unroll
    for (int i = 0; i < 4; i++)
        tbuf[ty + i * 8][tx] =
            qkv[(size_t)(b * T_ + t0 + ty + i * 8) * QKV_LD + 2560 + kv * 128 + d0 + tx];
    __syncthreads();
#pragma unroll
    for (int i = 0; i < 4; i++)
        vt[((size_t)bkv * 128 + d0 + ty + i * 8) * T_ + t0 + tx] =
            __float2half_rn(tbuf[tx][ty + i * 8]);
}

// ---------------- fp16 mma.sync GEMM: 256x128 CTA tile, 512 thr, 4-stage cp.async ----------------
#define SMPAD 80
#define GASTG (256 * SMPAD)             // 20480 A bytes/stage
#define GBSTG (128 * SMPAD)             // 10240 B bytes/stage
#define GSTAGE_B (GASTG + GBSTG)        // 30720
#define GSMEM (4 * GSTAGE_B)            // 122880

__global__ __launch_bounds__(512, 1)
void gemm_f16(const __half* __restrict__ A, const __half* __restrict__ Bt,
              float* __restrict__ C, int N) {
    extern __shared__ uint8_t sm[];
    const uint32_t smb = smem_u32(sm);

    const int tid = threadIdx.x;
    const int lane = tid & 31, wid = tid >> 5;
    const int wm = wid >> 1, wn = wid & 1;
    const int m0 = blockIdx.y * 256, n0 = blockIdx.x * 128;

    const int crow = tid >> 2, c16 = tid & 3;
    const __half* agp0 = A + (size_t)(m0 + crow) * K2_ + c16 * 8;
    const __half* agp1 = agp0 + (size_t)128 * K2_;
    const __half* bgp  = Bt + (size_t)(n0 + crow) * KB_ + c16 * 8;
    const uint32_t sa0_rel = (uint32_t)(crow * SMPAD + c16 * 16);
    const uint32_t sa1_rel = sa0_rel + 128 * SMPAD;
    const uint32_t sb_rel  = (uint32_t)(GASTG + crow * SMPAD + c16 * 16);
    const bool do_b = (crow < 128);

    float acc[2][8][4];
#pragma unroll
    for (int i = 0; i < 2; i++)
#pragma unroll
        for (int j = 0; j < 8; j++)
#pragma unroll
            for (int r = 0; r < 4; r++) acc[i][j][r] = 0.0f;

    const int nK = K2_ / 32;   // 128 stages

#pragma unroll
    for (int s = 0; s < 3; s++) {
        const uint32_t base = smb + s * GSTAGE_B;
        const int k0 = s * 32;
        CP_ASYNC16(base + sa0_rel, agp0 + k0);
        CP_ASYNC16(base + sa1_rel, agp1 + k0);
        if (do_b) CP_ASYNC16(base + sb_rel, bgp + (k0 & (KB_ - 1)));
        CP_COMMIT();
    }

    const int lj = lane >> 3, lr = lane & 7;
    const uint32_t a_rel = (uint32_t)((wm * 32 + ((lj & 1) << 3) + lr) * SMPAD + ((lj >> 1) << 4));
    const uint32_t b_rel = (uint32_t)(GASTG + (wn * 64 + ((lj >> 1) << 3) + lr) * SMPAD + ((lj & 1) << 4));

    for (int it = 0; it < nK; it++) {
        CP_WAIT(2);
        __syncthreads();
        const int is = it + 3;
        if (is < nK) {
            const uint32_t base = smb + (is & 3) * GSTAGE_B;
            const int k0 = is * 32;
            CP_ASYNC16(base + sa0_rel, agp0 + k0);
            CP_ASYNC16(base + sa1_rel, agp1 + k0);
            if (do_b) CP_ASYNC16(base + sb_rel, bgp + (k0 & (KB_ - 1)));
        }
        CP_COMMIT();

        const uint32_t stg = smb + (it & 3) * GSTAGE_B;
#pragma unroll
        for (int kk = 0; kk < 2; kk++) {
            uint32_t af[2][4];
#pragma unroll
            for (int i = 0; i < 2; i++)
                LDMX4(af[i][0], af[i][1], af[i][2], af[i][3],
                      stg + a_rel + i * 16 * SMPAD + kk * 32);
            uint32_t bf[8][2];
#pragma unroll
            for (int p = 0; p < 4; p++) {
                uint32_t r0, r1, r2, r3;
                LDMX4(r0, r1, r2, r3, stg + b_rel + p * 16 * SMPAD + kk * 32);
                bf[2 * p][0] = r0; bf[2 * p][1] = r1;
                bf[2 * p + 1][0] = r2; bf[2 * p + 1][1] = r3;
            }
#pragma unroll
            for (int i = 0; i < 2; i++)
#pragma unroll
                for (int j = 0; j < 8; j++)
                    MMA16816F16(acc[i][j], af[i][0], af[i][1], af[i][2], af[i][3],
                                bf[j][0], bf[j][1]);
        }
    }

    const int cr = lane >> 2, cc = (lane & 3) << 1;
#pragma unroll
    for (int i = 0; i < 2; i++) {
        const int mrow = m0 + wm * 32 + i * 16 + cr;
#pragma unroll
        for (int j = 0; j < 8; j++) {
            const int col = n0 + wn * 64 + j * 8 + cc;
            *(float2*)(C + (size_t)mrow * N + col)       = make_float2(acc[i][j][0], acc[i][j][1]);
            *(float2*)(C + (size_t)(mrow + 8) * N + col) = make_float2(acc[i][j][2], acc[i][j][3]);
        }
    }
}

// ---------------- RoPE + RMSNorm (+ fused K fp16 write) ----------------
__global__ __launch_bounds__(32)
void rope_rms_kernel(float* __restrict__ qkv,
                     const float* __restrict__ cosp, const float* __restrict__ sinp,
                     __half* __restrict__ k2) {
    const int n  = blockIdx.x;
    const int bt = n / (H_ + KVH_);
    const int hh = n - bt * (H_ + KVH_);
    float* p = qkv + (size_t)bt * QKV_LD +
               ((hh < H_) ? (size_t)hh * 128 : (size_t)(2048 + (hh - H_) * 128));
    const int t = bt & (T_ - 1);
    const int l = threadIdx.x;

    float o1[2], o2[2];
    float ss = 0.0f;
#pragma unroll
    for (int u = 0; u < 2; u++) {
        int d = l + u * 32;
        float x1 = p[d];
        float x2 = p[d + 64];
        float c = cosp[t * 64 + d];
        float s = sinp[t * 64 + d];
        o1[u] = x1 * c + x2 * s;
        o2[u] = x2 * c - x1 * s;
        ss += o1[u] * o1[u] + o2[u] * o2[u];
    }
#pragma unroll
    for (int off = 16; off > 0; off >>= 1)
        ss += __shfl_xor_sync(0xffffffffu, ss, off);
    float r = rsqrtf(ss * (1.0f / 128.0f) + 1e-5f);
#pragma unroll
    for (int u = 0; u < 2; u++) {
        int d = l + u * 32;
        p[d]      = o1[u] * r;
        p[d + 64] = o2[u] * r;
    }
    if (hh >= H_) {
        const int kvh = hh - H_;
        const int b = bt >> 11;
        __half* krow = k2 + ((size_t)(b * KVH_ + kvh) * T_ + t) * 128;
#pragma unroll
        for (int u = 0; u < 2; u++) {
            int d = l + u * 32;
            krow[d]      = __float2half_rn(o1[u] * r);
            krow[d + 64] = __float2half_rn(o2[u] * r);
        }
    }
}

// ---------------- tensor-core flash attention (pure fp16, single-segment) ----------------
#define AKS 272          // Q/K row: 256B data + pad
#define AVS2 144         // V row: 128B data + pad
#define SM_Q   0
#define SM_K0  (64 * AKS)              // 17408
#define SM_K1  (SM_K0 + 64 * AKS)      // 34816
#define SM_V0  (SM_K1 + 64 * AKS)      // 52224
#define SM_V1  (SM_V0 + 128 * AVS2)    // 70656
#define SM_RED (SM_V1 + 128 * AVS2)    // 89088
#define ATT_SMEM (SM_RED + 1024)       // 90112
#define ATT_SCALE 0.08838834764831845f

__global__ __launch_bounds__(256, 2)
void attn_mma_kernel(const float* __restrict__ qkv,
                     const __half* __restrict__ k2,
                     const __half* __restrict__ vt,
                     __half* __restrict__ ys) {
    extern __shared__ uint8_t sm[];
    const uint32_t smb = smem_u32(sm);
    float* redmax = (float*)(sm + SM_RED);
    float* redsum = (float*)(sm + SM_RED + 512);

    const int tid = threadIdx.x;
    const int lane = tid & 31, wid = tid >> 5;
    const int wm = wid >> 1, wn = wid & 1;
    const int qtile = 31 - blockIdx.x;
    const int bh = blockIdx.y;
    const int b  = bh >> 4;
    const int h  = bh & 15;
    const int kv = h >> 2;
    const int q0 = qtile * 64;

    const int crow = tid >> 2;
    const int cc0  = (tid & 3) * 32;

    const __half* k2b = k2 + (size_t)(b * KVH_ + kv) * T_ * 128;
    const __half* vtb = vt + (size_t)(b * KVH_ + kv) * 128 * T_;

    const int krow = tid >> 2, kc = tid & 3;
    const int vrow = tid >> 1, vc = tid & 1;
    const uint32_t kdst_rel = (uint32_t)(krow * AKS);
    const uint32_t vdst_rel = (uint32_t)(vrow * AVS2);

    // prologue: issue K0/V0 loads, convert Q (single fp16 plane) while in flight
    {
        const __half* src = k2b + (size_t)krow * 128;
#pragma unroll
        for (int i = 0; i < 4; i++) {
            int c = kc + i * 4;
            CP_ASYNC16(smb + SM_K0 + kdst_rel + c * 16, src + c * 8);
        }
        const __half* srow = vtb + (size_t)vrow * T_;
#pragma unroll
        for (int i = 0; i < 4; i++) {
            int c = vc + i * 2;
            CP_ASYNC16(smb + SM_V0 + vdst_rel + c * 16, srow + c * 8);
        }
        CP_COMMIT();
    }

    {
        const float* qp = qkv + (size_t)(b * T_ + q0 + crow) * QKV_LD + h * 128 + cc0;
        uint8_t* qrow = sm + SM_Q + crow * AKS;
#pragma unroll
        for (int i = 0; i < 8; i++) {
            float4 v = *(const float4*)(qp + i * 4);
            int c = cc0 + i * 4;
            *(__half2*)(qrow + 2 * c)     = __floats2half2_rn(v.x, v.y);
            *(__half2*)(qrow + 2 * c + 4) = __floats2half2_rn(v.z, v.w);
        }
    }

    const int lj = lane >> 3, lr = lane & 7;
    const uint32_t a_off = smb + SM_Q + (uint32_t)((wm * 16 + ((lj & 1) << 3) + lr) * AKS + ((lj >> 1) << 4));
    const uint32_t b_rel = (uint32_t)((wn * 32 + ((lj >> 1) << 3) + lr) * AKS + ((lj & 1) << 4));
    const uint32_t v_rel = (uint32_t)((((lj >> 1) << 3) + lr) * AVS2 + ((lj & 1) << 4));

    const int ra = lane >> 2;
    const int row_a = wm * 16 + ra, row_b = row_a + 8;
    const int colb = wn * 32 + 2 * (lane & 3);
    float m_a = -FLT_MAX, m_b = -FLT_MAX, l_a = 0.0f, l_b = 0.0f;

    float o[16][4];
#pragma unroll
    for (int j = 0; j < 16; j++)
#pragma unroll
        for (int r = 0; r < 4; r++) o[j][r] = 0.0f;

    for (int jt = 0; jt <= qtile; jt++) {
        const int buf = jt & 1;
        const uint32_t sK = smb + (buf ? SM_K1 : SM_K0);
        const uint32_t sV = smb + (buf ? SM_V1 : SM_V0);

        CP_WAIT(0);
        __syncthreads();

        if (jt < qtile) {
            const int j1 = (jt + 1) * 64;
            const uint32_t dK = smb + (buf ? SM_K0 : SM_K1);
            const uint32_t dV = smb + (buf ? SM_V0 : SM_V1);
            const __half* src = k2b + (size_t)(j1 + krow) * 128;
#pragma unroll
            for (int i = 0; i < 4; i++) {
                int c = kc + i * 4;
                CP_ASYNC16(dK + kdst_rel + c * 16, src + c * 8);
            }
            const __half* srow = vtb + (size_t)vrow * T_ + j1;
#pragma unroll
            for (int i = 0; i < 4; i++) {
                int c = vc + i * 2;
                CP_ASYNC16(dV + vdst_rel + c * 16, srow + c * 8);
            }
        }
        CP_COMMIT();

        // ---- S = Qh Kh^T : single fp16 segment ----
        float s_[4][4];
#pragma unroll
        for (int j = 0; j < 4; j++)
#pragma unroll
            for (int r = 0; r < 4; r++) s_[j][r] = 0.0f;

#pragma unroll
        for (int kk = 0; kk < 8; kk++) {
            uint32_t af[4];
            LDMX4(af[0], af[1], af[2], af[3], a_off + 32 * kk);
            uint32_t bf[4][2];
#pragma unroll
            for (int p = 0; p < 2; p++) {
                uint32_t r0, r1, r2, r3;
                LDMX4(r0, r1, r2, r3, sK + b_rel + p * 16 * AKS + 32 * kk);
                bf[2 * p][0] = r0; bf[2 * p][1] = r1;
                bf[2 * p + 1][0] = r2; bf[2 * p + 1][1] = r3;
            }
#pragma unroll
            for (int j = 0; j < 4; j++)
                MMA16816F16(s_[j], af[0], af[1], af[2], af[3], bf[j][0], bf[j][1]);
        }

        // ---- online softmax ----
        const bool diag = (jt == qtile);
        float mxa = -FLT_MAX, mxb = -FLT_MAX;
#pragma unroll
        for (int j = 0; j < 4; j++)
#pragma unroll
            for (int e = 0; e < 2; e++) {
                int cg = colb + 8 * j + e;
                float va = s_[j][e] * ATT_SCALE;
                if (diag && cg > row_a) va = -FLT_MAX;
                s_[j][e] = va; mxa = fmaxf(mxa, va);
                float vb = s_[j][e + 2] * ATT_SCALE;
                if (diag && cg > row_b) vb = -FLT_MAX;
                s_[j][e + 2] = vb; mxb = fmaxf(mxb, vb);
            }
        mxa = fmaxf(mxa, __shfl_xor_sync(0xffffffffu, mxa, 1));
        mxa = fmaxf(mxa, __shfl_xor_sync(0xffffffffu, mxa, 2));
        mxb = fmaxf(mxb, __shfl_xor_sync(0xffffffffu, mxb, 1));
        mxb = fmaxf(mxb, __shfl_xor_sync(0xffffffffu, mxb, 2));
        if ((lane & 3) == 0) {
            redmax[wn * 64 + row_a] = mxa;
            redmax[wn * 64 + row_b] = mxb;
        }
        __syncthreads();
        float mna = fmaxf(m_a, fmaxf(redmax[row_a], redmax[64 + row_a]));
        float mnb = fmaxf(m_b, fmaxf(redmax[row_b], redmax[64 + row_b]));
        float fa = __expf(m_a - mna), fb = __expf(m_b - mnb);
        float sa = 0.0f, sb = 0.0f;
#pragma unroll
        for (int j = 0; j < 4; j++)
#pragma unroll
            for (int e = 0; e < 2; e++) {
                float pa = __expf(s_[j][e] - mna);
                s_[j][e] = pa; sa += pa;
                float pb = __expf(s_[j][e + 2] - mnb);
                s_[j][e + 2] = pb; sb += pb;
            }
        sa += __shfl_xor_sync(0xffffffffu, sa, 1);
        sa += __shfl_xor_sync(0xffffffffu, sa, 2);
        sb += __shfl_xor_sync(0xffffffffu, sb, 1);
        sb += __shfl_xor_sync(0xffffffffu, sb, 2);
        if ((lane & 3) == 0) {
            redsum[wn * 64 + row_a] = sa;
            redsum[wn * 64 + row_b] = sb;
        }
        __syncthreads();
        l_a = l_a * fa + redsum[row_a] + redsum[64 + row_a];
        l_b = l_b * fb + redsum[row_b] + redsum[64 + row_b];
        m_a = mna; m_b = mnb;

#pragma unroll
        for (int j = 0; j < 16; j++) {
            o[j][0] *= fa; o[j][1] *= fa;
            o[j][2] *= fb; o[j][3] *= fb;
        }

        // ---- P fragments (fp16 hi only) ----
        uint32_t php0[4], php1[4];
#pragma unroll
        for (int j = 0; j < 4; j++) {
            __half2 h01 = __floats2half2_rn(s_[j][0], s_[j][1]);
            __half2 h23 = __floats2half2_rn(s_[j][2], s_[j][3]);
            php0[j] = *(uint32_t*)&h01;
            php1[j] = *(uint32_t*)&h23;
        }

        // ---- O += Ph Vh : single fp16 segment ----
        {
            const uint32_t bbase = wn * 64u;
#pragma unroll
            for (int kk2 = 0; kk2 < 2; kk2++) {
                uint32_t a0 = php0[2 * kk2];
                uint32_t a1 = php1[2 * kk2];
                uint32_t a2 = php0[2 * kk2 + 1];
                uint32_t a3 = php1[2 * kk2 + 1];
                uint32_t vb[16][2];
#pragma unroll
                for (int p = 0; p < 8; p++) {
                    uint32_t r0, r1, r2, r3;
                    LDMX4(r0, r1, r2, r3, sV + v_rel + p * 16 * AVS2 + bbase + 32 * kk2);
                    vb[2 * p][0] = r0; vb[2 * p][1] = r1;
                    vb[2 * p + 1][0] = r2; vb[2 * p + 1][1] = r3;
                }
#pragma unroll
                for (int j = 0; j < 16; j++)
                    MMA16816F16(o[j], a0, a1, a2, a3, vb[j][0], vb[j][1]);
            }
        }
    }

    // epilogue: combine partials, write fp16 [hi|lo] ys directly
    __syncthreads();
    float* Ob = (float*)sm;
    if (wn == 1) {
#pragma unroll
        for (int j = 0; j < 16; j++) {
            int col = 8 * j + 2 * (lane & 3);
            *(float2*)&Ob[row_a * 132 + col] = make_float2(o[j][0], o[j][1]);
            *(float2*)&Ob[row_b * 132 + col] = make_float2(o[j][2], o[j][3]);
        }
    }
    __syncthreads();
    if (wn == 0) {
        float inva = 1.0f / l_a, invb = 1.0f / l_b;
        __half* base = ys + (size_t)(b * T_ + q0) * K2_ + h * 128;
#pragma unroll
        for (int j = 0; j < 16; j++) {
            int col = 8 * j + 2 * (lane & 3);
            float2 pa = *(float2*)&Ob[row_a * 132 + col];
            float2 pb = *(float2*)&Ob[row_b * 132 + col];
            float va0 = (o[j][0] + pa.x) * inva, va1 = (o[j][1] + pa.y) * inva;
            float vb0 = (o[j][2] + pb.x) * invb, vb1 = (o[j][3] + pb.y) * invb;
            __half h0, l0, h1, l1;
            split2h(va0, h0, l0); split2h(va1, h1, l1);
            __half* rp = base + (size_t)row_a * K2_ + col;
            *(__half2*)(rp)        = __halves2half2(h0, h1);
            *(__half2*)(rp + 2048) = __halves2half2(l0, l1);
            split2h(vb0, h0, l0); split2h(vb1, h1, l1);
            rp = base + (size_t)row_b * K2_ + col;
            *(__half2*)(rp)        = __halves2half2(h0, h1);
            *(__half2*)(rp + 2048) = __halves2half2(l0, l1);
        }
    }
}

// ---------------- launch ----------------
extern "C" void kernel_launch(void* const* d_in, const int* in_sizes, int n_in,
                              void* d_out, int out_size) {
    const float* x    = (const float*)d_in[0];
    const float* cosp = (const float*)d_in[1];
    const float* sinp = (const float*)d_in[2];
    const float* wq   = (const float*)d_in[3];
    const float* wk   = (const float*)d_in[4];
    const float* wv   = (const float*)d_in[5];
    const float* wo   = (const float*)d_in[6];
    float* out = (float*)d_out;

    __half *xs, *wb1, *wb2, *ys, *k2, *vt;
    float *qkv;
    cudaGetSymbolAddress((void**)&xs,  g_xs);
    cudaGetSymbolAddress((void**)&wb1, g_wb1);
    cudaGetSymbolAddress((void**)&wb2, g_wb2);
    cudaGetSymbolAddress((void**)&ys,  g_ys);
    cudaGetSymbolAddress((void**)&qkv, g_qkv);
    cudaGetSymbolAddress((void**)&k2,  g_k2);
    cudaGetSymbolAddress((void**)&vt,  g_vt);

    cudaFuncSetAttribute(attn_mma_kernel, cudaFuncAttributeMaxDynamicSharedMemorySize, ATT_SMEM);
    cudaFuncSetAttribute(gemm_f16, cudaFuncAttributeMaxDynamicSharedMemorySize, GSMEM);

    dim3 tb(32, 8);
    split_a_kernel<<<(M_ * 2048 / 4) / 256, 256>>>(x, xs);
    tsplit_b_kernel<<<dim3(2048 / 32, 2048 / 32), tb>>>(wq, wb1, 2048);
    tsplit_b_kernel<<<dim3(512  / 32, 2048 / 32), tb>>>(wk, wb1 + (size_t)2048 * KB_, 512);
    tsplit_b_kernel<<<dim3(512  / 32, 2048 / 32), tb>>>(wv, wb1 + (size_t)2560 * KB_, 512);
    tsplit_b_kernel<<<dim3(2048 / 32, 2048 / 32), tb>>>(wo, wb2, 2048);

    gemm_f16<<<dim3(3072 / 128, M_ / 256), 512, GSMEM>>>(xs, wb1, qkv, 3072);
    rope_rms_kernel<<<M_ * (H_ + KVH_), 32>>>(qkv, cosp, sinp, k2);
    split_v_kernel<<<dim3(4, 64, 8), tb>>>(qkv, vt);

    attn_mma_kernel<<<dim3(32, 32), 256, ATT_SMEM>>>(qkv, k2, vt, ys);
    gemm_f16<<<dim3(2048 / 128, M_ / 256), 512, GSMEM>>>(ys, wb2, out, 2048);
}

// round 13
// speedup vs baseline: 2.2369x; 1.0040x over previous
#include <cuda_runtime.h>
#include <cuda_bf16.h>
#include <cuda_fp16.h>
#include <math.h>
#include <float.h>
#include <stdint.h>

#define B_   2
#define T_   2048
#define C_   2048
#define H_   16
#define KVH_ 4
#define HD_  128
#define M_   (B_*T_)           // 4096
#define K2_  4096              // A planes: [Ah 2048 | Al 2048]
#define KB_  2048              // B stored once
#define QKV_LD 3072

// ---------------- scratch ----------------
__device__ __half g_xs [(size_t)M_ * K2_];
__device__ __half g_wb1[(size_t)3072 * KB_];
__device__ __half g_wb2[(size_t)2048 * KB_];
__device__ __half g_ys [(size_t)M_ * K2_];
__device__ float g_qkv[(size_t)M_ * QKV_LD];
__device__ __half g_q16[(size_t)M_ * 2048];              // roped+normed Q fp16
__device__ __half g_k2[(size_t)B_ * KVH_ * T_ * 128];    // [bkv][t][Kh 128]
__device__ __half g_vt[(size_t)B_ * KVH_ * HD_ * T_];    // [bkv][d][Vh t]

// ---------------- helpers ----------------
__device__ __forceinline__ void split2h(float v, __half& h, __half& l) {
    h = __float2half_rn(v);
    l = __float2half_rn(v - __half2float(h));
}
__device__ __forceinline__ uint32_t smem_u32(const void* p) {
    uint32_t a;
    asm("{ .reg .u64 t; cvta.to.shared.u64 t, %1; cvt.u32.u64 %0, t; }" : "=r"(a) : "l"(p));
    return a;
}
#define LDMX4(r0, r1, r2, r3, addr) \
    asm volatile("ldmatrix.sync.aligned.m8n8.x4.shared.b16 {%0,%1,%2,%3}, [%4];" \
        : "=r"(r0), "=r"(r1), "=r"(r2), "=r"(r3) : "r"(addr))
#define MMA16816F16(c, a0, a1, a2, a3, b0, b1) \
    asm volatile("mma.sync.aligned.m16n8k16.row.col.f32.f16.f16.f32 " \
        "{%0,%1,%2,%3}, {%4,%5,%6,%7}, {%8,%9}, {%0,%1,%2,%3};" \
        : "+f"((c)[0]), "+f"((c)[1]), "+f"((c)[2]), "+f"((c)[3]) \
        : "r"(a0), "r"(a1), "r"(a2), "r"(a3), "r"(b0), "r"(b1))
#define CP_ASYNC16(dst, src) \
    asm volatile("cp.async.cg.shared.global [%0], [%1], 16;" :: "r"(dst), "l"(src) : "memory")
#define CP_COMMIT() asm volatile("cp.async.commit_group;" ::: "memory")
#define CP_WAIT(n)  asm volatile("cp.async.wait_group %0;" :: "n"(n) : "memory")

// ---------------- split kernels ----------------
__global__ __launch_bounds__(256)
void split_a_kernel(const float* __restrict__ src, __half* __restrict__ dst) {
    int idx = blockIdx.x * 256 + threadIdx.x;
    int m = idx >> 9;
    int k = (idx & 511) << 2;
    float4 v = *(const float4*)(src + (size_t)m * 2048 + k);
    __half h0, h1, h2, h3, l0, l1, l2, l3;
    split2h(v.x, h0, l0); split2h(v.y, h1, l1);
    split2h(v.z, h2, l2); split2h(v.w, h3, l3);
    __half2* d0 = (__half2*)(dst + (size_t)m * K2_ + k);
    d0[0] = __halves2half2(h0, h1); d0[1] = __halves2half2(h2, h3);
    __half2* d1 = (__half2*)(dst + (size_t)m * K2_ + 2048 + k);
    d1[0] = __halves2half2(l0, l1); d1[1] = __halves2half2(l2, l3);
}

__global__ __launch_bounds__(256)
void tsplit_b_kernel(const float* __restrict__ src, __half* __restrict__ dst, int Ncols) {
    __shared__ float t[32][33];
    const int n0 = blockIdx.x * 32, k0 = blockIdx.y * 32;
    const int tx = threadIdx.x, ty = threadIdx.y;
#pragma unroll
    for (int i = 0; i < 4; i++)
        t[ty + i * 8][tx] = src[(size_t)(k0 + ty + i * 8) * Ncols + n0 + tx];
    __syncthreads();
#pragma unroll
    for (int i = 0; i < 4; i++)
        dst[(size_t)(n0 + ty + i * 8) * KB_ + k0 + tx] =
            __float2half_rn(t[tx][ty + i * 8]);
}

// ---------------- V transpose (fp16) ----------------
__global__ __launch_bounds__(256)
void split_v_kernel(const float* __restrict__ qkv, __half* __restrict__ vt) {
    __shared__ float tbuf[32][33];
    const int d0 = blockIdx.x * 32;
    const int t0 = blockIdx.y * 32;
    const int bkv = blockIdx.z;
    const int b = bkv >> 2, kv = bkv & 3;
    const int tx = threadIdx.x, ty = threadIdx.y;
#pragma unroll
    for (int i = 0; i < 4; i++)
        tbuf[ty + i * 8][tx] =
            qkv[(size_t)(b * T_ + t0 + ty + i * 8) * QKV_LD + 2560 + kv * 128 + d0 + tx];
    __syncthreads();
#pragma unroll
    for (int i = 0; i < 4; i++)
        vt[((size_t)bkv * 128 + d0 + ty + i * 8) * T_ + t0 + tx] =
            __float2half_rn(tbuf[tx][ty + i * 8]);
}

// ---------------- fp16 GEMM: dual-plane A, shared-B fragments ----------------
// K loop over 2048; stage holds Ahi[256][32], Alo[256][32], B[128][32].
#define SMPAD 80
#define GA_STG (256 * SMPAD)            // 20480 per A plane
#define GB_STG (128 * SMPAD)            // 10240
#define G2STG (2 * GA_STG + GB_STG)     // 51200
#define GSMEM3 (3 * G2STG)              // 153600

__global__ __launch_bounds__(512, 1)
void gemm_f16(const __half* __restrict__ A, const __half* __restrict__ Bt,
              float* __restrict__ C, int N) {
    extern __shared__ uint8_t sm[];
    const uint32_t smb = smem_u32(sm);

    const int tid = threadIdx.x;
    const int lane = tid & 31, wid = tid >> 5;
    const int wm = wid >> 1, wn = wid & 1;          // 8m x 2n warps, 32x64 tile
    const int m0 = blockIdx.y * 256, n0 = blockIdx.x * 128;

    const int crow = tid >> 2, c16 = tid & 3;        // crow 0..127
    const __half* ah0 = A + (size_t)(m0 + crow) * K2_ + c16 * 8;         // hi row crow
    const __half* ah1 = ah0 + (size_t)128 * K2_;                          // hi row crow+128
    const __half* bg  = Bt + (size_t)(n0 + crow) * KB_ + c16 * 8;
    const uint32_t sa0 = (uint32_t)(crow * SMPAD + c16 * 16);
    const uint32_t sa1 = sa0 + 128 * SMPAD;
    const uint32_t sb  = (uint32_t)(2 * GA_STG + crow * SMPAD + c16 * 16);

    float acc[2][8][4];
#pragma unroll
    for (int i = 0; i < 2; i++)
#pragma unroll
        for (int j = 0; j < 8; j++)
#pragma unroll
            for (int r = 0; r < 4; r++) acc[i][j][r] = 0.0f;

    const int nK = KB_ / 32;   // 64 stages

    // prologue: stages 0,1
#pragma unroll
    for (int s = 0; s < 2; s++) {
        const uint32_t base = smb + s * G2STG;
        const int k0 = s * 32;
        CP_ASYNC16(base + sa0, ah0 + k0);
        CP_ASYNC16(base + sa1, ah1 + k0);
        CP_ASYNC16(base + GA_STG + sa0, ah0 + 2048 + k0);
        CP_ASYNC16(base + GA_STG + sa1, ah1 + 2048 + k0);
        CP_ASYNC16(base + sb, bg + k0);
        CP_COMMIT();
    }

    const int lj = lane >> 3, lr = lane & 7;
    const uint32_t a_rel = (uint32_t)((wm * 32 + ((lj & 1) << 3) + lr) * SMPAD + ((lj >> 1) << 4));
    const uint32_t b_rel = (uint32_t)(2 * GA_STG + (wn * 64 + ((lj >> 1) << 3) + lr) * SMPAD + ((lj & 1) << 4));

    int cb = 0;   // current buffer (it % 3)
    int pb = 2;   // prefetch buffer ((it+2) % 3)
    for (int it = 0; it < nK; it++) {
        CP_WAIT(1);
        __syncthreads();
        const int is = it + 2;
        if (is < nK) {
            const uint32_t base = smb + pb * G2STG;
            const int k0 = is * 32;
            CP_ASYNC16(base + sa0, ah0 + k0);
            CP_ASYNC16(base + sa1, ah1 + k0);
            CP_ASYNC16(base + GA_STG + sa0, ah0 + 2048 + k0);
            CP_ASYNC16(base + GA_STG + sa1, ah1 + 2048 + k0);
            CP_ASYNC16(base + sb, bg + k0);
        }
        CP_COMMIT();

        const uint32_t stg = smb + cb * G2STG;
#pragma unroll
        for (int kk = 0; kk < 2; kk++) {
            // B fragments (shared by both A planes)
            uint32_t bf[8][2];
#pragma unroll
            for (int p = 0; p < 4; p++) {
                uint32_t r0, r1, r2, r3;
                LDMX4(r0, r1, r2, r3, stg + b_rel + p * 16 * SMPAD + kk * 32);
                bf[2 * p][0] = r0; bf[2 * p][1] = r1;
                bf[2 * p + 1][0] = r2; bf[2 * p + 1][1] = r3;
            }
            uint32_t af[2][4];
            // A-hi plane
#pragma unroll
            for (int i = 0; i < 2; i++)
                LDMX4(af[i][0], af[i][1], af[i][2], af[i][3],
                      stg + a_rel + i * 16 * SMPAD + kk * 32);
#pragma unroll
            for (int i = 0; i < 2; i++)
#pragma unroll
                for (int j = 0; j < 8; j++)
                    MMA16816F16(acc[i][j], af[i][0], af[i][1], af[i][2], af[i][3],
                                bf[j][0], bf[j][1]);
            // A-lo plane (reuses bf)
#pragma unroll
            for (int i = 0; i < 2; i++)
                LDMX4(af[i][0], af[i][1], af[i][2], af[i][3],
                      stg + GA_STG + a_rel + i * 16 * SMPAD + kk * 32);
#pragma unroll
            for (int i = 0; i < 2; i++)
#pragma unroll
                for (int j = 0; j < 8; j++)
                    MMA16816F16(acc[i][j], af[i][0], af[i][1], af[i][2], af[i][3],
                                bf[j][0], bf[j][1]);
        }
        cb = (cb == 2) ? 0 : cb + 1;
        pb = (pb == 2) ? 0 : pb + 1;
    }

    const int cr = lane >> 2, cc = (lane & 3) << 1;
#pragma unroll
    for (int i = 0; i < 2; i++) {
        const int mrow = m0 + wm * 32 + i * 16 + cr;
#pragma unroll
        for (int j = 0; j < 8; j++) {
            const int col = n0 + wn * 64 + j * 8 + cc;
            *(float2*)(C + (size_t)mrow * N + col)       = make_float2(acc[i][j][0], acc[i][j][1]);
            *(float2*)(C + (size_t)(mrow + 8) * N + col) = make_float2(acc[i][j][2], acc[i][j][3]);
        }
    }
}

// ---------------- RoPE + RMSNorm -> fp16 q16 / k2 (no fp32 writeback) ----------------
__global__ __launch_bounds__(32)
void rope_rms_kernel(const float* __restrict__ qkv,
                     const float* __restrict__ cosp, const float* __restrict__ sinp,
                     __half* __restrict__ q16, __half* __restrict__ k2) {
    const int n  = blockIdx.x;
    const int bt = n / (H_ + KVH_);
    const int hh = n - bt * (H_ + KVH_);
    const float* p = qkv + (size_t)bt * QKV_LD +
                     ((hh < H_) ? (size_t)hh * 128 : (size_t)(2048 + (hh - H_) * 128));
    const int t = bt & (T_ - 1);
    const int l = threadIdx.x;

    float o1[2], o2[2];
    float ss = 0.0f;
#pragma unroll
    for (int u = 0; u < 2; u++) {
        int d = l + u * 32;
        float x1 = p[d];
        float x2 = p[d + 64];
        float c = cosp[t * 64 + d];
        float s = sinp[t * 64 + d];
        o1[u] = x1 * c + x2 * s;
        o2[u] = x2 * c - x1 * s;
        ss += o1[u] * o1[u] + o2[u] * o2[u];
    }
#pragma unroll
    for (int off = 16; off > 0; off >>= 1)
        ss += __shfl_xor_sync(0xffffffffu, ss, off);
    float r = rsqrtf(ss * (1.0f / 128.0f) + 1e-5f);

    __half* dst = (hh < H_)
        ? (q16 + (size_t)bt * 2048 + (size_t)hh * 128)
        : (k2 + ((size_t)((bt >> 11) * KVH_ + (hh - H_)) * T_ + t) * 128);
#pragma unroll
    for (int u = 0; u < 2; u++) {
        int d = l + u * 32;
        dst[d]      = __float2half_rn(o1[u] * r);
        dst[d + 64] = __float2half_rn(o2[u] * r);
    }
}

// ---------------- tensor-core flash attention (pure fp16, Q via cp.async) ----------------
#define AKS 272          // Q/K row: 256B data + pad
#define AVS2 144         // V row: 128B data + pad
#define SM_Q   0
#define SM_K0  (64 * AKS)              // 17408
#define SM_K1  (SM_K0 + 64 * AKS)
#define SM_V0  (SM_K1 + 64 * AKS)
#define SM_V1  (SM_V0 + 128 * AVS2)
#define SM_RED (SM_V1 + 128 * AVS2)
#define ATT_SMEM (SM_RED + 1024)       // 90112
#define ATT_SCALE 0.08838834764831845f

__global__ __launch_bounds__(256, 2)
void attn_mma_kernel(const __half* __restrict__ q16,
                     const __half* __restrict__ k2,
                     const __half* __restrict__ vt,
                     __half* __restrict__ ys) {
    extern __shared__ uint8_t sm[];
    const uint32_t smb = smem_u32(sm);
    float* redmax = (float*)(sm + SM_RED);
    float* redsum = (float*)(sm + SM_RED + 512);

    const int tid = threadIdx.x;
    const int lane = tid & 31, wid = tid >> 5;
    const int wm = wid >> 1, wn = wid & 1;
    const int qtile = 31 - blockIdx.x;
    const int bh = blockIdx.y;
    const int b  = bh >> 4;
    const int h  = bh & 15;
    const int kv = h >> 2;
    const int q0 = qtile * 64;

    const __half* k2b = k2 + (size_t)(b * KVH_ + kv) * T_ * 128;
    const __half* vtb = vt + (size_t)(b * KVH_ + kv) * 128 * T_;
    const __half* q16b = q16 + (size_t)(b * T_ + q0) * 2048 + (size_t)h * 128;

    const int krow = tid >> 2, kc = tid & 3;
    const int vrow = tid >> 1, vc = tid & 1;
    const uint32_t kdst_rel = (uint32_t)(krow * AKS);
    const uint32_t vdst_rel = (uint32_t)(vrow * AVS2);

    // prologue: Q + K0 + V0 loads in one group
    {
#pragma unroll
        for (int i = 0; i < 4; i++) {
            int c = kc + i * 4;
            CP_ASYNC16(smb + SM_Q + kdst_rel + c * 16, q16b + (size_t)krow * 2048 + c * 8);
        }
        const __half* src = k2b + (size_t)krow * 128;
#pragma unroll
        for (int i = 0; i < 4; i++) {
            int c = kc + i * 4;
            CP_ASYNC16(smb + SM_K0 + kdst_rel + c * 16, src + c * 8);
        }
        const __half* srow = vtb + (size_t)vrow * T_;
#pragma unroll
        for (int i = 0; i < 4; i++) {
            int c = vc + i * 2;
            CP_ASYNC16(smb + SM_V0 + vdst_rel + c * 16, srow + c * 8);
        }
        CP_COMMIT();
    }

    const int lj = lane >> 3, lr = lane & 7;
    const uint32_t a_off = smb + SM_Q + (uint32_t)((wm * 16 + ((lj & 1) << 3) + lr) * AKS + ((lj >> 1) << 4));
    const uint32_t b_rel = (uint32_t)((wn * 32 + ((lj >> 1) << 3) + lr) * AKS + ((lj & 1) << 4));
    const uint32_t v_rel = (uint32_t)((((lj >> 1) << 3) + lr) * AVS2 + ((lj & 1) << 4));

    const int ra = lane >> 2;
    const int row_a = wm * 16 + ra, row_b = row_a + 8;
    const int colb = wn * 32 + 2 * (lane & 3);
    float m_a = -FLT_MAX, m_b = -FLT_MAX, l_a = 0.0f, l_b = 0.0f;

    float o[16][4];
#pragma unroll
    for (int j = 0; j < 16; j++)
#pragma unroll
        for (int r = 0; r < 4; r++) o[j][r] = 0.0f;

    for (int jt = 0; jt <= qtile; jt++) {
        const int buf = jt & 1;
        const uint32_t sK = smb + (buf ? SM_K1 : SM_K0);
        const uint32_t sV = smb + (buf ? SM_V1 : SM_V0);

        CP_WAIT(0);
        __syncthreads();

        if (jt < qtile) {
            const int j1 = (jt + 1) * 64;
            const uint32_t dK = smb + (buf ? SM_K0 : SM_K1);
            const uint32_t dV = smb + (buf ? SM_V0 : SM_V1);
            const __half* src = k2b + (size_t)(j1 + krow) * 128;
#pragma unroll
            for (int i = 0; i < 4; i++) {
                int c = kc + i * 4;
                CP_ASYNC16(dK + kdst_rel + c * 16, src + c * 8);
            }
            const __half* srow = vtb + (size_t)vrow * T_ + j1;
#pragma unroll
            for (int i = 0; i < 4; i++) {
                int c = vc + i * 2;
                CP_ASYNC16(dV + vdst_rel + c * 16, srow + c * 8);
            }
        }
        CP_COMMIT();

        // ---- S = Qh Kh^T ----
        float s_[4][4];
#pragma unroll
        for (int j = 0; j < 4; j++)
#pragma unroll
            for (int r = 0; r < 4; r++) s_[j][r] = 0.0f;

#pragma unroll
        for (int kk = 0; kk < 8; kk++) {
            uint32_t af[4];
            LDMX4(af[0], af[1], af[2], af[3], a_off + 32 * kk);
            uint32_t bf[4][2];
#pragma unroll
            for (int p = 0; p < 2; p++) {
                uint32_t r0, r1, r2, r3;
                LDMX4(r0, r1, r2, r3, sK + b_rel + p * 16 * AKS + 32 * kk);
                bf[2 * p][0] = r0; bf[2 * p][1] = r1;
                bf[2 * p + 1][0] = r2; bf[2 * p + 1][1] = r3;
            }
#pragma unroll
            for (int j = 0; j < 4; j++)
                MMA16816F16(s_[j], af[0], af[1], af[2], af[3], bf[j][0], bf[j][1]);
        }

        // ---- online softmax ----
        const bool diag = (jt == qtile);
        float mxa = -FLT_MAX, mxb = -FLT_MAX;
#pragma unroll
        for (int j = 0; j < 4; j++)
#pragma unroll
            for (int e = 0; e < 2; e++) {
                int cg = colb + 8 * j + e;
                float va = s_[j][e] * ATT_SCALE;
                if (diag && cg > row_a) va = -FLT_MAX;
                s_[j][e] = va; mxa = fmaxf(mxa, va);
                float vb = s_[j][e + 2] * ATT_SCALE;
                if (diag && cg > row_b) vb = -FLT_MAX;
                s_[j][e + 2] = vb; mxb = fmaxf(mxb, vb);
            }
        mxa = fmaxf(mxa, __shfl_xor_sync(0xffffffffu, mxa, 1));
        mxa = fmaxf(mxa, __shfl_xor_sync(0xffffffffu, mxa, 2));
        mxb = fmaxf(mxb, __shfl_xor_sync(0xffffffffu, mxb, 1));
        mxb = fmaxf(mxb, __shfl_xor_sync(0xffffffffu, mxb, 2));
        if ((lane & 3) == 0) {
            redmax[wn * 64 + row_a] = mxa;
            redmax[wn * 64 + row_b] = mxb;
        }
        __syncthreads();
        float mna = fmaxf(m_a, fmaxf(redmax[row_a], redmax[64 + row_a]));
        float mnb = fmaxf(m_b, fmaxf(redmax[row_b], redmax[64 + row_b]));
        float fa = __expf(m_a - mna), fb = __expf(m_b - mnb);
        float sa = 0.0f, sb = 0.0f;
#pragma unroll
        for (int j = 0; j < 4; j++)
#pragma unroll
            for (int e = 0; e < 2; e++) {
                float pa = __expf(s_[j][e] - mna);
                s_[j][e] = pa; sa += pa;
                float pb = __expf(s_[j][e + 2] - mnb);
                s_[j][e + 2] = pb; sb += pb;
            }
        sa += __shfl_xor_sync(0xffffffffu, sa, 1);
        sa += __shfl_xor_sync(0xffffffffu, sa, 2);
        sb += __shfl_xor_sync(0xffffffffu, sb, 1);
        sb += __shfl_xor_sync(0xffffffffu, sb, 2);
        if ((lane & 3) == 0) {
            redsum[wn * 64 + row_a] = sa;
            redsum[wn * 64 + row_b] = sb;
        }
        __syncthreads();
        l_a = l_a * fa + redsum[row_a] + redsum[64 + row_a];
        l_b = l_b * fb + redsum[row_b] + redsum[64 + row_b];
        m_a = mna; m_b = mnb;

#pragma unroll
        for (int j = 0; j < 16; j++) {
            o[j][0] *= fa; o[j][1] *= fa;
            o[j][2] *= fb; o[j][3] *= fb;
        }

        // ---- P fragments (fp16) ----
        uint32_t php0[4], php1[4];
#pragma unroll
        for (int j = 0; j < 4; j++) {
            __half2 h01 = __floats2half2_rn(s_[j][0], s_[j][1]);
            __half2 h23 = __floats2half2_rn(s_[j][2], s_[j][3]);
            php0[j] = *(uint32_t*)&h01;
            php1[j] = *(uint32_t*)&h23;
        }

        // ---- O += Ph Vh ----
        {
            const uint32_t bbase = wn * 64u;
#pragma unroll
            for (int kk2 = 0; kk2 < 2; kk2++) {
                uint32_t a0 = php0[2 * kk2];
                uint32_t a1 = php1[2 * kk2];
                uint32_t a2 = php0[2 * kk2 + 1];
                uint32_t a3 = php1[2 * kk2 + 1];
                uint32_t vb[16][2];
#pragma unroll
                for (int p = 0; p < 8; p++) {
                    uint32_t r0, r1, r2, r3;
                    LDMX4(r0, r1, r2, r3, sV + v_rel + p * 16 * AVS2 + bbase + 32 * kk2);
                    vb[2 * p][0] = r0; vb[2 * p][1] = r1;
                    vb[2 * p + 1][0] = r2; vb[2 * p + 1][1] = r3;
                }
#pragma unroll
                for (int j = 0; j < 16; j++)
                    MMA16816F16(o[j], a0, a1, a2, a3, vb[j][0], vb[j][1]);
            }
        }
    }

    // epilogue
    __syncthreads();
    float* Ob = (float*)sm;
    if (wn == 1) {
#pragma unroll
        for (int j = 0; j < 16; j++) {
            int col = 8 * j + 2 * (lane & 3);
            *(float2*)&Ob[row_a * 132 + col] = make_float2(o[j][0], o[j][1]);
            *(float2*)&Ob[row_b * 132 + col] = make_float2(o[j][2], o[j][3]);
        }
    }
    __syncthreads();
    if (wn == 0) {
        float inva = 1.0f / l_a, invb = 1.0f / l_b;
        __half* base = ys + (size_t)(b * T_ + q0) * K2_ + h * 128;
#pragma unroll
        for (int j = 0; j < 16; j++) {
            int col = 8 * j + 2 * (lane & 3);
            float2 pa = *(float2*)&Ob[row_a * 132 + col];
            float2 pb = *(float2*)&Ob[row_b * 132 + col];
            float va0 = (o[j][0] + pa.x) * inva, va1 = (o[j][1] + pa.y) * inva;
            float vb0 = (o[j][2] + pb.x) * invb, vb1 = (o[j][3] + pb.y) * invb;
            __half h0, l0, h1, l1;
            split2h(va0, h0, l0); split2h(va1, h1, l1);
            __half* rp = base + (size_t)row_a * K2_ + col;
            *(__half2*)(rp)        = __halves2half2(h0, h1);
            *(__half2*)(rp + 2048) = __halves2half2(l0, l1);
            split2h(vb0, h0, l0); split2h(vb1, h1, l1);
            rp = base + (size_t)row_b * K2_ + col;
            *(__half2*)(rp)        = __halves2half2(h0, h1);
            *(__half2*)(rp + 2048) = __halves2half2(l0, l1);
        }
    }
}

// ---------------- launch ----------------
extern "C" void kernel_launch(void* const* d_in, const int* in_sizes, int n_in,
                              void* d_out, int out_size) {
    const float* x    = (const float*)d_in[0];
    const float* cosp = (const float*)d_in[1];
    const float* sinp = (const float*)d_in[2];
    const float* wq   = (const float*)d_in[3];
    const float* wk   = (const float*)d_in[4];
    const float* wv   = (const float*)d_in[5];
    const float* wo   = (const float*)d_in[6];
    float* out = (float*)d_out;

    __half *xs, *wb1, *wb2, *ys, *q16, *k2, *vt;
    float *qkv;
    cudaGetSymbolAddress((void**)&xs,  g_xs);
    cudaGetSymbolAddress((void**)&wb1, g_wb1);
    cudaGetSymbolAddress((void**)&wb2, g_wb2);
    cudaGetSymbolAddress((void**)&ys,  g_ys);
    cudaGetSymbolAddress((void**)&qkv, g_qkv);
    cudaGetSymbolAddress((void**)&q16, g_q16);
    cudaGetSymbolAddress((void**)&k2,  g_k2);
    cudaGetSymbolAddress((void**)&vt,  g_vt);

    cudaFuncSetAttribute(attn_mma_kernel, cudaFuncAttributeMaxDynamicSharedMemorySize, ATT_SMEM);
    cudaFuncSetAttribute(gemm_f16, cudaFuncAttributeMaxDynamicSharedMemorySize, GSMEM3);

    dim3 tb(32, 8);
    split_a_kernel<<<(M_ * 2048 / 4) / 256, 256>>>(x, xs);
    tsplit_b_kernel<<<dim3(2048 / 32, 2048 / 32), tb>>>(wq, wb1, 2048);
    tsplit_b_kernel<<<dim3(512  / 32, 2048 / 32), tb>>>(wk, wb1 + (size_t)2048 * KB_, 512);
    tsplit_b_kernel<<<dim3(512  / 32, 2048 / 32), tb>>>(wv, wb1 + (size_t)2560 * KB_, 512);
    tsplit_b_kernel<<<dim3(2048 / 32, 2048 / 32), tb>>>(wo, wb2, 2048);

    gemm_f16<<<dim3(3072 / 128, M_ / 256), 512, GSMEM3>>>(xs, wb1, qkv, 3072);
    rope_rms_kernel<<<M_ * (H_ + KVH_), 32>>>(qkv, cosp, sinp, q16, k2);
    split_v_kernel<<<dim3(4, 64, 8), tb>>>(qkv, vt);

    attn_mma_kernel<<<dim3(32, 32), 256, ATT_SMEM>>>(q16, k2, vt, ys);
    gemm_f16<<<dim3(2048 / 128, M_ / 256), 512, GSMEM3>>>(ys, wb2, out, 2048);
}

// round 14
// speedup vs baseline: 3.2599x; 1.4573x over previous
#include <cuda_runtime.h>
#include <cuda_bf16.h>
#include <cuda_fp16.h>
#include <math.h>
#include <float.h>
#include <stdint.h>

#define B_   2
#define T_   2048
#define C_   2048
#define H_   16
#define KVH_ 4
#define HD_  128
#define M_   (B_*T_)           // 4096
#define KG_  2048              // GEMM K (plain fp16, no planes)
#define QKV_LD 3072

// ---------------- scratch ----------------
__device__ __half g_xs [(size_t)M_ * KG_];
__device__ __half g_wb1[(size_t)3072 * KG_];
__device__ __half g_wb2[(size_t)2048 * KG_];
__device__ __half g_ys [(size_t)M_ * KG_];
__device__ float g_qkv[(size_t)M_ * QKV_LD];
__device__ __half g_q16[(size_t)M_ * 2048];              // roped+normed Q fp16
__device__ __half g_k2[(size_t)B_ * KVH_ * T_ * 128];    // [bkv][t][Kh 128]
__device__ __half g_vt[(size_t)B_ * KVH_ * HD_ * T_];    // [bkv][d][Vh t]

// ---------------- helpers ----------------
__device__ __forceinline__ uint32_t smem_u32(const void* p) {
    uint32_t a;
    asm("{ .reg .u64 t; cvta.to.shared.u64 t, %1; cvt.u32.u64 %0, t; }" : "=r"(a) : "l"(p));
    return a;
}
#define LDMX4(r0, r1, r2, r3, addr) \
    asm volatile("ldmatrix.sync.aligned.m8n8.x4.shared.b16 {%0,%1,%2,%3}, [%4];" \
        : "=r"(r0), "=r"(r1), "=r"(r2), "=r"(r3) : "r"(addr))
#define MMA16816F16(c, a0, a1, a2, a3, b0, b1) \
    asm volatile("mma.sync.aligned.m16n8k16.row.col.f32.f16.f16.f32 " \
        "{%0,%1,%2,%3}, {%4,%5,%6,%7}, {%8,%9}, {%0,%1,%2,%3};" \
        : "+f"((c)[0]), "+f"((c)[1]), "+f"((c)[2]), "+f"((c)[3]) \
        : "r"(a0), "r"(a1), "r"(a2), "r"(a3), "r"(b0), "r"(b1))
#define CP_ASYNC16(dst, src) \
    asm volatile("cp.async.cg.shared.global [%0], [%1], 16;" :: "r"(dst), "l"(src) : "memory")
#define CP_COMMIT() asm volatile("cp.async.commit_group;" ::: "memory")
#define CP_WAIT(n)  asm volatile("cp.async.wait_group %0;" :: "n"(n) : "memory")

// ---------------- convert kernels ----------------
// x fp32 [M][2048] -> xs fp16 [M][2048]
__global__ __launch_bounds__(256)
void conv_a_kernel(const float* __restrict__ src, __half* __restrict__ dst) {
    int idx = blockIdx.x * 256 + threadIdx.x;
    int m = idx >> 9;
    int k = (idx & 511) << 2;
    float4 v = *(const float4*)(src + (size_t)m * 2048 + k);
    __half2* d = (__half2*)(dst + (size_t)m * KG_ + k);
    d[0] = __floats2half2_rn(v.x, v.y);
    d[1] = __floats2half2_rn(v.z, v.w);
}

// W fp32 [2048][Ncols] -> Bt fp16 [n][2048]
__global__ __launch_bounds__(256)
void tsplit_b_kernel(const float* __restrict__ src, __half* __restrict__ dst, int Ncols) {
    __shared__ float t[32][33];
    const int n0 = blockIdx.x * 32, k0 = blockIdx.y * 32;
    const int tx = threadIdx.x, ty = threadIdx.y;
#pragma unroll
    for (int i = 0; i < 4; i++)
        t[ty + i * 8][tx] = src[(size_t)(k0 + ty + i * 8) * Ncols + n0 + tx];
    __syncthreads();
#pragma unroll
    for (int i = 0; i < 4; i++)
        dst[(size_t)(n0 + ty + i * 8) * KG_ + k0 + tx] =
            __float2half_rn(t[tx][ty + i * 8]);
}

// ---------------- V transpose (fp16) ----------------
__global__ __launch_bounds__(256)
void split_v_kernel(const float* __restrict__ qkv, __half* __restrict__ vt) {
    __shared__ float tbuf[32][33];
    const int d0 = blockIdx.x * 32;
    const int t0 = blockIdx.y * 32;
    const int bkv = blockIdx.z;
    const int b = bkv >> 2, kv = bkv & 3;
    const int tx = threadIdx.x, ty = threadIdx.y;
#pragma unroll
    for (int i = 0; i < 4; i++)
        tbuf[ty + i * 8][tx] =
            qkv[(size_t)(b * T_ + t0 + ty + i * 8) * QKV_LD + 2560 + kv * 128 + d0 + tx];
    __syncthreads();
#pragma unroll
    for (int i = 0; i < 4; i++)
        vt[((size_t)bkv * 128 + d0 + ty + i * 8) * T_ + t0 + tx] =
            __float2half_rn(tbuf[tx][ty + i * 8]);
}

// ---------------- fp16 GEMM: 256x128 CTA tile, 512 thr, 4-stage cp.async ----------------
#define SMPAD 80
#define GASTG (256 * SMPAD)             // 20480 A bytes/stage
#define GBSTG (128 * SMPAD)             // 10240 B bytes/stage
#define GSTAGE_B (GASTG + GBSTG)        // 30720
#define GSMEM (4 * GSTAGE_B)            // 122880

__global__ __launch_bounds__(512, 1)
void gemm_f16(const __half* __restrict__ A, const __half* __restrict__ Bt,
              float* __restrict__ C, int N) {
    extern __shared__ uint8_t sm[];
    const uint32_t smb = smem_u32(sm);

    const int tid = threadIdx.x;
    const int lane = tid & 31, wid = tid >> 5;
    const int wm = wid >> 1, wn = wid & 1;          // 8m x 2n warps, 32x64 tile
    const int m0 = blockIdx.y * 256, n0 = blockIdx.x * 128;

    const int crow = tid >> 2, c16 = tid & 3;
    const __half* agp0 = A + (size_t)(m0 + crow) * KG_ + c16 * 8;
    const __half* agp1 = agp0 + (size_t)128 * KG_;
    const __half* bgp  = Bt + (size_t)(n0 + crow) * KG_ + c16 * 8;
    const uint32_t sa0_rel = (uint32_t)(crow * SMPAD + c16 * 16);
    const uint32_t sa1_rel = sa0_rel + 128 * SMPAD;
    const uint32_t sb_rel  = (uint32_t)(GASTG + crow * SMPAD + c16 * 16);
    const bool do_b = (crow < 128);

    float acc[2][8][4];
#pragma unroll
    for (int i = 0; i < 2; i++)
#pragma unroll
        for (int j = 0; j < 8; j++)
#pragma unroll
            for (int r = 0; r < 4; r++) acc[i][j][r] = 0.0f;

    const int nK = KG_ / 32;   // 64 stages

#pragma unroll
    for (int s = 0; s < 3; s++) {
        const uint32_t base = smb + s * GSTAGE_B;
        const int k0 = s * 32;
        CP_ASYNC16(base + sa0_rel, agp0 + k0);
        CP_ASYNC16(base + sa1_rel, agp1 + k0);
        if (do_b) CP_ASYNC16(base + sb_rel, bgp + k0);
        CP_COMMIT();
    }

    const int lj = lane >> 3, lr = lane & 7;
    const uint32_t a_rel = (uint32_t)((wm * 32 + ((lj & 1) << 3) + lr) * SMPAD + ((lj >> 1) << 4));
    const uint32_t b_rel = (uint32_t)(GASTG + (wn * 64 + ((lj >> 1) << 3) + lr) * SMPAD + ((lj & 1) << 4));

    for (int it = 0; it < nK; it++) {
        CP_WAIT(2);
        __syncthreads();
        const int is = it + 3;
        if (is < nK) {
            const uint32_t base = smb + (is & 3) * GSTAGE_B;
            const int k0 = is * 32;
            CP_ASYNC16(base + sa0_rel, agp0 + k0);
            CP_ASYNC16(base + sa1_rel, agp1 + k0);
            if (do_b) CP_ASYNC16(base + sb_rel, bgp + k0);
        }
        CP_COMMIT();

        const uint32_t stg = smb + (it & 3) * GSTAGE_B;
#pragma unroll
        for (int kk = 0; kk < 2; kk++) {
            uint32_t af[2][4];
#pragma unroll
            for (int i = 0; i < 2; i++)
                LDMX4(af[i][0], af[i][1], af[i][2], af[i][3],
                      stg + a_rel + i * 16 * SMPAD + kk * 32);
            uint32_t bf[8][2];
#pragma unroll
            for (int p = 0; p < 4; p++) {
                uint32_t r0, r1, r2, r3;
                LDMX4(r0, r1, r2, r3, stg + b_rel + p * 16 * SMPAD + kk * 32);
                bf[2 * p][0] = r0; bf[2 * p][1] = r1;
                bf[2 * p + 1][0] = r2; bf[2 * p + 1][1] = r3;
            }
#pragma unroll
            for (int i = 0; i < 2; i++)
#pragma unroll
                for (int j = 0; j < 8; j++)
                    MMA16816F16(acc[i][j], af[i][0], af[i][1], af[i][2], af[i][3],
                                bf[j][0], bf[j][1]);
        }
    }

    const int cr = lane >> 2, cc = (lane & 3) << 1;
#pragma unroll
    for (int i = 0; i < 2; i++) {
        const int mrow = m0 + wm * 32 + i * 16 + cr;
#pragma unroll
        for (int j = 0; j < 8; j++) {
            const int col = n0 + wn * 64 + j * 8 + cc;
            *(float2*)(C + (size_t)mrow * N + col)       = make_float2(acc[i][j][0], acc[i][j][1]);
            *(float2*)(C + (size_t)(mrow + 8) * N + col) = make_float2(acc[i][j][2], acc[i][j][3]);
        }
    }
}

// ---------------- RoPE + RMSNorm -> fp16 q16 / k2 ----------------
__global__ __launch_bounds__(32)
void rope_rms_kernel(const float* __restrict__ qkv,
                     const float* __restrict__ cosp, const float* __restrict__ sinp,
                     __half* __restrict__ q16, __half* __restrict__ k2) {
    const int n  = blockIdx.x;
    const int bt = n / (H_ + KVH_);
    const int hh = n - bt * (H_ + KVH_);
    const float* p = qkv + (size_t)bt * QKV_LD +
                     ((hh < H_) ? (size_t)hh * 128 : (size_t)(2048 + (hh - H_) * 128));
    const int t = bt & (T_ - 1);
    const int l = threadIdx.x;

    float o1[2], o2[2];
    float ss = 0.0f;
#pragma unroll
    for (int u = 0; u < 2; u++) {
        int d = l + u * 32;
        float x1 = p[d];
        float x2 = p[d + 64];
        float c = cosp[t * 64 + d];
        float s = sinp[t * 64 + d];
        o1[u] = x1 * c + x2 * s;
        o2[u] = x2 * c - x1 * s;
        ss += o1[u] * o1[u] + o2[u] * o2[u];
    }
#pragma unroll
    for (int off = 16; off > 0; off >>= 1)
        ss += __shfl_xor_sync(0xffffffffu, ss, off);
    float r = rsqrtf(ss * (1.0f / 128.0f) + 1e-5f);

    __half* dst = (hh < H_)
        ? (q16 + (size_t)bt * 2048 + (size_t)hh * 128)
        : (k2 + ((size_t)((bt >> 11) * KVH_ + (hh - H_)) * T_ + t) * 128);
#pragma unroll
    for (int u = 0; u < 2; u++) {
        int d = l + u * 32;
        dst[d]      = __float2half_rn(o1[u] * r);
        dst[d + 64] = __float2half_rn(o2[u] * r);
    }
}

// ---------------- tensor-core flash attention (pure fp16) ----------------
#define AKS 272
#define AVS2 144
#define SM_Q   0
#define SM_K0  (64 * AKS)
#define SM_K1  (SM_K0 + 64 * AKS)
#define SM_V0  (SM_K1 + 64 * AKS)
#define SM_V1  (SM_V0 + 128 * AVS2)
#define SM_RED (SM_V1 + 128 * AVS2)
#define ATT_SMEM (SM_RED + 1024)       // 90112
#define ATT_SCALE 0.08838834764831845f

__global__ __launch_bounds__(256, 2)
void attn_mma_kernel(const __half* __restrict__ q16,
                     const __half* __restrict__ k2,
                     const __half* __restrict__ vt,
                     __half* __restrict__ ys) {
    extern __shared__ uint8_t sm[];
    const uint32_t smb = smem_u32(sm);
    float* redmax = (float*)(sm + SM_RED);
    float* redsum = (float*)(sm + SM_RED + 512);

    const int tid = threadIdx.x;
    const int lane = tid & 31, wid = tid >> 5;
    const int wm = wid >> 1, wn = wid & 1;
    const int qtile = 31 - blockIdx.x;
    const int bh = blockIdx.y;
    const int b  = bh >> 4;
    const int h  = bh & 15;
    const int kv = h >> 2;
    const int q0 = qtile * 64;

    const __half* k2b = k2 + (size_t)(b * KVH_ + kv) * T_ * 128;
    const __half* vtb = vt + (size_t)(b * KVH_ + kv) * 128 * T_;
    const __half* q16b = q16 + (size_t)(b * T_ + q0) * 2048 + (size_t)h * 128;

    const int krow = tid >> 2, kc = tid & 3;
    const int vrow = tid >> 1, vc = tid & 1;
    const uint32_t kdst_rel = (uint32_t)(krow * AKS);
    const uint32_t vdst_rel = (uint32_t)(vrow * AVS2);

    // prologue: Q + K0 + V0 loads
    {
#pragma unroll
        for (int i = 0; i < 4; i++) {
            int c = kc + i * 4;
            CP_ASYNC16(smb + SM_Q + kdst_rel + c * 16, q16b + (size_t)krow * 2048 + c * 8);
        }
        const __half* src = k2b + (size_t)krow * 128;
#pragma unroll
        for (int i = 0; i < 4; i++) {
            int c = kc + i * 4;
            CP_ASYNC16(smb + SM_K0 + kdst_rel + c * 16, src + c * 8);
        }
        const __half* srow = vtb + (size_t)vrow * T_;
#pragma unroll
        for (int i = 0; i < 4; i++) {
            int c = vc + i * 2;
            CP_ASYNC16(smb + SM_V0 + vdst_rel + c * 16, srow + c * 8);
        }
        CP_COMMIT();
    }

    const int lj = lane >> 3, lr = lane & 7;
    const uint32_t a_off = smb + SM_Q + (uint32_t)((wm * 16 + ((lj & 1) << 3) + lr) * AKS + ((lj >> 1) << 4));
    const uint32_t b_rel = (uint32_t)((wn * 32 + ((lj >> 1) << 3) + lr) * AKS + ((lj & 1) << 4));
    const uint32_t v_rel = (uint32_t)((((lj >> 1) << 3) + lr) * AVS2 + ((lj & 1) << 4));

    const int ra = lane >> 2;
    const int row_a = wm * 16 + ra, row_b = row_a + 8;
    const int colb = wn * 32 + 2 * (lane & 3);
    float m_a = -FLT_MAX, m_b = -FLT_MAX, l_a = 0.0f, l_b = 0.0f;

    float o[16][4];
#pragma unroll
    for (int j = 0; j < 16; j++)
#pragma unroll
        for (int r = 0; r < 4; r++) o[j][r] = 0.0f;

    for (int jt = 0; jt <= qtile; jt++) {
        const int buf = jt & 1;
        const uint32_t sK = smb + (buf ? SM_K1 : SM_K0);
        const uint32_t sV = smb + (buf ? SM_V1 : SM_V0);

        CP_WAIT(0);
        __syncthreads();

        if (jt < qtile) {
            const int j1 = (jt + 1) * 64;
            const uint32_t dK = smb + (buf ? SM_K0 : SM_K1);
            const uint32_t dV = smb + (buf ? SM_V0 : SM_V1);
            const __half* src = k2b + (size_t)(j1 + krow) * 128;
#pragma unroll
            for (int i = 0; i < 4; i++) {
                int c = kc + i * 4;
                CP_ASYNC16(dK + kdst_rel + c * 16, src + c * 8);
            }
            const __half* srow = vtb + (size_t)vrow * T_ + j1;
#pragma unroll
            for (int i = 0; i < 4; i++) {
                int c = vc + i * 2;
                CP_ASYNC16(dV + vdst_rel + c * 16, srow + c * 8);
            }
        }
        CP_COMMIT();

        // ---- S = Qh Kh^T ----
        float s_[4][4];
#pragma unroll
        for (int j = 0; j < 4; j++)
#pragma unroll
            for (int r = 0; r < 4; r++) s_[j][r] = 0.0f;

#pragma unroll
        for (int kk = 0; kk < 8; kk++) {
            uint32_t af[4];
            LDMX4(af[0], af[1], af[2], af[3], a_off + 32 * kk);
            uint32_t bf[4][2];
#pragma unroll
            for (int p = 0; p < 2; p++) {
                uint32_t r0, r1, r2, r3;
                LDMX4(r0, r1, r2, r3, sK + b_rel + p * 16 * AKS + 32 * kk);
                bf[2 * p][0] = r0; bf[2 * p][1] = r1;
                bf[2 * p + 1][0] = r2; bf[2 * p + 1][1] = r3;
            }
#pragma unroll
            for (int j = 0; j < 4; j++)
                MMA16816F16(s_[j], af[0], af[1], af[2], af[3], bf[j][0], bf[j][1]);
        }

        // ---- online softmax ----
        const bool diag = (jt == qtile);
        float mxa = -FLT_MAX, mxb = -FLT_MAX;
#pragma unroll
        for (int j = 0; j < 4; j++)
#pragma unroll
            for (int e = 0; e < 2; e++) {
                int cg = colb + 8 * j + e;
                float va = s_[j][e] * ATT_SCALE;
                if (diag && cg > row_a) va = -FLT_MAX;
                s_[j][e] = va; mxa = fmaxf(mxa, va);
                float vb = s_[j][e + 2] * ATT_SCALE;
                if (diag && cg > row_b) vb = -FLT_MAX;
                s_[j][e + 2] = vb; mxb = fmaxf(mxb, vb);
            }
        mxa = fmaxf(mxa, __shfl_xor_sync(0xffffffffu, mxa, 1));
        mxa = fmaxf(mxa, __shfl_xor_sync(0xffffffffu, mxa, 2));
        mxb = fmaxf(mxb, __shfl_xor_sync(0xffffffffu, mxb, 1));
        mxb = fmaxf(mxb, __shfl_xor_sync(0xffffffffu, mxb, 2));
        if ((lane & 3) == 0) {
            redmax[wn * 64 + row_a] = mxa;
            redmax[wn * 64 + row_b] = mxb;
        }
        __syncthreads();
        float mna = fmaxf(m_a, fmaxf(redmax[row_a], redmax[64 + row_a]));
        float mnb = fmaxf(m_b, fmaxf(redmax[row_b], redmax[64 + row_b]));
        float fa = __expf(m_a - mna), fb = __expf(m_b - mnb);
        float sa = 0.0f, sb = 0.0f;
#pragma unroll
        for (int j = 0; j < 4; j++)
#pragma unroll
            for (int e = 0; e < 2; e++) {
                float pa = __expf(s_[j][e] - mna);
                s_[j][e] = pa; sa += pa;
                float pb = __expf(s_[j][e + 2] - mnb);
                s_[j][e + 2] = pb; sb += pb;
            }
        sa += __shfl_xor_sync(0xffffffffu, sa, 1);
        sa += __shfl_xor_sync(0xffffffffu, sa, 2);
        sb += __shfl_xor_sync(0xffffffffu, sb, 1);
        sb += __shfl_xor_sync(0xffffffffu, sb, 2);
        if ((lane & 3) == 0) {
            redsum[wn * 64 + row_a] = sa;
            redsum[wn * 64 + row_b] = sb;
        }
        __syncthreads();
        l_a = l_a * fa + redsum[row_a] + redsum[64 + row_a];
        l_b = l_b * fb + redsum[row_b] + redsum[64 + row_b];
        m_a = mna; m_b = mnb;

#pragma unroll
        for (int j = 0; j < 16; j++) {
            o[j][0] *= fa; o[j][1] *= fa;
            o[j][2] *= fb; o[j][3] *= fb;
        }

        // ---- P fragments (fp16) ----
        uint32_t php0[4], php1[4];
#pragma unroll
        for (int j = 0; j < 4; j++) {
            __half2 h01 = __floats2half2_rn(s_[j][0], s_[j][1]);
            __half2 h23 = __floats2half2_rn(s_[j][2], s_[j][3]);
            php0[j] = *(uint32_t*)&h01;
            php1[j] = *(uint32_t*)&h23;
        }

        // ---- O += Ph Vh ----
        {
            const uint32_t bbase = wn * 64u;
#pragma unroll
            for (int kk2 = 0; kk2 < 2; kk2++) {
                uint32_t a0 = php0[2 * kk2];
                uint32_t a1 = php1[2 * kk2];
                uint32_t a2 = php0[2 * kk2 + 1];
                uint32_t a3 = php1[2 * kk2 + 1];
                uint32_t vb[16][2];
#pragma unroll
                for (int p = 0; p < 8; p++) {
                    uint32_t r0, r1, r2, r3;
                    LDMX4(r0, r1, r2, r3, sV + v_rel + p * 16 * AVS2 + bbase + 32 * kk2);
                    vb[2 * p][0] = r0; vb[2 * p][1] = r1;
                    vb[2 * p + 1][0] = r2; vb[2 * p + 1][1] = r3;
                }
#pragma unroll
                for (int j = 0; j < 16; j++)
                    MMA16816F16(o[j], a0, a1, a2, a3, vb[j][0], vb[j][1]);
            }
        }
    }

    // epilogue: combine partials, write fp16 ys (single plane)
    __syncthreads();
    float* Ob = (float*)sm;
    if (wn == 1) {
#pragma unroll
        for (int j = 0; j < 16; j++) {
            int col = 8 * j + 2 * (lane & 3);
            *(float2*)&Ob[row_a * 132 + col] = make_float2(o[j][0], o[j][1]);
            *(float2*)&Ob[row_b * 132 + col] = make_float2(o[j][2], o[j][3]);
        }
    }
    __syncthreads();
    if (wn == 0) {
        float inva = 1.0f / l_a, invb = 1.0f / l_b;
        __half* base = ys + (size_t)(b * T_ + q0) * KG_ + h * 128;
#pragma unroll
        for (int j = 0; j < 16; j++) {
            int col = 8 * j + 2 * (lane & 3);
            float2 pa = *(float2*)&Ob[row_a * 132 + col];
            float2 pb = *(float2*)&Ob[row_b * 132 + col];
            *(__half2*)(base + (size_t)row_a * KG_ + col) =
                __floats2half2_rn((o[j][0] + pa.x) * inva, (o[j][1] + pa.y) * inva);
            *(__half2*)(base + (size_t)row_b * KG_ + col) =
                __floats2half2_rn((o[j][2] + pb.x) * invb, (o[j][3] + pb.y) * invb);
        }
    }
}

// ---------------- launch ----------------
extern "C" void kernel_launch(void* const* d_in, const int* in_sizes, int n_in,
                              void* d_out, int out_size) {
    const float* x    = (const float*)d_in[0];
    const float* cosp = (const float*)d_in[1];
    const float* sinp = (const float*)d_in[2];
    const float* wq   = (const float*)d_in[3];
    const float* wk   = (const float*)d_in[4];
    const float* wv   = (const float*)d_in[5];
    const float* wo   = (const float*)d_in[6];
    float* out = (float*)d_out;

    __half *xs, *wb1, *wb2, *ys, *q16, *k2, *vt;
    float *qkv;
    cudaGetSymbolAddress((void**)&xs,  g_xs);
    cudaGetSymbolAddress((void**)&wb1, g_wb1);
    cudaGetSymbolAddress((void**)&wb2, g_wb2);
    cudaGetSymbolAddress((void**)&ys,  g_ys);
    cudaGetSymbolAddress((void**)&qkv, g_qkv);
    cudaGetSymbolAddress((void**)&q16, g_q16);
    cudaGetSymbolAddress((void**)&k2,  g_k2);
    cudaGetSymbolAddress((void**)&vt,  g_vt);

    cudaFuncSetAttribute(attn_mma_kernel, cudaFuncAttributeMaxDynamicSharedMemorySize, ATT_SMEM);
    cudaFuncSetAttribute(gemm_f16, cudaFuncAttributeMaxDynamicSharedMemorySize, GSMEM);

    dim3 tb(32, 8);
    conv_a_kernel<<<(M_ * 2048 / 4) / 256, 256>>>(x, xs);
    tsplit_b_kernel<<<dim3(2048 / 32, 2048 / 32), tb>>>(wq, wb1, 2048);
    tsplit_b_kernel<<<dim3(512  / 32, 2048 / 32), tb>>>(wk, wb1 + (size_t)2048 * KG_, 512);
    tsplit_b_kernel<<<dim3(512  / 32, 2048 / 32), tb>>>(wv, wb1 + (size_t)2560 * KG_, 512);
    tsplit_b_kernel<<<dim3(2048 / 32, 2048 / 32), tb>>>(wo, wb2, 2048);

    gemm_f16<<<dim3(3072 / 128, M_ / 256), 512, GSMEM>>>(xs, wb1, qkv, 3072);
    rope_rms_kernel<<<M_ * (H_ + KVH_), 32>>>(qkv, cosp, sinp, q16, k2);
    split_v_kernel<<<dim3(4, 64, 8), tb>>>(qkv, vt);

    attn_mma_kernel<<<dim3(32, 32), 256, ATT_SMEM>>>(q16, k2, vt, ys);
    gemm_f16<<<dim3(2048 / 128, M_ / 256), 512, GSMEM>>>(ys, wb2, out, 2048);
}

// round 15
// speedup vs baseline: 3.4957x; 1.0723x over previous
#include <cuda_runtime.h>
#include <cuda_bf16.h>
#include <cuda_fp16.h>
#include <math.h>
#include <float.h>
#include <stdint.h>

#define B_   2
#define T_   2048
#define C_   2048
#define H_   16
#define KVH_ 4
#define HD_  128
#define M_   (B_*T_)           // 4096
#define KG_  2048
#define QKV_LD 3072

// ---------------- scratch ----------------
__device__ __half g_xs [(size_t)M_ * KG_];
__device__ __half g_wb1[(size_t)3072 * KG_];
__device__ __half g_wb2[(size_t)2048 * KG_];
__device__ __half g_ys [(size_t)M_ * KG_];
__device__ __half g_q16[(size_t)M_ * 2048];              // roped+normed Q fp16
__device__ __half g_k2[(size_t)B_ * KVH_ * T_ * 128];    // [bkv][t][Kh 128]
__device__ __half g_vt[(size_t)B_ * KVH_ * HD_ * T_];    // [bkv][d][Vh t]

// ---------------- helpers ----------------
__device__ __forceinline__ uint32_t smem_u32(const void* p) {
    uint32_t a;
    asm("{ .reg .u64 t; cvta.to.shared.u64 t, %1; cvt.u32.u64 %0, t; }" : "=r"(a) : "l"(p));
    return a;
}
#define LDMX4(r0, r1, r2, r3, addr) \
    asm volatile("ldmatrix.sync.aligned.m8n8.x4.shared.b16 {%0,%1,%2,%3}, [%4];" \
        : "=r"(r0), "=r"(r1), "=r"(r2), "=r"(r3) : "r"(addr))
#define MMA16816F16(c, a0, a1, a2, a3, b0, b1) \
    asm volatile("mma.sync.aligned.m16n8k16.row.col.f32.f16.f16.f32 " \
        "{%0,%1,%2,%3}, {%4,%5,%6,%7}, {%8,%9}, {%0,%1,%2,%3};" \
        : "+f"((c)[0]), "+f"((c)[1]), "+f"((c)[2]), "+f"((c)[3]) \
        : "r"(a0), "r"(a1), "r"(a2), "r"(a3), "r"(b0), "r"(b1))
#define CP_ASYNC16(dst, src) \
    asm volatile("cp.async.cg.shared.global [%0], [%1], 16;" :: "r"(dst), "l"(src) : "memory")
#define CP_COMMIT() asm volatile("cp.async.commit_group;" ::: "memory")
#define CP_WAIT(n)  asm volatile("cp.async.wait_group %0;" :: "n"(n) : "memory")

// ---------------- convert kernels ----------------
__global__ __launch_bounds__(256)
void conv_a_kernel(const float* __restrict__ src, __half* __restrict__ dst) {
    int idx = blockIdx.x * 256 + threadIdx.x;
    int m = idx >> 9;
    int k = (idx & 511) << 2;
    float4 v = *(const float4*)(src + (size_t)m * 2048 + k);
    __half2* d = (__half2*)(dst + (size_t)m * KG_ + k);
    d[0] = __floats2half2_rn(v.x, v.y);
    d[1] = __floats2half2_rn(v.z, v.w);
}

__global__ __launch_bounds__(256)
void tsplit_b_kernel(const float* __restrict__ src, __half* __restrict__ dst, int Ncols) {
    __shared__ float t[32][33];
    const int n0 = blockIdx.x * 32, k0 = blockIdx.y * 32;
    const int tx = threadIdx.x, ty = threadIdx.y;
#pragma unroll
    for (int i = 0; i < 4; i++)
        t[ty + i * 8][tx] = src[(size_t)(k0 + ty + i * 8) * Ncols + n0 + tx];
    __syncthreads();
#pragma unroll
    for (int i = 0; i < 4; i++)
        dst[(size_t)(n0 + ty + i * 8) * KG_ + k0 + tx] =
            __float2half_rn(t[tx][ty + i * 8]);
}

// ---------------- shared GEMM config ----------------
#define SMPAD 80
#define GASTG (256 * SMPAD)
#define GBSTG (128 * SMPAD)
#define GSTAGE_B (GASTG + GBSTG)        // 30720
#define GSMEM (4 * GSTAGE_B)            // 122880
#define EPAD 132                        // epilogue tile row stride (floats)

// ================= QKV GEMM with fused rope/rms/V-transpose epilogue =================
__global__ __launch_bounds__(512, 1)
void gemm_qkv(const __half* __restrict__ A, const __half* __restrict__ Bt,
              const float* __restrict__ cosp, const float* __restrict__ sinp,
              __half* __restrict__ q16, __half* __restrict__ k2,
              __half* __restrict__ vt) {
    extern __shared__ uint8_t sm[];
    const uint32_t smb = smem_u32(sm);

    const int tid = threadIdx.x;
    const int lane = tid & 31, wid = tid >> 5;
    const int wm = wid >> 1, wn = wid & 1;
    const int m0 = blockIdx.y * 256, n0 = blockIdx.x * 128;

    const int crow = tid >> 2, c16 = tid & 3;
    const __half* agp0 = A + (size_t)(m0 + crow) * KG_ + c16 * 8;
    const __half* agp1 = agp0 + (size_t)128 * KG_;
    const __half* bgp  = Bt + (size_t)(n0 + crow) * KG_ + c16 * 8;
    const uint32_t sa0_rel = (uint32_t)(crow * SMPAD + c16 * 16);
    const uint32_t sa1_rel = sa0_rel + 128 * SMPAD;
    const uint32_t sb_rel  = (uint32_t)(GASTG + crow * SMPAD + c16 * 16);
    const bool do_b = (crow < 128);

    float acc[2][8][4];
#pragma unroll
    for (int i = 0; i < 2; i++)
#pragma unroll
        for (int j = 0; j < 8; j++)
#pragma unroll
            for (int r = 0; r < 4; r++) acc[i][j][r] = 0.0f;

    const int nK = KG_ / 32;

#pragma unroll
    for (int s = 0; s < 3; s++) {
        const uint32_t base = smb + s * GSTAGE_B;
        const int k0 = s * 32;
        CP_ASYNC16(base + sa0_rel, agp0 + k0);
        CP_ASYNC16(base + sa1_rel, agp1 + k0);
        if (do_b) CP_ASYNC16(base + sb_rel, bgp + k0);
        CP_COMMIT();
    }

    const int lj = lane >> 3, lr = lane & 7;
    const uint32_t a_rel = (uint32_t)((wm * 32 + ((lj & 1) << 3) + lr) * SMPAD + ((lj >> 1) << 4));
    const uint32_t b_rel = (uint32_t)(GASTG + (wn * 64 + ((lj >> 1) << 3) + lr) * SMPAD + ((lj & 1) << 4));

    for (int it = 0; it < nK; it++) {
        CP_WAIT(2);
        __syncthreads();
        const int is = it + 3;
        if (is < nK) {
            const uint32_t base = smb + (is & 3) * GSTAGE_B;
            const int k0 = is * 32;
            CP_ASYNC16(base + sa0_rel, agp0 + k0);
            CP_ASYNC16(base + sa1_rel, agp1 + k0);
            if (do_b) CP_ASYNC16(base + sb_rel, bgp + k0);
        }
        CP_COMMIT();

        const uint32_t stg = smb + (it & 3) * GSTAGE_B;
#pragma unroll
        for (int kk = 0; kk < 2; kk++) {
            uint32_t af[2][4];
#pragma unroll
            for (int i = 0; i < 2; i++)
                LDMX4(af[i][0], af[i][1], af[i][2], af[i][3],
                      stg + a_rel + i * 16 * SMPAD + kk * 32);
            uint32_t bf[8][2];
#pragma unroll
            for (int p = 0; p < 4; p++) {
                uint32_t r0, r1, r2, r3;
                LDMX4(r0, r1, r2, r3, stg + b_rel + p * 16 * SMPAD + kk * 32);
                bf[2 * p][0] = r0; bf[2 * p][1] = r1;
                bf[2 * p + 1][0] = r2; bf[2 * p + 1][1] = r3;
            }
#pragma unroll
            for (int i = 0; i < 2; i++)
#pragma unroll
                for (int j = 0; j < 8; j++)
                    MMA16816F16(acc[i][j], af[i][0], af[i][1], af[i][2], af[i][3],
                                bf[j][0], bf[j][1]);
        }
    }

    // ---- fused epilogue: two 128-row halves through smem ----
    float* tile = (float*)sm;
    const int nt = blockIdx.x;             // 0..15 q, 16..19 k, 20..23 v
    const int cr = lane >> 2, cc = (lane & 3) << 1;

#pragma unroll 1
    for (int half = 0; half < 2; half++) {
        __syncthreads();   // mainloop smem / prev-half reads done
        if ((wm >> 2) == half) {
            const int lwm = wm & 3;
#pragma unroll
            for (int i = 0; i < 2; i++) {
                const int row = lwm * 32 + i * 16 + cr;
#pragma unroll
                for (int j = 0; j < 8; j++) {
                    const int col = wn * 64 + j * 8 + cc;
                    tile[row * EPAD + col]           = acc[i][j][0];
                    tile[row * EPAD + col + 1]       = acc[i][j][1];
                    tile[(row + 8) * EPAD + col]     = acc[i][j][2];
                    tile[(row + 8) * EPAD + col + 1] = acc[i][j][3];
                }
            }
        }
        __syncthreads();

        const int mbase = m0 + half * 128;
        if (nt < 20) {
            // q/k head: rope + rms, thread = (row, quarter)
            const int r = tid >> 2, q = tid & 3;
            const int mrow = mbase + r;
            const int t = mrow & (T_ - 1);
            float o1v[16], o2v[16];
            float ss = 0.0f;
#pragma unroll
            for (int i = 0; i < 16; i += 4) {
                float4 x1 = *(float4*)&tile[r * EPAD + q * 16 + i];
                float4 x2 = *(float4*)&tile[r * EPAD + 64 + q * 16 + i];
                float4 cv = *(const float4*)(cosp + t * 64 + q * 16 + i);
                float4 sv = *(const float4*)(sinp + t * 64 + q * 16 + i);
                o1v[i]     = x1.x * cv.x + x2.x * sv.x;
                o2v[i]     = x2.x * cv.x - x1.x * sv.x;
                o1v[i + 1] = x1.y * cv.y + x2.y * sv.y;
                o2v[i + 1] = x2.y * cv.y - x1.y * sv.y;
                o1v[i + 2] = x1.z * cv.z + x2.z * sv.z;
                o2v[i + 2] = x2.z * cv.z - x1.z * sv.z;
                o1v[i + 3] = x1.w * cv.w + x2.w * sv.w;
                o2v[i + 3] = x2.w * cv.w - x1.w * sv.w;
#pragma unroll
                for (int e = 0; e < 4; e++)
                    ss += o1v[i + e] * o1v[i + e] + o2v[i + e] * o2v[i + e];
            }
            ss += __shfl_xor_sync(0xffffffffu, ss, 1);
            ss += __shfl_xor_sync(0xffffffffu, ss, 2);
            const float rn = rsqrtf(ss * (1.0f / 128.0f) + 1e-5f);

            __half* dst = (nt < 16)
                ? (q16 + (size_t)mrow * 2048 + (size_t)nt * 128)
                : (k2 + ((size_t)((mrow >> 11) * KVH_ + (nt - 16)) * T_ + t) * 128);
            __half2 w1[8], w2[8];
#pragma unroll
            for (int i = 0; i < 8; i++) {
                w1[i] = __floats2half2_rn(o1v[2 * i] * rn, o1v[2 * i + 1] * rn);
                w2[i] = __floats2half2_rn(o2v[2 * i] * rn, o2v[2 * i + 1] * rn);
            }
            *(uint4*)(dst + q * 16)          = *(uint4*)&w1[0];
            *(uint4*)(dst + q * 16 + 8)      = *(uint4*)&w1[4];
            *(uint4*)(dst + 64 + q * 16)     = *(uint4*)&w2[0];
            *(uint4*)(dst + 64 + q * 16 + 8) = *(uint4*)&w2[4];
        } else {
            // v head: transpose + fp16 convert; thread = (d, rowchunk)
            const int d = tid >> 2, rc = tid & 3;
            const int kvh = nt - 20;
            const int b = mbase >> 11;
            const int t0 = mbase & (T_ - 1);
            __half hv[32];
#pragma unroll
            for (int rr = 0; rr < 32; rr++)
                hv[rr] = __float2half_rn(tile[(rc * 32 + rr) * EPAD + d]);
            __half* dst = vt + ((size_t)(b * KVH_ + kvh) * 128 + d) * T_ + t0 + rc * 32;
#pragma unroll
            for (int c = 0; c < 4; c++)
                *(uint4*)(dst + c * 8) = *(uint4*)&hv[c * 8];
        }
    }
}

// ================= plain fp16 GEMM (output projection) =================
__global__ __launch_bounds__(512, 1)
void gemm_f16(const __half* __restrict__ A, const __half* __restrict__ Bt,
              float* __restrict__ C, int N) {
    extern __shared__ uint8_t sm[];
    const uint32_t smb = smem_u32(sm);

    const int tid = threadIdx.x;
    const int lane = tid & 31, wid = tid >> 5;
    const int wm = wid >> 1, wn = wid & 1;
    const int m0 = blockIdx.y * 256, n0 = blockIdx.x * 128;

    const int crow = tid >> 2, c16 = tid & 3;
    const __half* agp0 = A + (size_t)(m0 + crow) * KG_ + c16 * 8;
    const __half* agp1 = agp0 + (size_t)128 * KG_;
    const __half* bgp  = Bt + (size_t)(n0 + crow) * KG_ + c16 * 8;
    const uint32_t sa0_rel = (uint32_t)(crow * SMPAD + c16 * 16);
    const uint32_t sa1_rel = sa0_rel + 128 * SMPAD;
    const uint32_t sb_rel  = (uint32_t)(GASTG + crow * SMPAD + c16 * 16);
    const bool do_b = (crow < 128);

    float acc[2][8][4];
#pragma unroll
    for (int i = 0; i < 2; i++)
#pragma unroll
        for (int j = 0; j < 8; j++)
#pragma unroll
            for (int r = 0; r < 4; r++) acc[i][j][r] = 0.0f;

    const int nK = KG_ / 32;

#pragma unroll
    for (int s = 0; s < 3; s++) {
        const uint32_t base = smb + s * GSTAGE_B;
        const int k0 = s * 32;
        CP_ASYNC16(base + sa0_rel, agp0 + k0);
        CP_ASYNC16(base + sa1_rel, agp1 + k0);
        if (do_b) CP_ASYNC16(base + sb_rel, bgp + k0);
        CP_COMMIT();
    }

    const int lj = lane >> 3, lr = lane & 7;
    const uint32_t a_rel = (uint32_t)((wm * 32 + ((lj & 1) << 3) + lr) * SMPAD + ((lj >> 1) << 4));
    const uint32_t b_rel = (uint32_t)(GASTG + (wn * 64 + ((lj >> 1) << 3) + lr) * SMPAD + ((lj & 1) << 4));

    for (int it = 0; it < nK; it++) {
        CP_WAIT(2);
        __syncthreads();
        const int is = it + 3;
        if (is < nK) {
            const uint32_t base = smb + (is & 3) * GSTAGE_B;
            const int k0 = is * 32;
            CP_ASYNC16(base + sa0_rel, agp0 + k0);
            CP_ASYNC16(base + sa1_rel, agp1 + k0);
            if (do_b) CP_ASYNC16(base + sb_rel, bgp + k0);
        }
        CP_COMMIT();

        const uint32_t stg = smb + (it & 3) * GSTAGE_B;
#pragma unroll
        for (int kk = 0; kk < 2; kk++) {
            uint32_t af[2][4];
#pragma unroll
            for (int i = 0; i < 2; i++)
                LDMX4(af[i][0], af[i][1], af[i][2], af[i][3],
                      stg + a_rel + i * 16 * SMPAD + kk * 32);
            uint32_t bf[8][2];
#pragma unroll
            for (int p = 0; p < 4; p++) {
                uint32_t r0, r1, r2, r3;
                LDMX4(r0, r1, r2, r3, stg + b_rel + p * 16 * SMPAD + kk * 32);
                bf[2 * p][0] = r0; bf[2 * p][1] = r1;
                bf[2 * p + 1][0] = r2; bf[2 * p + 1][1] = r3;
            }
#pragma unroll
            for (int i = 0; i < 2; i++)
#pragma unroll
                for (int j = 0; j < 8; j++)
                    MMA16816F16(acc[i][j], af[i][0], af[i][1], af[i][2], af[i][3],
                                bf[j][0], bf[j][1]);
        }
    }

    const int cr = lane >> 2, cc = (lane & 3) << 1;
#pragma unroll
    for (int i = 0; i < 2; i++) {
        const int mrow = m0 + wm * 32 + i * 16 + cr;
#pragma unroll
        for (int j = 0; j < 8; j++) {
            const int col = n0 + wn * 64 + j * 8 + cc;
            *(float2*)(C + (size_t)mrow * N + col)       = make_float2(acc[i][j][0], acc[i][j][1]);
            *(float2*)(C + (size_t)(mrow + 8) * N + col) = make_float2(acc[i][j][2], acc[i][j][3]);
        }
    }
}

// ---------------- tensor-core flash attention (pure fp16) ----------------
#define AKS 272
#define AVS2 144
#define SM_Q   0
#define SM_K0  (64 * AKS)
#define SM_K1  (SM_K0 + 64 * AKS)
#define SM_V0  (SM_K1 + 64 * AKS)
#define SM_V1  (SM_V0 + 128 * AVS2)
#define SM_RED (SM_V1 + 128 * AVS2)
#define ATT_SMEM (SM_RED + 1024)       // 90112
#define ATT_SCALE 0.08838834764831845f

__global__ __launch_bounds__(256, 2)
void attn_mma_kernel(const __half* __restrict__ q16,
                     const __half* __restrict__ k2,
                     const __half* __restrict__ vt,
                     __half* __restrict__ ys) {
    extern __shared__ uint8_t sm[];
    const uint32_t smb = smem_u32(sm);
    float* redmax = (float*)(sm + SM_RED);
    float* redsum = (float*)(sm + SM_RED + 512);

    const int tid = threadIdx.x;
    const int lane = tid & 31, wid = tid >> 5;
    const int wm = wid >> 1, wn = wid & 1;
    const int qtile = 31 - blockIdx.x;
    const int bh = blockIdx.y;
    const int b  = bh >> 4;
    const int h  = bh & 15;
    const int kv = h >> 2;
    const int q0 = qtile * 64;

    const __half* k2b = k2 + (size_t)(b * KVH_ + kv) * T_ * 128;
    const __half* vtb = vt + (size_t)(b * KVH_ + kv) * 128 * T_;
    const __half* q16b = q16 + (size_t)(b * T_ + q0) * 2048 + (size_t)h * 128;

    const int krow = tid >> 2, kc = tid & 3;
    const int vrow = tid >> 1, vc = tid & 1;
    const uint32_t kdst_rel = (uint32_t)(krow * AKS);
    const uint32_t vdst_rel = (uint32_t)(vrow * AVS2);

    {
#pragma unroll
        for (int i = 0; i < 4; i++) {
            int c = kc + i * 4;
            CP_ASYNC16(smb + SM_Q + kdst_rel + c * 16, q16b + (size_t)krow * 2048 + c * 8);
        }
        const __half* src = k2b + (size_t)krow * 128;
#pragma unroll
        for (int i = 0; i < 4; i++) {
            int c = kc + i * 4;
            CP_ASYNC16(smb + SM_K0 + kdst_rel + c * 16, src + c * 8);
        }
        const __half* srow = vtb + (size_t)vrow * T_;
#pragma unroll
        for (int i = 0; i < 4; i++) {
            int c = vc + i * 2;
            CP_ASYNC16(smb + SM_V0 + vdst_rel + c * 16, srow + c * 8);
        }
        CP_COMMIT();
    }

    const int lj = lane >> 3, lr = lane & 7;
    const uint32_t a_off = smb + SM_Q + (uint32_t)((wm * 16 + ((lj & 1) << 3) + lr) * AKS + ((lj >> 1) << 4));
    const uint32_t b_rel = (uint32_t)((wn * 32 + ((lj >> 1) << 3) + lr) * AKS + ((lj & 1) << 4));
    const uint32_t v_rel = (uint32_t)((((lj >> 1) << 3) + lr) * AVS2 + ((lj & 1) << 4));

    const int ra = lane >> 2;
    const int row_a = wm * 16 + ra, row_b = row_a + 8;
    const int colb = wn * 32 + 2 * (lane & 3);
    float m_a = -FLT_MAX, m_b = -FLT_MAX, l_a = 0.0f, l_b = 0.0f;

    float o[16][4];
#pragma unroll
    for (int j = 0; j < 16; j++)
#pragma unroll
        for (int r = 0; r < 4; r++) o[j][r] = 0.0f;

    for (int jt = 0; jt <= qtile; jt++) {
        const int buf = jt & 1;
        const uint32_t sK = smb + (buf ? SM_K1 : SM_K0);
        const uint32_t sV = smb + (buf ? SM_V1 : SM_V0);

        CP_WAIT(0);
        __syncthreads();

        if (jt < qtile) {
            const int j1 = (jt + 1) * 64;
            const uint32_t dK = smb + (buf ? SM_K0 : SM_K1);
            const uint32_t dV = smb + (buf ? SM_V0 : SM_V1);
            const __half* src = k2b + (size_t)(j1 + krow) * 128;
#pragma unroll
            for (int i = 0; i < 4; i++) {
                int c = kc + i * 4;
                CP_ASYNC16(dK + kdst_rel + c * 16, src + c * 8);
            }
            const __half* srow = vtb + (size_t)vrow * T_ + j1;
#pragma unroll
            for (int i = 0; i < 4; i++) {
                int c = vc + i * 2;
                CP_ASYNC16(dV + vdst_rel + c * 16, srow + c * 8);
            }
        }
        CP_COMMIT();

        float s_[4][4];
#pragma unroll
        for (int j = 0; j < 4; j++)
#pragma unroll
            for (int r = 0; r < 4; r++) s_[j][r] = 0.0f;

#pragma unroll
        for (int kk = 0; kk < 8; kk++) {
            uint32_t af[4];
            LDMX4(af[0], af[1], af[2], af[3], a_off + 32 * kk);
            uint32_t bf[4][2];
#pragma unroll
            for (int p = 0; p < 2; p++) {
                uint32_t r0, r1, r2, r3;
                LDMX4(r0, r1, r2, r3, sK + b_rel + p * 16 * AKS + 32 * kk);
                bf[2 * p][0] = r0; bf[2 * p][1] = r1;
                bf[2 * p + 1][0] = r2; bf[2 * p + 1][1] = r3;
            }
#pragma unroll
            for (int j = 0; j < 4; j++)
                MMA16816F16(s_[j], af[0], af[1], af[2], af[3], bf[j][0], bf[j][1]);
        }

        const bool diag = (jt == qtile);
        float mxa = -FLT_MAX, mxb = -FLT_MAX;
#pragma unroll
        for (int j = 0; j < 4; j++)
#pragma unroll
            for (int e = 0; e < 2; e++) {
                int cg = colb + 8 * j + e;
                float va = s_[j][e] * ATT_SCALE;
                if (diag && cg > row_a) va = -FLT_MAX;
                s_[j][e] = va; mxa = fmaxf(mxa, va);
                float vb = s_[j][e + 2] * ATT_SCALE;
                if (diag && cg > row_b) vb = -FLT_MAX;
                s_[j][e + 2] = vb; mxb = fmaxf(mxb, vb);
            }
        mxa = fmaxf(mxa, __shfl_xor_sync(0xffffffffu, mxa, 1));
        mxa = fmaxf(mxa, __shfl_xor_sync(0xffffffffu, mxa, 2));
        mxb = fmaxf(mxb, __shfl_xor_sync(0xffffffffu, mxb, 1));
        mxb = fmaxf(mxb, __shfl_xor_sync(0xffffffffu, mxb, 2));
        if ((lane & 3) == 0) {
            redmax[wn * 64 + row_a] = mxa;
            redmax[wn * 64 + row_b] = mxb;
        }
        __syncthreads();
        float mna = fmaxf(m_a, fmaxf(redmax[row_a], redmax[64 + row_a]));
        float mnb = fmaxf(m_b, fmaxf(redmax[row_b], redmax[64 + row_b]));
        float fa = __expf(m_a - mna), fb = __expf(m_b - mnb);
        float sa = 0.0f, sb = 0.0f;
#pragma unroll
        for (int j = 0; j < 4; j++)
#pragma unroll
            for (int e = 0; e < 2; e++) {
                float pa = __expf(s_[j][e] - mna);
                s_[j][e] = pa; sa += pa;
                float pb = __expf(s_[j][e + 2] - mnb);
                s_[j][e + 2] = pb; sb += pb;
            }
        sa += __shfl_xor_sync(0xffffffffu, sa, 1);
        sa += __shfl_xor_sync(0xffffffffu, sa, 2);
        sb += __shfl_xor_sync(0xffffffffu, sb, 1);
        sb += __shfl_xor_sync(0xffffffffu, sb, 2);
        if ((lane & 3) == 0) {
            redsum[wn * 64 + row_a] = sa;
            redsum[wn * 64 + row_b] = sb;
        }
        __syncthreads();
        l_a = l_a * fa + redsum[row_a] + redsum[64 + row_a];
        l_b = l_b * fb + redsum[row_b] + redsum[64 + row_b];
        m_a = mna; m_b = mnb;

#pragma unroll
        for (int j = 0; j < 16; j++) {
            o[j][0] *= fa; o[j][1] *= fa;
            o[j][2] *= fb; o[j][3] *= fb;
        }

        uint32_t php0[4], php1[4];
#pragma unroll
        for (int j = 0; j < 4; j++) {
            __half2 h01 = __floats2half2_rn(s_[j][0], s_[j][1]);
            __half2 h23 = __floats2half2_rn(s_[j][2], s_[j][3]);
            php0[j] = *(uint32_t*)&h01;
            php1[j] = *(uint32_t*)&h23;
        }

        {
            const uint32_t bbase = wn * 64u;
#pragma unroll
            for (int kk2 = 0; kk2 < 2; kk2++) {
                uint32_t a0 = php0[2 * kk2];
                uint32_t a1 = php1[2 * kk2];
                uint32_t a2 = php0[2 * kk2 + 1];
                uint32_t a3 = php1[2 * kk2 + 1];
                uint32_t vb[16][2];
#pragma unroll
                for (int p = 0; p < 8; p++) {
                    uint32_t r0, r1, r2, r3;
                    LDMX4(r0, r1, r2, r3, sV + v_rel + p * 16 * AVS2 + bbase + 32 * kk2);
                    vb[2 * p][0] = r0; vb[2 * p][1] = r1;
                    vb[2 * p + 1][0] = r2; vb[2 * p + 1][1] = r3;
                }
#pragma unroll
                for (int j = 0; j < 16; j++)
                    MMA16816F16(o[j], a0, a1, a2, a3, vb[j][0], vb[j][1]);
            }
        }
    }

    __syncthreads();
    float* Ob = (float*)sm;
    if (wn == 1) {
#pragma unroll
        for (int j = 0; j < 16; j++) {
            int col = 8 * j + 2 * (lane & 3);
            *(float2*)&Ob[row_a * 132 + col] = make_float2(o[j][0], o[j][1]);
            *(float2*)&Ob[row_b * 132 + col] = make_float2(o[j][2], o[j][3]);
        }
    }
    __syncthreads();
    if (wn == 0) {
        float inva = 1.0f / l_a, invb = 1.0f / l_b;
        __half* base = ys + (size_t)(b * T_ + q0) * KG_ + h * 128;
#pragma unroll
        for (int j = 0; j < 16; j++) {
            int col = 8 * j + 2 * (lane & 3);
            float2 pa = *(float2*)&Ob[row_a * 132 + col];
            float2 pb = *(float2*)&Ob[row_b * 132 + col];
            *(__half2*)(base + (size_t)row_a * KG_ + col) =
                __floats2half2_rn((o[j][0] + pa.x) * inva, (o[j][1] + pa.y) * inva);
            *(__half2*)(base + (size_t)row_b * KG_ + col) =
                __floats2half2_rn((o[j][2] + pb.x) * invb, (o[j][3] + pb.y) * invb);
        }
    }
}

// ---------------- launch ----------------
extern "C" void kernel_launch(void* const* d_in, const int* in_sizes, int n_in,
                              void* d_out, int out_size) {
    const float* x    = (const float*)d_in[0];
    const float* cosp = (const float*)d_in[1];
    const float* sinp = (const float*)d_in[2];
    const float* wq   = (const float*)d_in[3];
    const float* wk   = (const float*)d_in[4];
    const float* wv   = (const float*)d_in[5];
    const float* wo   = (const float*)d_in[6];
    float* out = (float*)d_out;

    __half *xs, *wb1, *wb2, *ys, *q16, *k2, *vt;
    cudaGetSymbolAddress((void**)&xs,  g_xs);
    cudaGetSymbolAddress((void**)&wb1, g_wb1);
    cudaGetSymbolAddress((void**)&wb2, g_wb2);
    cudaGetSymbolAddress((void**)&ys,  g_ys);
    cudaGetSymbolAddress((void**)&q16, g_q16);
    cudaGetSymbolAddress((void**)&k2,  g_k2);
    cudaGetSymbolAddress((void**)&vt,  g_vt);

    cudaFuncSetAttribute(attn_mma_kernel, cudaFuncAttributeMaxDynamicSharedMemorySize, ATT_SMEM);
    cudaFuncSetAttribute(gemm_f16, cudaFuncAttributeMaxDynamicSharedMemorySize, GSMEM);
    cudaFuncSetAttribute(gemm_qkv, cudaFuncAttributeMaxDynamicSharedMemorySize, GSMEM);

    dim3 tb(32, 8);
    conv_a_kernel<<<(M_ * 2048 / 4) / 256, 256>>>(x, xs);
    tsplit_b_kernel<<<dim3(2048 / 32, 2048 / 32), tb>>>(wq, wb1, 2048);
    tsplit_b_kernel<<<dim3(512  / 32, 2048 / 32), tb>>>(wk, wb1 + (size_t)2048 * KG_, 512);
    tsplit_b_kernel<<<dim3(512  / 32, 2048 / 32), tb>>>(wv, wb1 + (size_t)2560 * KG_, 512);
    tsplit_b_kernel<<<dim3(2048 / 32, 2048 / 32), tb>>>(wo, wb2, 2048);

    // fused QKV projection + rope + rms + V transpose
    gemm_qkv<<<dim3(3072 / 128, M_ / 256), 512, GSMEM>>>(xs, wb1, cosp, sinp, q16, k2, vt);

    attn_mma_kernel<<<dim3(32, 32), 256, ATT_SMEM>>>(q16, k2, vt, ys);
    gemm_f16<<<dim3(2048 / 128, M_ / 256), 512, GSMEM>>>(ys, wb2, out, 2048);
}